// round 3
// baseline (speedup 1.0000x reference)
#include <cuda_runtime.h>
#include <cuda_bf16.h>

#define NNODES 50000
#define NEDGES 400000
#define MP     50048      // 391 * 128, padded row count for GEMM tiles
#define NOUT   256

// ---------------- static device scratch (no allocations allowed) ----------------
__device__ int   g_deg[NNODES];
__device__ int   g_cnt[NNODES];
__device__ int   g_fill[NNODES];
__device__ float g_dinv[NNODES];
__device__ int   g_rowptr[NNODES + 1];
__device__ int   g_col[NEDGES];
__device__ float g_wval[NEDGES];
__device__ float g_agg[(size_t)MP * 256];
__device__ float g_h1 [(size_t)MP * 256];
__device__ float g_h2 [(size_t)MP * 256];

// Buffer selectors (resolved in device code; no host symbol queries)
#define SEL_EXT 0
#define SEL_H1  1
#define SEL_H2  2

__device__ __forceinline__ const float* sel_cbuf(int SEL, const float* ext) {
    switch (SEL) {
        case SEL_H1: return g_h1;
        case SEL_H2: return g_h2;
        default:     return ext;
    }
}
__device__ __forceinline__ float* sel_buf(int SEL, float* ext) {
    switch (SEL) {
        case SEL_H1: return g_h1;
        case SEL_H2: return g_h2;
        default:     return ext;
    }
}

// ---------------- graph setup kernels ----------------
__global__ void k_init() {
    int i = blockIdx.x * blockDim.x + threadIdx.x;
    if (i < NNODES) { g_deg[i] = 0; g_cnt[i] = 0; g_fill[i] = 0; }
}

// edge_index is int32 (JAX default config disables x64; the int64 request
// in the reference silently yields int32 arrays).
__global__ void k_deg(const int* __restrict__ ei) {
    int e = blockIdx.x * blockDim.x + threadIdx.x;
    if (e < NEDGES) {
        int s = ei[e];
        int d = ei[NEDGES + e];
        if (s != d && (unsigned)s < NNODES && (unsigned)d < NNODES) {
            atomicAdd(&g_deg[s], 1);   // degree by src (matches reference)
            atomicAdd(&g_cnt[d], 1);   // CSR rows keyed by dst
        }
    }
}

__global__ void k_dinv() {
    int i = blockIdx.x * blockDim.x + threadIdx.x;
    if (i < NNODES) {
        int dg = g_deg[i];
        g_dinv[i] = (dg > 0) ? rsqrtf((float)dg) : 0.0f;
    }
}

// Single-block exclusive scan of g_cnt -> g_rowptr (N = 50000, 1024 threads).
__global__ void k_scan() {
    __shared__ int sums[1024];
    const int t  = threadIdx.x;
    const int CH = (NNODES + 1023) / 1024;   // 49
    int start = t * CH;
    int end   = start + CH; if (end > NNODES) end = NNODES;
    int s = 0;
    for (int i = start; i < end; ++i) { g_rowptr[i] = s; s += g_cnt[i]; }
    sums[t] = s;
    __syncthreads();
    for (int off = 1; off < 1024; off <<= 1) {
        int v = (t >= off) ? sums[t - off] : 0;
        __syncthreads();
        sums[t] += v;
        __syncthreads();
    }
    int prefix = (t > 0) ? sums[t - 1] : 0;
    for (int i = start; i < end; ++i) g_rowptr[i] += prefix;
    if (t == 1023) g_rowptr[NNODES] = sums[1023];
}

__global__ void k_fill(const int* __restrict__ ei) {
    int e = blockIdx.x * blockDim.x + threadIdx.x;
    if (e < NEDGES) {
        int s = ei[e];
        int d = ei[NEDGES + e];
        if (s != d && (unsigned)s < NNODES && (unsigned)d < NNODES) {
            int pos = atomicAdd(&g_fill[d], 1);
            int idx = g_rowptr[d] + pos;
            g_col[idx]  = s;
            g_wval[idx] = -g_dinv[s] * g_dinv[d];
        }
    }
}

// ---------------- SpMM: g_agg[row,:] = sum_j w_j * in[col_j,:] ----------------
template <int F, int SEL_IN>
__global__ void k_spmm(const float* __restrict__ in_ext) {
    const float* __restrict__ in = sel_cbuf(SEL_IN, in_ext);
    const int row = blockIdx.x;
    const int f   = threadIdx.x;
    const int beg = g_rowptr[row];
    const int end = g_rowptr[row + 1];
    float acc0 = 0.0f, acc1 = 0.0f;
    int j = beg;
    for (; j + 1 < end; j += 2) {
        float w0 = g_wval[j];     int c0 = g_col[j];
        float w1 = g_wval[j + 1]; int c1 = g_col[j + 1];
        acc0 += w0 * __ldg(&in[(size_t)c0 * F + f]);
        acc1 += w1 * __ldg(&in[(size_t)c1 * F + f]);
    }
    if (j < end) {
        float w = g_wval[j]; int c = g_col[j];
        acc0 += w * __ldg(&in[(size_t)c * F + f]);
    }
    g_agg[(size_t)row * F + f] = acc0 + acc1;
}

// ---------------- fused dual-GEMM: C = A0@B0 + g_agg@B1 + bias (opt relu) ----------------
#define BM 128
#define BN 128
#define BK 8
#define TM 8
#define TN 8

template <int SEL_A0, int SEL_C>
__global__ void __launch_bounds__(256, 2) k_gemm(
    const float* __restrict__ A0_ext, const float* __restrict__ B0,
    const float* __restrict__ B1,
    const float* __restrict__ bias, float* __restrict__ C_ext,
    int K, int M_store, int do_relu)
{
    const float* __restrict__ A0 = sel_cbuf(SEL_A0, A0_ext);
    const float* __restrict__ A1 = g_agg;
    float* __restrict__ C = sel_buf(SEL_C, C_ext);

    __shared__ float As[BK][BM];
    __shared__ float Bs[BK][BN];

    const int tid = threadIdx.x;          // 0..255
    const int tx  = tid & 15;             // col group
    const int ty  = tid >> 4;             // row group
    const int rowBase = blockIdx.x * BM;
    const int colBase = blockIdx.y * BN;

    const int aRow = tid >> 1;            // 0..127
    const int aCol = (tid & 1) * 4;       // 0 or 4
    const int bRow = tid >> 5;            // 0..7
    const int bCol = (tid & 31) * 4;      // 0..124

    const int  gRowA  = rowBase + aRow;
    const bool aValid = (gRowA < NNODES);

    float acc[TM][TN];
#pragma unroll
    for (int i = 0; i < TM; ++i)
#pragma unroll
        for (int j = 0; j < TN; ++j) acc[i][j] = 0.0f;

#pragma unroll 1
    for (int p = 0; p < 2; ++p) {
        const float* __restrict__ A = p ? A1 : A0;
        const float* __restrict__ B = p ? B1 : B0;
#pragma unroll 1
        for (int k0 = 0; k0 < K; k0 += BK) {
            float4 av = make_float4(0.f, 0.f, 0.f, 0.f);
            if (aValid)
                av = *reinterpret_cast<const float4*>(A + (size_t)gRowA * K + k0 + aCol);
            float4 bv = *reinterpret_cast<const float4*>(B + (size_t)(k0 + bRow) * NOUT + colBase + bCol);

            __syncthreads();
            As[aCol + 0][aRow] = av.x;
            As[aCol + 1][aRow] = av.y;
            As[aCol + 2][aRow] = av.z;
            As[aCol + 3][aRow] = av.w;
            *reinterpret_cast<float4*>(&Bs[bRow][bCol]) = bv;
            __syncthreads();

#pragma unroll
            for (int kk = 0; kk < BK; ++kk) {
                float ra[TM], rb[TN];
#pragma unroll
                for (int i = 0; i < TM; ++i) ra[i] = As[kk][ty * TM + i];
#pragma unroll
                for (int j = 0; j < TN; ++j) rb[j] = Bs[kk][tx * TN + j];
#pragma unroll
                for (int i = 0; i < TM; ++i)
#pragma unroll
                    for (int j = 0; j < TN; ++j)
                        acc[i][j] += ra[i] * rb[j];
            }
        }
    }

    // epilogue: bias + optional relu + guarded store
    float bb[TN];
#pragma unroll
    for (int j = 0; j < TN; ++j) bb[j] = bias[colBase + tx * TN + j];

#pragma unroll
    for (int i = 0; i < TM; ++i) {
        int r = rowBase + ty * TM + i;
        if (r < M_store) {
#pragma unroll
            for (int j = 0; j < TN; ++j) {
                int c = colBase + tx * TN + j;
                float v = acc[i][j] + bb[j];
                if (do_relu) v = fmaxf(v, 0.0f);
                C[(size_t)r * NOUT + c] = v;
            }
        }
    }
}

// ---------------- launcher ----------------
extern "C" void kernel_launch(void* const* d_in, const int* in_sizes, int n_in,
                              void* d_out, int out_size)
{
    const float* x    = (const float*)d_in[0];
    const int*   ei   = (const int*)d_in[1];     // int32 (JAX x64 disabled)
    const float* W1_0 = (const float*)d_in[2];
    const float* W1_1 = (const float*)d_in[3];
    const float* b1   = (const float*)d_in[4];
    const float* W2_0 = (const float*)d_in[5];
    const float* W2_1 = (const float*)d_in[6];
    const float* b2   = (const float*)d_in[7];
    const float* W3_0 = (const float*)d_in[8];
    const float* W3_1 = (const float*)d_in[9];
    const float* b3   = (const float*)d_in[10];
    float*       out  = (float*)d_out;

    const int TB = 256;
    // graph setup
    k_init<<<(NNODES + TB - 1) / TB, TB>>>();
    k_deg <<<(NEDGES + TB - 1) / TB, TB>>>(ei);
    k_dinv<<<(NNODES + TB - 1) / TB, TB>>>();
    k_scan<<<1, 1024>>>();
    k_fill<<<(NEDGES + TB - 1) / TB, TB>>>(ei);

    dim3 ggrid(MP / BM, NOUT / BN);   // 391 x 2

    // layer 1 (K = 128): agg = L_hat @ x ; h1 = relu(x@W1_0 + agg@W1_1 + b1)
    k_spmm<128, SEL_EXT><<<NNODES, 128>>>(x);
    k_gemm<SEL_EXT, SEL_H1><<<ggrid, 256>>>(x, W1_0, W1_1, b1, nullptr, 128, MP, 1);

    // layer 2 (K = 256)
    k_spmm<256, SEL_H1><<<NNODES, 256>>>(nullptr);
    k_gemm<SEL_H1, SEL_H2><<<ggrid, 256>>>(nullptr, W2_0, W2_1, b2, nullptr, 256, MP, 1);

    // layer 3 (K = 256), no relu, store only real rows into d_out
    k_spmm<256, SEL_H2><<<NNODES, 256>>>(nullptr);
    k_gemm<SEL_H2, SEL_EXT><<<ggrid, 256>>>(nullptr, W3_0, W3_1, b3, out, 256, NNODES, 0);
}

// round 4
// speedup vs baseline: 1.1791x; 1.1791x over previous
#include <cuda_runtime.h>
#include <cuda_bf16.h>

#define NNODES 50000
#define NEDGES 400000
#define MP     50048      // 391 * 128, padded row count for GEMM tiles
#define NOUT   256
#define SCAN_BLOCKS 49    // 49*1024 = 50176 >= NNODES

// ---------------- static device scratch (no allocations allowed) ----------------
__device__ int   g_deg[NNODES];
__device__ int   g_cnt[NNODES];
__device__ int   g_fill[NNODES];
__device__ float g_dinv[NNODES];
__device__ int   g_rowptr[NNODES + 1];
__device__ int   g_bsum[SCAN_BLOCKS];
__device__ int   g_col[NEDGES];
__device__ float g_wval[NEDGES];
__device__ float g_agg[(size_t)MP * 256];
__device__ float g_h1 [(size_t)MP * 256];
__device__ float g_h2 [(size_t)MP * 256];

// Buffer selectors (resolved in device code; no host symbol queries)
#define SEL_EXT 0
#define SEL_H1  1
#define SEL_H2  2

__device__ __forceinline__ const float* sel_cbuf(int SEL, const float* ext) {
    switch (SEL) {
        case SEL_H1: return g_h1;
        case SEL_H2: return g_h2;
        default:     return ext;
    }
}
__device__ __forceinline__ float* sel_buf(int SEL, float* ext) {
    switch (SEL) {
        case SEL_H1: return g_h1;
        case SEL_H2: return g_h2;
        default:     return ext;
    }
}

// ---------------- packed fp32x2 helpers (sm_103a FFMA2 — PTX only) ----------------
__device__ __forceinline__ unsigned long long pack2(float lo, float hi) {
    unsigned long long r;
    asm("mov.b64 %0, {%1, %2};" : "=l"(r) : "f"(lo), "f"(hi));
    return r;
}
__device__ __forceinline__ void unpack2(unsigned long long v, float& lo, float& hi) {
    asm("mov.b64 {%0, %1}, %2;" : "=f"(lo), "=f"(hi) : "l"(v));
}
__device__ __forceinline__ unsigned long long fma2(unsigned long long a,
                                                   unsigned long long b,
                                                   unsigned long long c) {
    unsigned long long d;
    asm("fma.rn.f32x2 %0, %1, %2, %3;" : "=l"(d) : "l"(a), "l"(b), "l"(c));
    return d;
}

// ---------------- graph setup kernels ----------------
__global__ void k_init() {
    int i = blockIdx.x * blockDim.x + threadIdx.x;
    if (i < NNODES) { g_deg[i] = 0; g_cnt[i] = 0; g_fill[i] = 0; }
}

// edge_index is int32 (JAX default config disables x64)
__global__ void k_deg(const int* __restrict__ ei) {
    int e = blockIdx.x * blockDim.x + threadIdx.x;
    if (e < NEDGES) {
        int s = ei[e];
        int d = ei[NEDGES + e];
        if (s != d && (unsigned)s < NNODES && (unsigned)d < NNODES) {
            atomicAdd(&g_deg[s], 1);
            atomicAdd(&g_cnt[d], 1);
        }
    }
}

__global__ void k_dinv() {
    int i = blockIdx.x * blockDim.x + threadIdx.x;
    if (i < NNODES) {
        int dg = g_deg[i];
        g_dinv[i] = (dg > 0) ? rsqrtf((float)dg) : 0.0f;
    }
}

// Hierarchical coalesced scan: phase 1 — per-block (1024 elems) exclusive scan
__global__ void k_scan1() {
    __shared__ int sh[1024];
    const int t = threadIdx.x;
    const int i = blockIdx.x * 1024 + t;
    int v = (i < NNODES) ? g_cnt[i] : 0;
    sh[t] = v;
    __syncthreads();
    for (int off = 1; off < 1024; off <<= 1) {
        int u = (t >= off) ? sh[t - off] : 0;
        __syncthreads();
        sh[t] += u;
        __syncthreads();
    }
    if (i < NNODES) g_rowptr[i] = sh[t] - v;   // block-local exclusive
    if (t == 1023) g_bsum[blockIdx.x] = sh[1023];
}

// phase 2 — add block offsets (each block re-derives its prefix from <=49 sums)
__global__ void k_scan2() {
    __shared__ int sh[SCAN_BLOCKS];
    const int t = threadIdx.x;
    if (t < SCAN_BLOCKS) sh[t] = g_bsum[t];
    __syncthreads();
    int offset = 0, total = 0;
    for (int b = 0; b < SCAN_BLOCKS; ++b) {
        if (b < (int)blockIdx.x) offset += sh[b];
        total += sh[b];
    }
    const int i = blockIdx.x * 1024 + t;
    if (i < NNODES) g_rowptr[i] += offset;
    if (blockIdx.x == SCAN_BLOCKS - 1 && t == 0) g_rowptr[NNODES] = total;
}

__global__ void k_fill(const int* __restrict__ ei) {
    int e = blockIdx.x * blockDim.x + threadIdx.x;
    if (e < NEDGES) {
        int s = ei[e];
        int d = ei[NEDGES + e];
        if (s != d && (unsigned)s < NNODES && (unsigned)d < NNODES) {
            int pos = atomicAdd(&g_fill[d], 1);
            int idx = g_rowptr[d] + pos;
            g_col[idx]  = s;
            g_wval[idx] = -g_dinv[s] * g_dinv[d];
        }
    }
}

// ---------------- SpMM: g_agg[row,:] = sum_j w_j * in[col_j,:] ----------------
template <int F, int SEL_IN>
__global__ void k_spmm(const float* __restrict__ in_ext) {
    const float* __restrict__ in = sel_cbuf(SEL_IN, in_ext);
    const int row = blockIdx.x;
    const int f   = threadIdx.x;
    const int beg = g_rowptr[row];
    const int end = g_rowptr[row + 1];
    float acc0 = 0.f, acc1 = 0.f, acc2 = 0.f, acc3 = 0.f;
    int j = beg;
    for (; j + 3 < end; j += 4) {
        float w0 = g_wval[j];     int c0 = g_col[j];
        float w1 = g_wval[j + 1]; int c1 = g_col[j + 1];
        float w2 = g_wval[j + 2]; int c2 = g_col[j + 2];
        float w3 = g_wval[j + 3]; int c3 = g_col[j + 3];
        acc0 += w0 * __ldg(&in[(size_t)c0 * F + f]);
        acc1 += w1 * __ldg(&in[(size_t)c1 * F + f]);
        acc2 += w2 * __ldg(&in[(size_t)c2 * F + f]);
        acc3 += w3 * __ldg(&in[(size_t)c3 * F + f]);
    }
    for (; j < end; ++j) {
        float w = g_wval[j]; int c = g_col[j];
        acc0 += w * __ldg(&in[(size_t)c * F + f]);
    }
    g_agg[(size_t)row * F + f] = (acc0 + acc1) + (acc2 + acc3);
}

// ---------------- fused dual-GEMM: C = A0@B0 + g_agg@B1 + bias (opt relu) -------
// f32x2 packed-FMA microkernel, BK=16, register-staged global prefetch.
#define BM 128
#define BN 128
#define BK 16
#define TM 8
#define TN 8
#define ASTRIDE (BM + 4)   // pad to break STS bank conflicts

template <int SEL_A0, int SEL_C>
__global__ void __launch_bounds__(256, 2) k_gemm(
    const float* __restrict__ A0_ext, const float* __restrict__ B0,
    const float* __restrict__ B1,
    const float* __restrict__ bias, float* __restrict__ C_ext,
    int K, int M_store, int do_relu)
{
    const float* __restrict__ A0 = sel_cbuf(SEL_A0, A0_ext);
    const float* __restrict__ A1 = g_agg;
    float* __restrict__ C = sel_buf(SEL_C, C_ext);

    __shared__ float As[BK][ASTRIDE];
    __shared__ float Bs[BK][BN];

    const int tid = threadIdx.x;          // 0..255
    const int tx  = tid & 15;             // col group (compute)
    const int ty  = tid >> 4;             // row group (compute)
    const int rowBase = blockIdx.x * BM;
    const int colBase = blockIdx.y * BN;

    // A loader: 128 rows x 16 cols; each thread: rows {r, r+64}, 4 cols
    const int aRow = tid >> 2;            // 0..63
    const int aCol = (tid & 3) * 4;       // 0,4,8,12
    const bool aV0 = (rowBase + aRow      < NNODES);
    const bool aV1 = (rowBase + aRow + 64 < NNODES);
    // B loader: 16 rows x 128 cols; each thread: rows {br, br+8}, 4 cols
    const int bRow = tid >> 5;            // 0..7
    const int bCol = (tid & 31) * 4;      // 0..124

    const int Kt = K / BK;                // tiles per pass
    const int T  = 2 * Kt;                // total tiles (A0 pass + A1 pass)

    unsigned long long acc[TM][TN / 2];
#pragma unroll
    for (int i = 0; i < TM; ++i)
#pragma unroll
        for (int j = 0; j < TN / 2; ++j) acc[i][j] = 0ULL;

    float4 av0, av1, bv0, bv1;

    // prefetch tile 0
    {
        const float* A = A0; const float* B = B0; int k0 = 0;
        av0 = aV0 ? *reinterpret_cast<const float4*>(A + (size_t)(rowBase + aRow) * K + k0 + aCol)
                  : make_float4(0.f, 0.f, 0.f, 0.f);
        av1 = aV1 ? *reinterpret_cast<const float4*>(A + (size_t)(rowBase + aRow + 64) * K + k0 + aCol)
                  : make_float4(0.f, 0.f, 0.f, 0.f);
        bv0 = *reinterpret_cast<const float4*>(B + (size_t)(k0 + bRow) * NOUT + colBase + bCol);
        bv1 = *reinterpret_cast<const float4*>(B + (size_t)(k0 + bRow + 8) * NOUT + colBase + bCol);
    }

#pragma unroll 1
    for (int t = 0; t < T; ++t) {
        __syncthreads();   // previous compute done before overwriting smem
        As[aCol + 0][aRow]      = av0.x;
        As[aCol + 1][aRow]      = av0.y;
        As[aCol + 2][aRow]      = av0.z;
        As[aCol + 3][aRow]      = av0.w;
        As[aCol + 0][aRow + 64] = av1.x;
        As[aCol + 1][aRow + 64] = av1.y;
        As[aCol + 2][aRow + 64] = av1.z;
        As[aCol + 3][aRow + 64] = av1.w;
        *reinterpret_cast<float4*>(&Bs[bRow][bCol])     = bv0;
        *reinterpret_cast<float4*>(&Bs[bRow + 8][bCol]) = bv1;
        __syncthreads();

        // prefetch next tile into registers (hidden under compute)
        if (t + 1 < T) {
            int tn = t + 1;
            const float* A = (tn >= Kt) ? A1 : A0;
            const float* B = (tn >= Kt) ? B1 : B0;
            int k0 = (tn - (tn >= Kt ? Kt : 0)) * BK;
            av0 = aV0 ? *reinterpret_cast<const float4*>(A + (size_t)(rowBase + aRow) * K + k0 + aCol)
                      : make_float4(0.f, 0.f, 0.f, 0.f);
            av1 = aV1 ? *reinterpret_cast<const float4*>(A + (size_t)(rowBase + aRow + 64) * K + k0 + aCol)
                      : make_float4(0.f, 0.f, 0.f, 0.f);
            bv0 = *reinterpret_cast<const float4*>(B + (size_t)(k0 + bRow) * NOUT + colBase + bCol);
            bv1 = *reinterpret_cast<const float4*>(B + (size_t)(k0 + bRow + 8) * NOUT + colBase + bCol);
        }

#pragma unroll
        for (int kk = 0; kk < BK; ++kk) {
            float4 a0 = *reinterpret_cast<const float4*>(&As[kk][ty * TM]);
            float4 a1 = *reinterpret_cast<const float4*>(&As[kk][ty * TM + 4]);
            float4 b0 = *reinterpret_cast<const float4*>(&Bs[kk][tx * TN]);
            float4 b1 = *reinterpret_cast<const float4*>(&Bs[kk][tx * TN + 4]);
            unsigned long long rb[4];
            rb[0] = pack2(b0.x, b0.y);
            rb[1] = pack2(b0.z, b0.w);
            rb[2] = pack2(b1.x, b1.y);
            rb[3] = pack2(b1.z, b1.w);
            float ra[8] = {a0.x, a0.y, a0.z, a0.w, a1.x, a1.y, a1.z, a1.w};
#pragma unroll
            for (int i = 0; i < TM; ++i) {
                unsigned long long aa = pack2(ra[i], ra[i]);
#pragma unroll
                for (int j = 0; j < TN / 2; ++j)
                    acc[i][j] = fma2(aa, rb[j], acc[i][j]);
            }
        }
    }

    // epilogue: bias + optional relu + guarded store
    float bb[TN];
    {
        float4 t0 = *reinterpret_cast<const float4*>(&bias[colBase + tx * TN]);
        float4 t1 = *reinterpret_cast<const float4*>(&bias[colBase + tx * TN + 4]);
        bb[0]=t0.x; bb[1]=t0.y; bb[2]=t0.z; bb[3]=t0.w;
        bb[4]=t1.x; bb[5]=t1.y; bb[6]=t1.z; bb[7]=t1.w;
    }

#pragma unroll
    for (int i = 0; i < TM; ++i) {
        int r = rowBase + ty * TM + i;
        if (r < M_store) {
            float v[TN];
#pragma unroll
            for (int j = 0; j < TN / 2; ++j)
                unpack2(acc[i][j], v[2 * j], v[2 * j + 1]);
#pragma unroll
            for (int j = 0; j < TN; ++j) {
                v[j] += bb[j];
                if (do_relu) v[j] = fmaxf(v[j], 0.0f);
            }
            float4 s0 = make_float4(v[0], v[1], v[2], v[3]);
            float4 s1 = make_float4(v[4], v[5], v[6], v[7]);
            *reinterpret_cast<float4*>(&C[(size_t)r * NOUT + colBase + tx * TN])     = s0;
            *reinterpret_cast<float4*>(&C[(size_t)r * NOUT + colBase + tx * TN + 4]) = s1;
        }
    }
}

// ---------------- launcher ----------------
extern "C" void kernel_launch(void* const* d_in, const int* in_sizes, int n_in,
                              void* d_out, int out_size)
{
    const float* x    = (const float*)d_in[0];
    const int*   ei   = (const int*)d_in[1];     // int32 (JAX x64 disabled)
    const float* W1_0 = (const float*)d_in[2];
    const float* W1_1 = (const float*)d_in[3];
    const float* b1   = (const float*)d_in[4];
    const float* W2_0 = (const float*)d_in[5];
    const float* W2_1 = (const float*)d_in[6];
    const float* b2   = (const float*)d_in[7];
    const float* W3_0 = (const float*)d_in[8];
    const float* W3_1 = (const float*)d_in[9];
    const float* b3   = (const float*)d_in[10];
    float*       out  = (float*)d_out;

    const int TB = 256;
    // graph setup
    k_init <<<(NNODES + TB - 1) / TB, TB>>>();
    k_deg  <<<(NEDGES + TB - 1) / TB, TB>>>(ei);
    k_dinv <<<(NNODES + TB - 1) / TB, TB>>>();
    k_scan1<<<SCAN_BLOCKS, 1024>>>();
    k_scan2<<<SCAN_BLOCKS, 1024>>>();
    k_fill <<<(NEDGES + TB - 1) / TB, TB>>>(ei);

    dim3 ggrid(MP / BM, NOUT / BN);   // 391 x 2

    // layer 1 (K = 128): agg = L_hat @ x ; h1 = relu(x@W1_0 + agg@W1_1 + b1)
    k_spmm<128, SEL_EXT><<<NNODES, 128>>>(x);
    k_gemm<SEL_EXT, SEL_H1><<<ggrid, 256>>>(x, W1_0, W1_1, b1, nullptr, 128, MP, 1);

    // layer 2 (K = 256)
    k_spmm<256, SEL_H1><<<NNODES, 256>>>(nullptr);
    k_gemm<SEL_H1, SEL_H2><<<ggrid, 256>>>(nullptr, W2_0, W2_1, b2, nullptr, 256, MP, 1);

    // layer 3 (K = 256), no relu, store only real rows into d_out
    k_spmm<256, SEL_H2><<<NNODES, 256>>>(nullptr);
    k_gemm<SEL_H2, SEL_EXT><<<ggrid, 256>>>(nullptr, W3_0, W3_1, b3, out, 256, NNODES, 0);
}

// round 5
// speedup vs baseline: 1.9306x; 1.6374x over previous
#include <cuda_runtime.h>
#include <cuda_bf16.h>
#include <cstdint>

#define NNODES 50000
#define NEDGES 400000
#define MP     50048      // 391 * 128, padded row count for GEMM tiles
#define NOUT   256
#define SCAN_BLOCKS 49    // 49*1024 >= NNODES

// ---------------- static device scratch (no allocations allowed) ----------------
__device__ int   g_deg[NNODES];
__device__ int   g_cnt[NNODES];
__device__ int   g_fill[NNODES];
__device__ float g_dinv[NNODES];
__device__ int   g_rowptr[NNODES + 1];
__device__ int   g_bsum[SCAN_BLOCKS];
__device__ int   g_col[NEDGES];
__device__ float g_wval[NEDGES];
__device__ float g_agg[(size_t)MP * 256];
__device__ float g_h1 [(size_t)MP * 256];
__device__ float g_h2 [(size_t)MP * 256];

#define SEL_EXT 0
#define SEL_H1  1
#define SEL_H2  2

__device__ __forceinline__ const float* sel_cbuf(int SEL, const float* ext) {
    switch (SEL) {
        case SEL_H1: return g_h1;
        case SEL_H2: return g_h2;
        default:     return ext;
    }
}
__device__ __forceinline__ float* sel_buf(int SEL, float* ext) {
    switch (SEL) {
        case SEL_H1: return g_h1;
        case SEL_H2: return g_h2;
        default:     return ext;
    }
}

// ---------------- tf32 helpers ----------------
__device__ __forceinline__ uint32_t f2tf32(float f) {
    uint32_t r;
    asm("cvt.rna.tf32.f32 %0, %1;" : "=r"(r) : "f"(f));
    return r;
}
__device__ __forceinline__ void mma_tf32(float* c, const uint32_t* a, const uint32_t* b) {
    asm volatile(
        "mma.sync.aligned.m16n8k8.row.col.f32.tf32.tf32.f32 "
        "{%0,%1,%2,%3}, {%4,%5,%6,%7}, {%8,%9}, {%0,%1,%2,%3};"
        : "+f"(c[0]), "+f"(c[1]), "+f"(c[2]), "+f"(c[3])
        : "r"(a[0]), "r"(a[1]), "r"(a[2]), "r"(a[3]), "r"(b[0]), "r"(b[1]));
}

// ---------------- graph setup kernels ----------------
__global__ void k_init() {
    int i = blockIdx.x * blockDim.x + threadIdx.x;
    if (i < NNODES) { g_deg[i] = 0; g_cnt[i] = 0; g_fill[i] = 0; }
}

// edge_index is int32 (JAX default config disables x64)
__global__ void k_deg(const int* __restrict__ ei) {
    int e = blockIdx.x * blockDim.x + threadIdx.x;
    if (e < NEDGES) {
        int s = ei[e];
        int d = ei[NEDGES + e];
        if (s != d && (unsigned)s < NNODES && (unsigned)d < NNODES) {
            atomicAdd(&g_deg[s], 1);
            atomicAdd(&g_cnt[d], 1);
        }
    }
}

__global__ void k_dinv() {
    int i = blockIdx.x * blockDim.x + threadIdx.x;
    if (i < NNODES) {
        int dg = g_deg[i];
        g_dinv[i] = (dg > 0) ? rsqrtf((float)dg) : 0.0f;
    }
}

__global__ void k_scan1() {
    __shared__ int sh[1024];
    const int t = threadIdx.x;
    const int i = blockIdx.x * 1024 + t;
    int v = (i < NNODES) ? g_cnt[i] : 0;
    sh[t] = v;
    __syncthreads();
    for (int off = 1; off < 1024; off <<= 1) {
        int u = (t >= off) ? sh[t - off] : 0;
        __syncthreads();
        sh[t] += u;
        __syncthreads();
    }
    if (i < NNODES) g_rowptr[i] = sh[t] - v;
    if (t == 1023) g_bsum[blockIdx.x] = sh[1023];
}

__global__ void k_scan2() {
    __shared__ int sh[SCAN_BLOCKS];
    const int t = threadIdx.x;
    if (t < SCAN_BLOCKS) sh[t] = g_bsum[t];
    __syncthreads();
    int offset = 0, total = 0;
    for (int b = 0; b < SCAN_BLOCKS; ++b) {
        if (b < (int)blockIdx.x) offset += sh[b];
        total += sh[b];
    }
    const int i = blockIdx.x * 1024 + t;
    if (i < NNODES) g_rowptr[i] += offset;
    if (blockIdx.x == SCAN_BLOCKS - 1 && t == 0) g_rowptr[NNODES] = total;
}

__global__ void k_fill(const int* __restrict__ ei) {
    int e = blockIdx.x * blockDim.x + threadIdx.x;
    if (e < NEDGES) {
        int s = ei[e];
        int d = ei[NEDGES + e];
        if (s != d && (unsigned)s < NNODES && (unsigned)d < NNODES) {
            int pos = atomicAdd(&g_fill[d], 1);
            int idx = g_rowptr[d] + pos;
            g_col[idx]  = s;
            g_wval[idx] = -g_dinv[s] * g_dinv[d];
        }
    }
}

// ---------------- SpMM: g_agg[row,:] = sum_j w_j * in[col_j,:] ----------------
template <int F, int SEL_IN>
__global__ void k_spmm(const float* __restrict__ in_ext) {
    const float* __restrict__ in = sel_cbuf(SEL_IN, in_ext);
    const int row = blockIdx.x;
    const int f   = threadIdx.x;
    const int beg = g_rowptr[row];
    const int end = g_rowptr[row + 1];
    float acc0 = 0.f, acc1 = 0.f, acc2 = 0.f, acc3 = 0.f;
    int j = beg;
    for (; j + 3 < end; j += 4) {
        float w0 = g_wval[j];     int c0 = g_col[j];
        float w1 = g_wval[j + 1]; int c1 = g_col[j + 1];
        float w2 = g_wval[j + 2]; int c2 = g_col[j + 2];
        float w3 = g_wval[j + 3]; int c3 = g_col[j + 3];
        acc0 += w0 * __ldg(&in[(size_t)c0 * F + f]);
        acc1 += w1 * __ldg(&in[(size_t)c1 * F + f]);
        acc2 += w2 * __ldg(&in[(size_t)c2 * F + f]);
        acc3 += w3 * __ldg(&in[(size_t)c3 * F + f]);
    }
    for (; j < end; ++j) {
        float w = g_wval[j]; int c = g_col[j];
        acc0 += w * __ldg(&in[(size_t)c * F + f]);
    }
    g_agg[(size_t)row * F + f] = (acc0 + acc1) + (acc2 + acc3);
}

// ---------------- tensor-core fused dual-GEMM ----------------
// C = A0@B0 + g_agg@B1 + bias (opt relu), via mma.sync m16n8k8 tf32.
// Block 128x128, 128 threads (4 warps, 2x2), warp tile 64x64, BK=16,
// double-buffered smem, fragment layout [m][k]/[n][k] stride 20 (conflict-free).
#define BM 128
#define BN 128
#define BK 16
#define SK 20   // smem k-stride in words

template <int SEL_A0, int SEL_C>
__global__ void __launch_bounds__(128, 2) k_gemm(
    const float* __restrict__ A0_ext, const float* __restrict__ B0,
    const float* __restrict__ B1,
    const float* __restrict__ bias, float* __restrict__ C_ext,
    int K, int M_store, int do_relu)
{
    const float* __restrict__ A0 = sel_cbuf(SEL_A0, A0_ext);
    const float* __restrict__ A1 = g_agg;
    float* __restrict__ C = sel_buf(SEL_C, C_ext);

    __shared__ uint32_t As[2][BM * SK];   // [m][k]
    __shared__ uint32_t Bs[2][BN * SK];   // [n][k]

    const int tid  = threadIdx.x;        // 0..127
    const int warp = tid >> 5;           // 0..3
    const int lane = tid & 31;
    const int gid  = lane >> 2;          // 0..7
    const int tig  = lane & 3;           // 0..3
    const int wm   = (warp >> 1) * 64;   // warp row offset in block tile
    const int wn   = (warp & 1)  * 64;   // warp col offset

    const int rowBase = blockIdx.x * BM;
    const int colBase = blockIdx.y * BN;

    const bool aValid = (rowBase + tid < NNODES);  // loader row = rowBase + tid

    const int Kt = K / BK;     // tiles per pass
    const int T  = 2 * Kt;     // A0 pass then A1(g_agg) pass

    float acc[4][8][4];
#pragma unroll
    for (int mt = 0; mt < 4; ++mt)
#pragma unroll
        for (int nt = 0; nt < 8; ++nt)
#pragma unroll
            for (int q = 0; q < 4; ++q) acc[mt][nt][q] = 0.0f;

    float4 av[4];      // staged A row (16 k-values)
    float  bv[16];     // staged B col (16 k-values)

    // ---- stage tile 0 ----
    {
        const float* A = A0; const float* B = B0; const int k0 = 0;
#pragma unroll
        for (int q = 0; q < 4; ++q)
            av[q] = aValid
                ? *reinterpret_cast<const float4*>(A + (size_t)(rowBase + tid) * K + k0 + 4 * q)
                : make_float4(0.f, 0.f, 0.f, 0.f);
#pragma unroll
        for (int k = 0; k < 16; ++k)
            bv[k] = B[(size_t)(k0 + k) * NOUT + colBase + tid];
    }
    // store tile 0 -> buffer 0
    {
        uint32_t* as = As[0]; uint32_t* bs = Bs[0];
#pragma unroll
        for (int q = 0; q < 4; ++q) {
            uint4 s = make_uint4(f2tf32(av[q].x), f2tf32(av[q].y), f2tf32(av[q].z), f2tf32(av[q].w));
            *reinterpret_cast<uint4*>(&as[tid * SK + 4 * q]) = s;
        }
#pragma unroll
        for (int q = 0; q < 4; ++q) {
            uint4 s = make_uint4(f2tf32(bv[4 * q + 0]), f2tf32(bv[4 * q + 1]),
                                 f2tf32(bv[4 * q + 2]), f2tf32(bv[4 * q + 3]));
            *reinterpret_cast<uint4*>(&bs[tid * SK + 4 * q]) = s;
        }
    }
    __syncthreads();

#pragma unroll 1
    for (int t = 0; t < T; ++t) {
        const int cur = t & 1;

        // stage next tile (global -> regs), hidden under mma
        if (t + 1 < T) {
            const int tn = t + 1;
            const bool p2 = (tn >= Kt);
            const float* A = p2 ? A1 : A0;
            const float* B = p2 ? B1 : B0;
            const int k0 = (tn - (p2 ? Kt : 0)) * BK;
#pragma unroll
            for (int q = 0; q < 4; ++q)
                av[q] = aValid
                    ? *reinterpret_cast<const float4*>(A + (size_t)(rowBase + tid) * K + k0 + 4 * q)
                    : make_float4(0.f, 0.f, 0.f, 0.f);
#pragma unroll
            for (int k = 0; k < 16; ++k)
                bv[k] = B[(size_t)(k0 + k) * NOUT + colBase + tid];
        }

        // compute on current buffer: two k8 halves
        {
            const uint32_t* as = As[cur];
            const uint32_t* bs = Bs[cur];
#pragma unroll
            for (int kh = 0; kh < 2; ++kh) {
                const int ko = kh * 8;
                uint32_t a[4][4], b[8][2];
#pragma unroll
                for (int mt = 0; mt < 4; ++mt) {
                    const int mr = (wm + mt * 16 + gid) * SK + ko + tig;
                    a[mt][0] = as[mr];
                    a[mt][1] = as[mr + 8 * SK];
                    a[mt][2] = as[mr + 4];
                    a[mt][3] = as[mr + 8 * SK + 4];
                }
#pragma unroll
                for (int nt = 0; nt < 8; ++nt) {
                    const int nr = (wn + nt * 8 + gid) * SK + ko + tig;
                    b[nt][0] = bs[nr];
                    b[nt][1] = bs[nr + 4];
                }
#pragma unroll
                for (int mt = 0; mt < 4; ++mt)
#pragma unroll
                    for (int nt = 0; nt < 8; ++nt)
                        mma_tf32(acc[mt][nt], a[mt], b[nt]);
            }
        }

        // store staged tile -> other buffer
        if (t + 1 < T) {
            const int nxt = cur ^ 1;
            uint32_t* as = As[nxt]; uint32_t* bs = Bs[nxt];
#pragma unroll
            for (int q = 0; q < 4; ++q) {
                uint4 s = make_uint4(f2tf32(av[q].x), f2tf32(av[q].y), f2tf32(av[q].z), f2tf32(av[q].w));
                *reinterpret_cast<uint4*>(&as[tid * SK + 4 * q]) = s;
            }
#pragma unroll
            for (int q = 0; q < 4; ++q) {
                uint4 s = make_uint4(f2tf32(bv[4 * q + 0]), f2tf32(bv[4 * q + 1]),
                                     f2tf32(bv[4 * q + 2]), f2tf32(bv[4 * q + 3]));
                *reinterpret_cast<uint4*>(&bs[tid * SK + 4 * q]) = s;
            }
            __syncthreads();
        }
    }

    // ---- epilogue: bias + optional relu + guarded float2 stores ----
    float2 bb[8];
#pragma unroll
    for (int nt = 0; nt < 8; ++nt)
        bb[nt] = *reinterpret_cast<const float2*>(&bias[colBase + wn + nt * 8 + 2 * tig]);

#pragma unroll
    for (int mt = 0; mt < 4; ++mt) {
        const int r0 = rowBase + wm + mt * 16 + gid;
        const int r1 = r0 + 8;
#pragma unroll
        for (int nt = 0; nt < 8; ++nt) {
            const int c = colBase + wn + nt * 8 + 2 * tig;
            float v0 = acc[mt][nt][0] + bb[nt].x;
            float v1 = acc[mt][nt][1] + bb[nt].y;
            float v2 = acc[mt][nt][2] + bb[nt].x;
            float v3 = acc[mt][nt][3] + bb[nt].y;
            if (do_relu) {
                v0 = fmaxf(v0, 0.f); v1 = fmaxf(v1, 0.f);
                v2 = fmaxf(v2, 0.f); v3 = fmaxf(v3, 0.f);
            }
            if (r0 < M_store)
                *reinterpret_cast<float2*>(&C[(size_t)r0 * NOUT + c]) = make_float2(v0, v1);
            if (r1 < M_store)
                *reinterpret_cast<float2*>(&C[(size_t)r1 * NOUT + c]) = make_float2(v2, v3);
        }
    }
}

// ---------------- launcher ----------------
extern "C" void kernel_launch(void* const* d_in, const int* in_sizes, int n_in,
                              void* d_out, int out_size)
{
    const float* x    = (const float*)d_in[0];
    const int*   ei   = (const int*)d_in[1];     // int32 (JAX x64 disabled)
    const float* W1_0 = (const float*)d_in[2];
    const float* W1_1 = (const float*)d_in[3];
    const float* b1   = (const float*)d_in[4];
    const float* W2_0 = (const float*)d_in[5];
    const float* W2_1 = (const float*)d_in[6];
    const float* b2   = (const float*)d_in[7];
    const float* W3_0 = (const float*)d_in[8];
    const float* W3_1 = (const float*)d_in[9];
    const float* b3   = (const float*)d_in[10];
    float*       out  = (float*)d_out;

    const int TB = 256;
    k_init <<<(NNODES + TB - 1) / TB, TB>>>();
    k_deg  <<<(NEDGES + TB - 1) / TB, TB>>>(ei);
    k_dinv <<<(NNODES + TB - 1) / TB, TB>>>();
    k_scan1<<<SCAN_BLOCKS, 1024>>>();
    k_scan2<<<SCAN_BLOCKS, 1024>>>();
    k_fill <<<(NEDGES + TB - 1) / TB, TB>>>(ei);

    dim3 ggrid(MP / BM, NOUT / BN);   // 391 x 2

    // layer 1 (K = 128)
    k_spmm<128, SEL_EXT><<<NNODES, 128>>>(x);
    k_gemm<SEL_EXT, SEL_H1><<<ggrid, 128>>>(x, W1_0, W1_1, b1, nullptr, 128, MP, 1);

    // layer 2 (K = 256)
    k_spmm<256, SEL_H1><<<NNODES, 256>>>(nullptr);
    k_gemm<SEL_H1, SEL_H2><<<ggrid, 128>>>(nullptr, W2_0, W2_1, b2, nullptr, 256, MP, 1);

    // layer 3 (K = 256), no relu, store only real rows into d_out
    k_spmm<256, SEL_H2><<<NNODES, 256>>>(nullptr);
    k_gemm<SEL_H2, SEL_EXT><<<ggrid, 128>>>(nullptr, W3_0, W3_1, b3, out, 256, NNODES, 0);
}

// round 6
// speedup vs baseline: 2.3386x; 1.2113x over previous
#include <cuda_runtime.h>
#include <cuda_bf16.h>
#include <cstdint>

#define NNODES 50000
#define NEDGES 400000
#define MP     50048      // 391 * 128, padded row count for GEMM tiles
#define NOUT   256
#define SCAN_BLOCKS 49    // 49*1024 >= NNODES

// ---------------- static device scratch (no allocations allowed) ----------------
__device__ int   g_deg[NNODES];
__device__ int   g_cnt[NNODES];
__device__ int   g_fill[NNODES];
__device__ float g_dinv[NNODES];
__device__ int   g_rowptr[NNODES + 1];
__device__ int   g_bsum[SCAN_BLOCKS];
__device__ int   g_col[NEDGES];
__device__ float g_wval[NEDGES];
__device__ float g_agg[(size_t)MP * 256];
__device__ float g_h1 [(size_t)MP * 256];
__device__ float g_h2 [(size_t)MP * 256];

#define SEL_EXT 0
#define SEL_H1  1
#define SEL_H2  2

__device__ __forceinline__ const float* sel_cbuf(int SEL, const float* ext) {
    switch (SEL) {
        case SEL_H1: return g_h1;
        case SEL_H2: return g_h2;
        default:     return ext;
    }
}
__device__ __forceinline__ float* sel_buf(int SEL, float* ext) {
    switch (SEL) {
        case SEL_H1: return g_h1;
        case SEL_H2: return g_h2;
        default:     return ext;
    }
}

// ---------------- tf32 helpers ----------------
__device__ __forceinline__ uint32_t f2tf32(float f) {
    uint32_t r;
    asm("cvt.rna.tf32.f32 %0, %1;" : "=r"(r) : "f"(f));
    return r;
}
__device__ __forceinline__ void mma_tf32(float* c, const uint32_t* a, const uint32_t* b) {
    asm volatile(
        "mma.sync.aligned.m16n8k8.row.col.f32.tf32.tf32.f32 "
        "{%0,%1,%2,%3}, {%4,%5,%6,%7}, {%8,%9}, {%0,%1,%2,%3};"
        : "+f"(c[0]), "+f"(c[1]), "+f"(c[2]), "+f"(c[3])
        : "r"(a[0]), "r"(a[1]), "r"(a[2]), "r"(a[3]), "r"(b[0]), "r"(b[1]));
}

// ---------------- graph setup kernels ----------------
__global__ void k_init() {
    int i = blockIdx.x * blockDim.x + threadIdx.x;
    if (i < NNODES) { g_deg[i] = 0; g_cnt[i] = 0; g_fill[i] = 0; }
}

// edge_index is int32 (JAX default config disables x64)
__global__ void k_deg(const int* __restrict__ ei) {
    int e = blockIdx.x * blockDim.x + threadIdx.x;
    if (e < NEDGES) {
        int s = ei[e];
        int d = ei[NEDGES + e];
        if (s != d && (unsigned)s < NNODES && (unsigned)d < NNODES) {
            atomicAdd(&g_deg[s], 1);
            atomicAdd(&g_cnt[d], 1);
        }
    }
}

__global__ void k_dinv() {
    int i = blockIdx.x * blockDim.x + threadIdx.x;
    if (i < NNODES) {
        int dg = g_deg[i];
        g_dinv[i] = (dg > 0) ? rsqrtf((float)dg) : 0.0f;
    }
}

__global__ void k_scan1() {
    __shared__ int sh[1024];
    const int t = threadIdx.x;
    const int i = blockIdx.x * 1024 + t;
    int v = (i < NNODES) ? g_cnt[i] : 0;
    sh[t] = v;
    __syncthreads();
    for (int off = 1; off < 1024; off <<= 1) {
        int u = (t >= off) ? sh[t - off] : 0;
        __syncthreads();
        sh[t] += u;
        __syncthreads();
    }
    if (i < NNODES) g_rowptr[i] = sh[t] - v;
    if (t == 1023) g_bsum[blockIdx.x] = sh[1023];
}

__global__ void k_scan2() {
    __shared__ int sh[SCAN_BLOCKS];
    const int t = threadIdx.x;
    if (t < SCAN_BLOCKS) sh[t] = g_bsum[t];
    __syncthreads();
    int offset = 0, total = 0;
    for (int b = 0; b < SCAN_BLOCKS; ++b) {
        if (b < (int)blockIdx.x) offset += sh[b];
        total += sh[b];
    }
    const int i = blockIdx.x * 1024 + t;
    if (i < NNODES) g_rowptr[i] += offset;
    if (blockIdx.x == SCAN_BLOCKS - 1 && t == 0) g_rowptr[NNODES] = total;
}

__global__ void k_fill(const int* __restrict__ ei) {
    int e = blockIdx.x * blockDim.x + threadIdx.x;
    if (e < NEDGES) {
        int s = ei[e];
        int d = ei[NEDGES + e];
        if (s != d && (unsigned)s < NNODES && (unsigned)d < NNODES) {
            int pos = atomicAdd(&g_fill[d], 1);
            int idx = g_rowptr[d] + pos;
            g_col[idx]  = s;
            g_wval[idx] = -g_dinv[s] * g_dinv[d];
        }
    }
}

// ---------------- SpMM: g_agg[row,:] = sum_j w_j * in[col_j,:] (float2 lanes) ----
template <int F, int SEL_IN>
__global__ void k_spmm(const float* __restrict__ in_ext) {
    const float2* __restrict__ in =
        reinterpret_cast<const float2*>(sel_cbuf(SEL_IN, in_ext));
    const int row = blockIdx.x;
    const int f2  = threadIdx.x;              // F/2 threads
    const int W2  = F / 2;
    const int beg = g_rowptr[row];
    const int end = g_rowptr[row + 1];
    float ax0 = 0.f, ay0 = 0.f, ax1 = 0.f, ay1 = 0.f;
    float ax2 = 0.f, ay2 = 0.f, ax3 = 0.f, ay3 = 0.f;
    int j = beg;
    for (; j + 3 < end; j += 4) {
        float w0 = g_wval[j];     int c0 = g_col[j];
        float w1 = g_wval[j + 1]; int c1 = g_col[j + 1];
        float w2 = g_wval[j + 2]; int c2 = g_col[j + 2];
        float w3 = g_wval[j + 3]; int c3 = g_col[j + 3];
        float2 v0 = __ldg(&in[(size_t)c0 * W2 + f2]);
        float2 v1 = __ldg(&in[(size_t)c1 * W2 + f2]);
        float2 v2 = __ldg(&in[(size_t)c2 * W2 + f2]);
        float2 v3 = __ldg(&in[(size_t)c3 * W2 + f2]);
        ax0 += w0 * v0.x; ay0 += w0 * v0.y;
        ax1 += w1 * v1.x; ay1 += w1 * v1.y;
        ax2 += w2 * v2.x; ay2 += w2 * v2.y;
        ax3 += w3 * v3.x; ay3 += w3 * v3.y;
    }
    for (; j < end; ++j) {
        float w = g_wval[j]; int c = g_col[j];
        float2 v = __ldg(&in[(size_t)c * W2 + f2]);
        ax0 += w * v.x; ay0 += w * v.y;
    }
    float2 r;
    r.x = (ax0 + ax1) + (ax2 + ax3);
    r.y = (ay0 + ay1) + (ay2 + ay3);
    reinterpret_cast<float2*>(g_agg)[(size_t)row * W2 + f2] = r;
}

// ---------------- tensor-core fused dual-GEMM ----------------
// C = A0@B0 + g_agg@B1 + bias (opt relu), via mma.sync m16n8k8 tf32.
// Block 128x128, 128 threads (4 warps 2x2), warp tile 64x64, BK=16,
// double-buffered smem. As: [m][k] stride 20 (conflict-free both sides).
// Bs: [k][n] stride 136 (conflict-free both sides, enables LDG.128 staging).
#define BM 128
#define BN 128
#define BK 16
#define SKA 20    // As k-stride in words
#define SNB 136   // Bs n-stride in words

template <int SEL_A0, int SEL_C>
__global__ void __launch_bounds__(128, 2) k_gemm(
    const float* __restrict__ A0_ext, const float* __restrict__ B0,
    const float* __restrict__ B1,
    const float* __restrict__ bias, float* __restrict__ C_ext,
    int K, int M_store, int do_relu)
{
    const float* __restrict__ A0 = sel_cbuf(SEL_A0, A0_ext);
    const float* __restrict__ A1 = g_agg;
    float* __restrict__ C = sel_buf(SEL_C, C_ext);

    __shared__ uint32_t As[2][BM * SKA];   // [m][k]
    __shared__ uint32_t Bs[2][BK * SNB];   // [k][n]

    const int tid  = threadIdx.x;        // 0..127
    const int warp = tid >> 5;           // 0..3
    const int lane = tid & 31;
    const int gid  = lane >> 2;          // 0..7
    const int tig  = lane & 3;           // 0..3
    const int wm   = (warp >> 1) * 64;   // warp row offset
    const int wn   = (warp & 1)  * 64;   // warp col offset

    const int rowBase = blockIdx.x * BM;
    const int colBase = blockIdx.y * BN;

    const bool aValid = (rowBase + tid < NNODES);

    // B loader: thread covers rows {w, w+4, w+8, w+12} (w = warp), 4 cols at 4*lane
    const int bR = warp;
    const int bC = lane * 4;

    const int Kt = K / BK;     // tiles per pass
    const int T  = 2 * Kt;     // A0 pass then A1(g_agg) pass

    float acc[4][8][4];
#pragma unroll
    for (int mt = 0; mt < 4; ++mt)
#pragma unroll
        for (int nt = 0; nt < 8; ++nt)
#pragma unroll
            for (int q = 0; q < 4; ++q) acc[mt][nt][q] = 0.0f;

    float4 av[4];      // staged A row (16 k-values)
    float4 bv[4];      // staged B: rows bR+4q, cols bC..bC+3

    // ---- stage tile 0 ----
    {
        const float* A = A0; const float* B = B0; const int k0 = 0;
#pragma unroll
        for (int q = 0; q < 4; ++q)
            av[q] = aValid
                ? *reinterpret_cast<const float4*>(A + (size_t)(rowBase + tid) * K + k0 + 4 * q)
                : make_float4(0.f, 0.f, 0.f, 0.f);
#pragma unroll
        for (int q = 0; q < 4; ++q)
            bv[q] = *reinterpret_cast<const float4*>(B + (size_t)(k0 + bR + 4 * q) * NOUT + colBase + bC);
    }
    {
        uint32_t* as = As[0]; uint32_t* bs = Bs[0];
#pragma unroll
        for (int q = 0; q < 4; ++q) {
            uint4 s = make_uint4(f2tf32(av[q].x), f2tf32(av[q].y), f2tf32(av[q].z), f2tf32(av[q].w));
            *reinterpret_cast<uint4*>(&as[tid * SKA + 4 * q]) = s;
        }
#pragma unroll
        for (int q = 0; q < 4; ++q) {
            uint4 s = make_uint4(f2tf32(bv[q].x), f2tf32(bv[q].y), f2tf32(bv[q].z), f2tf32(bv[q].w));
            *reinterpret_cast<uint4*>(&bs[(bR + 4 * q) * SNB + bC]) = s;
        }
    }
    __syncthreads();

#pragma unroll 1
    for (int t = 0; t < T; ++t) {
        const int cur = t & 1;

        // stage next tile (global -> regs), hidden under mma
        if (t + 1 < T) {
            const int tn = t + 1;
            const bool p2 = (tn >= Kt);
            const float* A = p2 ? A1 : A0;
            const float* B = p2 ? B1 : B0;
            const int k0 = (tn - (p2 ? Kt : 0)) * BK;
#pragma unroll
            for (int q = 0; q < 4; ++q)
                av[q] = aValid
                    ? *reinterpret_cast<const float4*>(A + (size_t)(rowBase + tid) * K + k0 + 4 * q)
                    : make_float4(0.f, 0.f, 0.f, 0.f);
#pragma unroll
            for (int q = 0; q < 4; ++q)
                bv[q] = *reinterpret_cast<const float4*>(B + (size_t)(k0 + bR + 4 * q) * NOUT + colBase + bC);
        }

        // compute on current buffer: two k8 halves
        {
            const uint32_t* as = As[cur];
            const uint32_t* bs = Bs[cur];
#pragma unroll
            for (int kh = 0; kh < 2; ++kh) {
                const int ko = kh * 8;
                uint32_t a[4][4], b[8][2];
#pragma unroll
                for (int mt = 0; mt < 4; ++mt) {
                    const int mr = (wm + mt * 16 + gid) * SKA + ko + tig;
                    a[mt][0] = as[mr];
                    a[mt][1] = as[mr + 8 * SKA];
                    a[mt][2] = as[mr + 4];
                    a[mt][3] = as[mr + 8 * SKA + 4];
                }
#pragma unroll
                for (int nt = 0; nt < 8; ++nt) {
                    const int nr = (ko + tig) * SNB + wn + nt * 8 + gid;
                    b[nt][0] = bs[nr];
                    b[nt][1] = bs[nr + 4 * SNB];
                }
#pragma unroll
                for (int mt = 0; mt < 4; ++mt)
#pragma unroll
                    for (int nt = 0; nt < 8; ++nt)
                        mma_tf32(acc[mt][nt], a[mt], b[nt]);
            }
        }

        // store staged tile -> other buffer
        if (t + 1 < T) {
            const int nxt = cur ^ 1;
            uint32_t* as = As[nxt]; uint32_t* bs = Bs[nxt];
#pragma unroll
            for (int q = 0; q < 4; ++q) {
                uint4 s = make_uint4(f2tf32(av[q].x), f2tf32(av[q].y), f2tf32(av[q].z), f2tf32(av[q].w));
                *reinterpret_cast<uint4*>(&as[tid * SKA + 4 * q]) = s;
            }
#pragma unroll
            for (int q = 0; q < 4; ++q) {
                uint4 s = make_uint4(f2tf32(bv[q].x), f2tf32(bv[q].y), f2tf32(bv[q].z), f2tf32(bv[q].w));
                *reinterpret_cast<uint4*>(&bs[(bR + 4 * q) * SNB + bC]) = s;
            }
            __syncthreads();
        }
    }

    // ---- epilogue: bias + optional relu + guarded float2 stores ----
    float2 bb[8];
#pragma unroll
    for (int nt = 0; nt < 8; ++nt)
        bb[nt] = *reinterpret_cast<const float2*>(&bias[colBase + wn + nt * 8 + 2 * tig]);

#pragma unroll
    for (int mt = 0; mt < 4; ++mt) {
        const int r0 = rowBase + wm + mt * 16 + gid;
        const int r1 = r0 + 8;
#pragma unroll
        for (int nt = 0; nt < 8; ++nt) {
            const int c = colBase + wn + nt * 8 + 2 * tig;
            float v0 = acc[mt][nt][0] + bb[nt].x;
            float v1 = acc[mt][nt][1] + bb[nt].y;
            float v2 = acc[mt][nt][2] + bb[nt].x;
            float v3 = acc[mt][nt][3] + bb[nt].y;
            if (do_relu) {
                v0 = fmaxf(v0, 0.f); v1 = fmaxf(v1, 0.f);
                v2 = fmaxf(v2, 0.f); v3 = fmaxf(v3, 0.f);
            }
            if (r0 < M_store)
                *reinterpret_cast<float2*>(&C[(size_t)r0 * NOUT + c]) = make_float2(v0, v1);
            if (r1 < M_store)
                *reinterpret_cast<float2*>(&C[(size_t)r1 * NOUT + c]) = make_float2(v2, v3);
        }
    }
}

// ---------------- launcher ----------------
extern "C" void kernel_launch(void* const* d_in, const int* in_sizes, int n_in,
                              void* d_out, int out_size)
{
    const float* x    = (const float*)d_in[0];
    const int*   ei   = (const int*)d_in[1];     // int32 (JAX x64 disabled)
    const float* W1_0 = (const float*)d_in[2];
    const float* W1_1 = (const float*)d_in[3];
    const float* b1   = (const float*)d_in[4];
    const float* W2_0 = (const float*)d_in[5];
    const float* W2_1 = (const float*)d_in[6];
    const float* b2   = (const float*)d_in[7];
    const float* W3_0 = (const float*)d_in[8];
    const float* W3_1 = (const float*)d_in[9];
    const float* b3   = (const float*)d_in[10];
    float*       out  = (float*)d_out;

    const int TB = 256;
    k_init <<<(NNODES + TB - 1) / TB, TB>>>();
    k_deg  <<<(NEDGES + TB - 1) / TB, TB>>>(ei);
    k_dinv <<<(NNODES + TB - 1) / TB, TB>>>();
    k_scan1<<<SCAN_BLOCKS, 1024>>>();
    k_scan2<<<SCAN_BLOCKS, 1024>>>();
    k_fill <<<(NEDGES + TB - 1) / TB, TB>>>(ei);

    dim3 ggrid(MP / BM, NOUT / BN);   // 391 x 2

    // layer 1 (K = 128)
    k_spmm<128, SEL_EXT><<<NNODES, 64>>>(x);
    k_gemm<SEL_EXT, SEL_H1><<<ggrid, 128>>>(x, W1_0, W1_1, b1, nullptr, 128, MP, 1);

    // layer 2 (K = 256)
    k_spmm<256, SEL_H1><<<NNODES, 128>>>(nullptr);
    k_gemm<SEL_H1, SEL_H2><<<ggrid, 128>>>(nullptr, W2_0, W2_1, b2, nullptr, 256, MP, 1);

    // layer 3 (K = 256), no relu, store only real rows into d_out
    k_spmm<256, SEL_H2><<<NNODES, 128>>>(nullptr);
    k_gemm<SEL_H2, SEL_EXT><<<ggrid, 128>>>(nullptr, W3_0, W3_1, b3, out, 256, NNODES, 0);
}

// round 7
// speedup vs baseline: 2.4003x; 1.0264x over previous
#include <cuda_runtime.h>
#include <cuda_bf16.h>
#include <cstdint>

#define NNODES 50000
#define NEDGES 400000
#define MP     50048      // 391 * 128, padded row count for GEMM tiles
#define NOUT   256
#define SCAN_BLOCKS 49    // 49*1024 >= NNODES

// ---------------- static device scratch (no allocations allowed) ----------------
__device__ int   g_deg[NNODES];
__device__ int   g_cnt[NNODES];
__device__ int   g_fill[NNODES];
__device__ float g_dinv[NNODES];
__device__ int   g_rowptr[NNODES + 1];
__device__ int   g_bsum[SCAN_BLOCKS];
__device__ int   g_col[NEDGES];
__device__ float g_wval[NEDGES];
__device__ float g_agg[(size_t)MP * 256];
__device__ float g_h1 [(size_t)MP * 256];
__device__ float g_h2 [(size_t)MP * 256];

#define SEL_EXT 0
#define SEL_H1  1
#define SEL_H2  2

__device__ __forceinline__ const float* sel_cbuf(int SEL, const float* ext) {
    switch (SEL) {
        case SEL_H1: return g_h1;
        case SEL_H2: return g_h2;
        default:     return ext;
    }
}
__device__ __forceinline__ float* sel_buf(int SEL, float* ext) {
    switch (SEL) {
        case SEL_H1: return g_h1;
        case SEL_H2: return g_h2;
        default:     return ext;
    }
}

// ---------------- tf32 helpers ----------------
__device__ __forceinline__ uint32_t f2tf32(float f) {
    uint32_t r;
    asm("cvt.rna.tf32.f32 %0, %1;" : "=r"(r) : "f"(f));
    return r;
}
__device__ __forceinline__ void mma_tf32(float* c, const uint32_t* a, const uint32_t* b) {
    asm volatile(
        "mma.sync.aligned.m16n8k8.row.col.f32.tf32.tf32.f32 "
        "{%0,%1,%2,%3}, {%4,%5,%6,%7}, {%8,%9}, {%0,%1,%2,%3};"
        : "+f"(c[0]), "+f"(c[1]), "+f"(c[2]), "+f"(c[3])
        : "r"(a[0]), "r"(a[1]), "r"(a[2]), "r"(a[3]), "r"(b[0]), "r"(b[1]));
}

// ---------------- graph setup kernels ----------------
__global__ void k_init() {
    int i = blockIdx.x * blockDim.x + threadIdx.x;
    if (i < NNODES) { g_deg[i] = 0; g_cnt[i] = 0; g_fill[i] = 0; }
}

// edge_index is int32 (JAX default config disables x64)
__global__ void k_deg(const int* __restrict__ ei) {
    int e = blockIdx.x * blockDim.x + threadIdx.x;
    if (e < NEDGES) {
        int s = ei[e];
        int d = ei[NEDGES + e];
        if (s != d && (unsigned)s < NNODES && (unsigned)d < NNODES) {
            atomicAdd(&g_deg[s], 1);
            atomicAdd(&g_cnt[d], 1);
        }
    }
}

__global__ void k_dinv() {
    int i = blockIdx.x * blockDim.x + threadIdx.x;
    if (i < NNODES) {
        int dg = g_deg[i];
        g_dinv[i] = (dg > 0) ? rsqrtf((float)dg) : 0.0f;
    }
}

__global__ void k_scan1() {
    __shared__ int sh[1024];
    const int t = threadIdx.x;
    const int i = blockIdx.x * 1024 + t;
    int v = (i < NNODES) ? g_cnt[i] : 0;
    sh[t] = v;
    __syncthreads();
    for (int off = 1; off < 1024; off <<= 1) {
        int u = (t >= off) ? sh[t - off] : 0;
        __syncthreads();
        sh[t] += u;
        __syncthreads();
    }
    if (i < NNODES) g_rowptr[i] = sh[t] - v;
    if (t == 1023) g_bsum[blockIdx.x] = sh[1023];
}

__global__ void k_scan2() {
    __shared__ int sh[SCAN_BLOCKS];
    const int t = threadIdx.x;
    if (t < SCAN_BLOCKS) sh[t] = g_bsum[t];
    __syncthreads();
    int offset = 0, total = 0;
    for (int b = 0; b < SCAN_BLOCKS; ++b) {
        if (b < (int)blockIdx.x) offset += sh[b];
        total += sh[b];
    }
    const int i = blockIdx.x * 1024 + t;
    if (i < NNODES) g_rowptr[i] += offset;
    if (blockIdx.x == SCAN_BLOCKS - 1 && t == 0) g_rowptr[NNODES] = total;
}

__global__ void k_fill(const int* __restrict__ ei) {
    int e = blockIdx.x * blockDim.x + threadIdx.x;
    if (e < NEDGES) {
        int s = ei[e];
        int d = ei[NEDGES + e];
        if (s != d && (unsigned)s < NNODES && (unsigned)d < NNODES) {
            int pos = atomicAdd(&g_fill[d], 1);
            int idx = g_rowptr[d] + pos;
            g_col[idx]  = s;
            g_wval[idx] = -g_dinv[s] * g_dinv[d];
        }
    }
}

// ---------------- SpMM: g_agg[row,:] = sum_j w_j * in[col_j,:] (float2 lanes) ----
template <int F, int SEL_IN>
__global__ void k_spmm(const float* __restrict__ in_ext) {
    const float2* __restrict__ in =
        reinterpret_cast<const float2*>(sel_cbuf(SEL_IN, in_ext));
    const int row = blockIdx.x;
    const int f2  = threadIdx.x;              // F/2 threads
    const int W2  = F / 2;
    const int beg = g_rowptr[row];
    const int end = g_rowptr[row + 1];
    float ax0 = 0.f, ay0 = 0.f, ax1 = 0.f, ay1 = 0.f;
    float ax2 = 0.f, ay2 = 0.f, ax3 = 0.f, ay3 = 0.f;
    int j = beg;
    for (; j + 3 < end; j += 4) {
        float w0 = g_wval[j];     int c0 = g_col[j];
        float w1 = g_wval[j + 1]; int c1 = g_col[j + 1];
        float w2 = g_wval[j + 2]; int c2 = g_col[j + 2];
        float w3 = g_wval[j + 3]; int c3 = g_col[j + 3];
        float2 v0 = __ldg(&in[(size_t)c0 * W2 + f2]);
        float2 v1 = __ldg(&in[(size_t)c1 * W2 + f2]);
        float2 v2 = __ldg(&in[(size_t)c2 * W2 + f2]);
        float2 v3 = __ldg(&in[(size_t)c3 * W2 + f2]);
        ax0 += w0 * v0.x; ay0 += w0 * v0.y;
        ax1 += w1 * v1.x; ay1 += w1 * v1.y;
        ax2 += w2 * v2.x; ay2 += w2 * v2.y;
        ax3 += w3 * v3.x; ay3 += w3 * v3.y;
    }
    for (; j < end; ++j) {
        float w = g_wval[j]; int c = g_col[j];
        float2 v = __ldg(&in[(size_t)c * W2 + f2]);
        ax0 += w * v.x; ay0 += w * v.y;
    }
    float2 r;
    r.x = (ax0 + ax1) + (ax2 + ax3);
    r.y = (ay0 + ay1) + (ay2 + ay3);
    reinterpret_cast<float2*>(g_agg)[(size_t)row * W2 + f2] = r;
}

// ---------------- tensor-core fused dual-GEMM ----------------
// C = A0@B0 + g_agg@B1 + bias (opt relu), via mma.sync m16n8k8 tf32.
// Block 128x128, 256 threads (8 warps, 4x2), warp tile 32x64, BK=16,
// double-buffered smem. As: [m][k] stride 20; Bs: [k][n] stride 136.
#define BM 128
#define BN 128
#define BK 16
#define SKA 20    // As k-stride in words
#define SNB 136   // Bs n-stride in words

template <int SEL_A0, int SEL_C>
__global__ void __launch_bounds__(256, 2) k_gemm(
    const float* __restrict__ A0_ext, const float* __restrict__ B0,
    const float* __restrict__ B1,
    const float* __restrict__ bias, float* __restrict__ C_ext,
    int K, int M_store, int do_relu)
{
    const float* __restrict__ A0 = sel_cbuf(SEL_A0, A0_ext);
    const float* __restrict__ A1 = g_agg;
    float* __restrict__ C = sel_buf(SEL_C, C_ext);

    __shared__ uint32_t As[2][BM * SKA];   // [m][k]
    __shared__ uint32_t Bs[2][BK * SNB];   // [k][n]

    const int tid  = threadIdx.x;        // 0..255
    const int warp = tid >> 5;           // 0..7
    const int lane = tid & 31;
    const int gid  = lane >> 2;          // 0..7
    const int tig  = lane & 3;           // 0..3
    const int wm   = (warp & 3)  * 32;   // warp row offset (4 m-warps)
    const int wn   = (warp >> 2) * 64;   // warp col offset (2 n-warps)

    const int rowBase = blockIdx.x * BM;
    const int colBase = blockIdx.y * BN;

    // A loader: row = tid>>1 (0..127), cols (tid&1)*8 .. +7 (two float4)
    const int aRow = tid >> 1;
    const int aCol = (tid & 1) * 8;
    const bool aValid = (rowBase + aRow < NNODES);

    // B loader: rows {tid>>5, (tid>>5)+8}, 4 cols at 4*(tid&31)
    const int bR = tid >> 5;             // 0..7
    const int bC = (tid & 31) * 4;       // 0..124

    const int Kt = K / BK;     // tiles per pass
    const int T  = 2 * Kt;     // A0 pass then A1(g_agg) pass

    float acc[2][8][4];
#pragma unroll
    for (int mt = 0; mt < 2; ++mt)
#pragma unroll
        for (int nt = 0; nt < 8; ++nt)
#pragma unroll
            for (int q = 0; q < 4; ++q) acc[mt][nt][q] = 0.0f;

    float4 av[2];      // staged A: row aRow, cols aCol..aCol+3, aCol+4..aCol+7
    float4 bv[2];      // staged B: rows {bR, bR+8}, cols bC..bC+3

    // ---- stage tile 0 ----
    {
        const float* A = A0; const float* B = B0; const int k0 = 0;
#pragma unroll
        for (int q = 0; q < 2; ++q)
            av[q] = aValid
                ? *reinterpret_cast<const float4*>(A + (size_t)(rowBase + aRow) * K + k0 + aCol + 4 * q)
                : make_float4(0.f, 0.f, 0.f, 0.f);
#pragma unroll
        for (int q = 0; q < 2; ++q)
            bv[q] = *reinterpret_cast<const float4*>(B + (size_t)(k0 + bR + 8 * q) * NOUT + colBase + bC);
    }
    {
        uint32_t* as = As[0]; uint32_t* bs = Bs[0];
#pragma unroll
        for (int q = 0; q < 2; ++q) {
            uint4 s = make_uint4(f2tf32(av[q].x), f2tf32(av[q].y), f2tf32(av[q].z), f2tf32(av[q].w));
            *reinterpret_cast<uint4*>(&as[aRow * SKA + aCol + 4 * q]) = s;
        }
#pragma unroll
        for (int q = 0; q < 2; ++q) {
            uint4 s = make_uint4(f2tf32(bv[q].x), f2tf32(bv[q].y), f2tf32(bv[q].z), f2tf32(bv[q].w));
            *reinterpret_cast<uint4*>(&bs[(bR + 8 * q) * SNB + bC]) = s;
        }
    }
    __syncthreads();

#pragma unroll 1
    for (int t = 0; t < T; ++t) {
        const int cur = t & 1;

        // stage next tile (global -> regs), hidden under mma
        if (t + 1 < T) {
            const int tn = t + 1;
            const bool p2 = (tn >= Kt);
            const float* A = p2 ? A1 : A0;
            const float* B = p2 ? B1 : B0;
            const int k0 = (tn - (p2 ? Kt : 0)) * BK;
#pragma unroll
            for (int q = 0; q < 2; ++q)
                av[q] = aValid
                    ? *reinterpret_cast<const float4*>(A + (size_t)(rowBase + aRow) * K + k0 + aCol + 4 * q)
                    : make_float4(0.f, 0.f, 0.f, 0.f);
#pragma unroll
            for (int q = 0; q < 2; ++q)
                bv[q] = *reinterpret_cast<const float4*>(B + (size_t)(k0 + bR + 8 * q) * NOUT + colBase + bC);
        }

        // compute on current buffer: two k8 halves
        {
            const uint32_t* as = As[cur];
            const uint32_t* bs = Bs[cur];
#pragma unroll
            for (int kh = 0; kh < 2; ++kh) {
                const int ko = kh * 8;
                uint32_t a[2][4], b[8][2];
#pragma unroll
                for (int mt = 0; mt < 2; ++mt) {
                    const int mr = (wm + mt * 16 + gid) * SKA + ko + tig;
                    a[mt][0] = as[mr];
                    a[mt][1] = as[mr + 8 * SKA];
                    a[mt][2] = as[mr + 4];
                    a[mt][3] = as[mr + 8 * SKA + 4];
                }
#pragma unroll
                for (int nt = 0; nt < 8; ++nt) {
                    const int nr = (ko + tig) * SNB + wn + nt * 8 + gid;
                    b[nt][0] = bs[nr];
                    b[nt][1] = bs[nr + 4 * SNB];
                }
#pragma unroll
                for (int mt = 0; mt < 2; ++mt)
#pragma unroll
                    for (int nt = 0; nt < 8; ++nt)
                        mma_tf32(acc[mt][nt], a[mt], b[nt]);
            }
        }

        // store staged tile -> other buffer
        if (t + 1 < T) {
            const int nxt = cur ^ 1;
            uint32_t* as = As[nxt]; uint32_t* bs = Bs[nxt];
#pragma unroll
            for (int q = 0; q < 2; ++q) {
                uint4 s = make_uint4(f2tf32(av[q].x), f2tf32(av[q].y), f2tf32(av[q].z), f2tf32(av[q].w));
                *reinterpret_cast<uint4*>(&as[aRow * SKA + aCol + 4 * q]) = s;
            }
#pragma unroll
            for (int q = 0; q < 2; ++q) {
                uint4 s = make_uint4(f2tf32(bv[q].x), f2tf32(bv[q].y), f2tf32(bv[q].z), f2tf32(bv[q].w));
                *reinterpret_cast<uint4*>(&bs[(bR + 8 * q) * SNB + bC]) = s;
            }
            __syncthreads();
        }
    }

    // ---- epilogue: bias + optional relu + guarded float2 stores ----
    float2 bb[8];
#pragma unroll
    for (int nt = 0; nt < 8; ++nt)
        bb[nt] = *reinterpret_cast<const float2*>(&bias[colBase + wn + nt * 8 + 2 * tig]);

#pragma unroll
    for (int mt = 0; mt < 2; ++mt) {
        const int r0 = rowBase + wm + mt * 16 + gid;
        const int r1 = r0 + 8;
#pragma unroll
        for (int nt = 0; nt < 8; ++nt) {
            const int c = colBase + wn + nt * 8 + 2 * tig;
            float v0 = acc[mt][nt][0] + bb[nt].x;
            float v1 = acc[mt][nt][1] + bb[nt].y;
            float v2 = acc[mt][nt][2] + bb[nt].x;
            float v3 = acc[mt][nt][3] + bb[nt].y;
            if (do_relu) {
                v0 = fmaxf(v0, 0.f); v1 = fmaxf(v1, 0.f);
                v2 = fmaxf(v2, 0.f); v3 = fmaxf(v3, 0.f);
            }
            if (r0 < M_store)
                *reinterpret_cast<float2*>(&C[(size_t)r0 * NOUT + c]) = make_float2(v0, v1);
            if (r1 < M_store)
                *reinterpret_cast<float2*>(&C[(size_t)r1 * NOUT + c]) = make_float2(v2, v3);
        }
    }
}

// ---------------- launcher ----------------
extern "C" void kernel_launch(void* const* d_in, const int* in_sizes, int n_in,
                              void* d_out, int out_size)
{
    const float* x    = (const float*)d_in[0];
    const int*   ei   = (const int*)d_in[1];     // int32 (JAX x64 disabled)
    const float* W1_0 = (const float*)d_in[2];
    const float* W1_1 = (const float*)d_in[3];
    const float* b1   = (const float*)d_in[4];
    const float* W2_0 = (const float*)d_in[5];
    const float* W2_1 = (const float*)d_in[6];
    const float* b2   = (const float*)d_in[7];
    const float* W3_0 = (const float*)d_in[8];
    const float* W3_1 = (const float*)d_in[9];
    const float* b3   = (const float*)d_in[10];
    float*       out  = (float*)d_out;

    const int TB = 256;
    k_init <<<(NNODES + TB - 1) / TB, TB>>>();
    k_deg  <<<(NEDGES + TB - 1) / TB, TB>>>(ei);
    k_dinv <<<(NNODES + TB - 1) / TB, TB>>>();
    k_scan1<<<SCAN_BLOCKS, 1024>>>();
    k_scan2<<<SCAN_BLOCKS, 1024>>>();
    k_fill <<<(NEDGES + TB - 1) / TB, TB>>>(ei);

    dim3 ggrid(MP / BM, NOUT / BN);   // 391 x 2

    // layer 1 (K = 128)
    k_spmm<128, SEL_EXT><<<NNODES, 64>>>(x);
    k_gemm<SEL_EXT, SEL_H1><<<ggrid, 256>>>(x, W1_0, W1_1, b1, nullptr, 128, MP, 1);

    // layer 2 (K = 256)
    k_spmm<256, SEL_H1><<<NNODES, 128>>>(nullptr);
    k_gemm<SEL_H1, SEL_H2><<<ggrid, 256>>>(nullptr, W2_0, W2_1, b2, nullptr, 256, MP, 1);

    // layer 3 (K = 256), no relu, store only real rows into d_out
    k_spmm<256, SEL_H2><<<NNODES, 128>>>(nullptr);
    k_gemm<SEL_H2, SEL_EXT><<<ggrid, 256>>>(nullptr, W3_0, W3_1, b3, out, 256, NNODES, 0);
}

// round 9
// speedup vs baseline: 2.6321x; 1.0966x over previous
#include <cuda_runtime.h>
#include <cuda_fp16.h>
#include <cstdint>

#define NNODES 50000
#define NEDGES 400000
#define MP     50048
#define NOUT   256
#define SCAN_BLOCKS 49    // 49*1024 >= NNODES

// ---------------- static device scratch (no allocations allowed) ----------------
__device__ int   g_deg[NNODES];
__device__ int   g_cnt[NNODES];
__device__ int   g_fill[NNODES];
__device__ float g_dinv[NNODES];
__device__ int   g_rowptr[NNODES + 1];
__device__ int   g_bsum[SCAN_BLOCKS];
__device__ int   g_col[NEDGES];
__device__ float g_wval[NEDGES];
__device__ float g_agg[(size_t)MP * 256];
__device__ float g_h1 [(size_t)MP * 256];
__device__ float g_h2 [(size_t)MP * 256];
// transposed weights: Wt[n][k]; layout: [m0:256x128][m1:256x128][m2..m5:256x256]
__device__ float g_wt[256 * 128 * 2 + 256 * 256 * 4];

#define WT_OFF_10 0
#define WT_OFF_11 (256 * 128)
#define WT_OFF_20 (256 * 128 * 2)
#define WT_OFF_21 (WT_OFF_20 + 256 * 256)
#define WT_OFF_30 (WT_OFF_21 + 256 * 256)
#define WT_OFF_31 (WT_OFF_30 + 256 * 256)

#define SEL_EXT 0
#define SEL_H1  1
#define SEL_H2  2

__device__ __forceinline__ const float* sel_cbuf(int SEL, const float* ext) {
    switch (SEL) {
        case SEL_H1: return g_h1;
        case SEL_H2: return g_h2;
        default:     return ext;
    }
}
__device__ __forceinline__ float* sel_buf(int SEL, float* ext) {
    switch (SEL) {
        case SEL_H1: return g_h1;
        case SEL_H2: return g_h2;
        default:     return ext;
    }
}

// ---------------- fp16 helpers ----------------
__device__ __forceinline__ uint32_t pack_h2(float lo, float hi) {
    __half2 h = __floats2half2_rn(lo, hi);   // lo -> bits 15:0
    return *reinterpret_cast<uint32_t*>(&h);
}
// mma.sync m16n8k16 fp16 inputs, fp32 accum
__device__ __forceinline__ void mma_f16(float* c, const uint32_t* a, const uint32_t* b) {
    asm volatile(
        "mma.sync.aligned.m16n8k16.row.col.f32.f16.f16.f32 "
        "{%0,%1,%2,%3}, {%4,%5,%6,%7}, {%8,%9}, {%0,%1,%2,%3};"
        : "+f"(c[0]), "+f"(c[1]), "+f"(c[2]), "+f"(c[3])
        : "r"(a[0]), "r"(a[1]), "r"(a[2]), "r"(a[3]), "r"(b[0]), "r"(b[1]));
}

// ---------------- graph setup kernels ----------------
__global__ void k_init() {
    int i = blockIdx.x * blockDim.x + threadIdx.x;
    if (i < NNODES) { g_deg[i] = 0; g_cnt[i] = 0; g_fill[i] = 0; }
}

// edge_index is int32 (JAX default config disables x64)
__global__ void k_deg(const int* __restrict__ ei) {
    int e = blockIdx.x * blockDim.x + threadIdx.x;
    if (e < NEDGES) {
        int s = ei[e];
        int d = ei[NEDGES + e];
        if (s != d && (unsigned)s < NNODES && (unsigned)d < NNODES) {
            atomicAdd(&g_deg[s], 1);
            atomicAdd(&g_cnt[d], 1);
        }
    }
}

__global__ void k_dinv() {
    int i = blockIdx.x * blockDim.x + threadIdx.x;
    if (i < NNODES) {
        int dg = g_deg[i];
        g_dinv[i] = (dg > 0) ? rsqrtf((float)dg) : 0.0f;
    }
}

__global__ void k_scan1() {
    __shared__ int sh[1024];
    const int t = threadIdx.x;
    const int i = blockIdx.x * 1024 + t;
    int v = (i < NNODES) ? g_cnt[i] : 0;
    sh[t] = v;
    __syncthreads();
    for (int off = 1; off < 1024; off <<= 1) {
        int u = (t >= off) ? sh[t - off] : 0;
        __syncthreads();
        sh[t] += u;
        __syncthreads();
    }
    if (i < NNODES) g_rowptr[i] = sh[t] - v;
    if (t == 1023) g_bsum[blockIdx.x] = sh[1023];
}

__global__ void k_scan2() {
    __shared__ int sh[SCAN_BLOCKS];
    const int t = threadIdx.x;
    if (t < SCAN_BLOCKS) sh[t] = g_bsum[t];
    __syncthreads();
    int offset = 0, total = 0;
    for (int b = 0; b < SCAN_BLOCKS; ++b) {
        if (b < (int)blockIdx.x) offset += sh[b];
        total += sh[b];
    }
    const int i = blockIdx.x * 1024 + t;
    if (i < NNODES) g_rowptr[i] += offset;
    if (blockIdx.x == SCAN_BLOCKS - 1 && t == 0) g_rowptr[NNODES] = total;
}

__global__ void k_fill(const int* __restrict__ ei) {
    int e = blockIdx.x * blockDim.x + threadIdx.x;
    if (e < NEDGES) {
        int s = ei[e];
        int d = ei[NEDGES + e];
        if (s != d && (unsigned)s < NNODES && (unsigned)d < NNODES) {
            int pos = atomicAdd(&g_fill[d], 1);
            int idx = g_rowptr[d] + pos;
            g_col[idx]  = s;
            g_wval[idx] = -g_dinv[s] * g_dinv[d];
        }
    }
}

// ---------------- weight transpose: g_wt[n][k] = W[k][n] ----------------
__global__ void k_transpose(const float* __restrict__ w10, const float* __restrict__ w11,
                            const float* __restrict__ w20, const float* __restrict__ w21,
                            const float* __restrict__ w30, const float* __restrict__ w31)
{
    __shared__ float sh[32][33];
    const int m = blockIdx.z;
    const float* W; int K, off;
    switch (m) {
        case 0: W = w10; K = 128; off = WT_OFF_10; break;
        case 1: W = w11; K = 128; off = WT_OFF_11; break;
        case 2: W = w20; K = 256; off = WT_OFF_20; break;
        case 3: W = w21; K = 256; off = WT_OFF_21; break;
        case 4: W = w30; K = 256; off = WT_OFF_30; break;
        default: W = w31; K = 256; off = WT_OFF_31; break;
    }
    const int kb = blockIdx.y * 32;
    if (kb >= K) return;
    const int nb = blockIdx.x * 32;
    const int tx = threadIdx.x, ty0 = threadIdx.y;   // block (32, 8)
    for (int ty = ty0; ty < 32; ty += 8)
        sh[ty][tx] = W[(size_t)(kb + ty) * NOUT + nb + tx];
    __syncthreads();
    for (int ty = ty0; ty < 32; ty += 8)
        g_wt[(size_t)off + (size_t)(nb + ty) * K + kb + tx] = sh[tx][ty];
}

// ---------------- SpMM: g_agg[row,:] = sum_j w_j * in[col_j,:] ----------------
template <int F, int SEL_IN>
__global__ void k_spmm(const float* __restrict__ in_ext) {
    const float2* __restrict__ in =
        reinterpret_cast<const float2*>(sel_cbuf(SEL_IN, in_ext));
    const int row = blockIdx.x;
    const int f2  = threadIdx.x;
    const int W2  = F / 2;
    const int beg = g_rowptr[row];
    const int end = g_rowptr[row + 1];
    float ax0 = 0.f, ay0 = 0.f, ax1 = 0.f, ay1 = 0.f;
    float ax2 = 0.f, ay2 = 0.f, ax3 = 0.f, ay3 = 0.f;
    int j = beg;
    for (; j + 3 < end; j += 4) {
        float w0 = g_wval[j];     int c0 = g_col[j];
        float w1 = g_wval[j + 1]; int c1 = g_col[j + 1];
        float w2 = g_wval[j + 2]; int c2 = g_col[j + 2];
        float w3 = g_wval[j + 3]; int c3 = g_col[j + 3];
        float2 v0 = __ldg(&in[(size_t)c0 * W2 + f2]);
        float2 v1 = __ldg(&in[(size_t)c1 * W2 + f2]);
        float2 v2 = __ldg(&in[(size_t)c2 * W2 + f2]);
        float2 v3 = __ldg(&in[(size_t)c3 * W2 + f2]);
        ax0 += w0 * v0.x; ay0 += w0 * v0.y;
        ax1 += w1 * v1.x; ay1 += w1 * v1.y;
        ax2 += w2 * v2.x; ay2 += w2 * v2.y;
        ax3 += w3 * v3.x; ay3 += w3 * v3.y;
    }
    for (; j < end; ++j) {
        float w = g_wval[j]; int c = g_col[j];
        float2 v = __ldg(&in[(size_t)c * W2 + f2]);
        ax0 += w * v.x; ay0 += w * v.y;
    }
    float2 r;
    r.x = (ax0 + ax1) + (ax2 + ax3);
    r.y = (ay0 + ay1) + (ay2 + ay3);
    reinterpret_cast<float2*>(g_agg)[(size_t)row * W2 + f2] = r;
}

// ---------------- fp16 HMMA fused dual-GEMM ----------------
// C = A0@W0t^T + g_agg@W1t^T + bias (opt relu), via mma.sync m16n8k16 fp16.
// Block 128x128, 256 threads (8 warps, 4 m x 2 n), warp tile 32x64, BK=16.
// Both operands staged as [row][k-pair] fp16x2 words, stride 12 (conflict-free).
#define BM 128
#define BN 128
#define BK 16
#define SW 12   // smem word-stride per row (8 data words + 4 pad)

template <int SEL_A0, int SEL_C>
__global__ void __launch_bounds__(256, 2) k_gemm(
    const float* __restrict__ A0_ext,
    int wtOff0, int wtOff1,
    const float* __restrict__ bias, float* __restrict__ C_ext,
    int K, int M_store, int do_relu)
{
    const float* __restrict__ A0 = sel_cbuf(SEL_A0, A0_ext);
    const float* __restrict__ A1 = g_agg;
    const float* __restrict__ W0 = g_wt + wtOff0;
    const float* __restrict__ W1 = g_wt + wtOff1;
    float* __restrict__ C = sel_buf(SEL_C, C_ext);

    __shared__ uint32_t As[2][BM * SW];   // [m][k-pair]
    __shared__ uint32_t Bs[2][BN * SW];   // [n][k-pair]

    const int tid  = threadIdx.x;        // 0..255
    const int warp = tid >> 5;           // 0..7
    const int lane = tid & 31;
    const int gid  = lane >> 2;          // 0..7
    const int tig  = lane & 3;           // 0..3
    const int wm   = (warp & 3)  * 32;   // warp row offset (4 m-warps)
    const int wn   = (warp >> 2) * 64;   // warp col offset (2 n-warps)

    const int rowBase = blockIdx.x * BM;
    const int colBase = blockIdx.y * BN;

    // stager: row = tid>>1 (0..127), k-half = (tid&1)*8 floats
    const int sRow  = tid >> 1;
    const int sKoff = (tid & 1) * 8;
    const bool aValid = (rowBase + sRow < NNODES);
    const float* __restrict__ Arow0 = A0 + (size_t)(rowBase + sRow) * K;
    const float* __restrict__ Arow1 = A1 + (size_t)(rowBase + sRow) * K;
    const float* __restrict__ Brow0 = W0 + (size_t)(colBase + sRow) * K;
    const float* __restrict__ Brow1 = W1 + (size_t)(colBase + sRow) * K;

    const int Kt = K / BK;     // tiles per pass
    const int T  = 2 * Kt;     // A0 pass then A1(g_agg) pass

    float acc[2][8][4];
#pragma unroll
    for (int mt = 0; mt < 2; ++mt)
#pragma unroll
        for (int nt = 0; nt < 8; ++nt)
#pragma unroll
            for (int q = 0; q < 4; ++q) acc[mt][nt][q] = 0.0f;

    float4 av[2], bv[2];   // staged 8 floats of A, 8 floats of B

    // ---- stage tile 0 ----
    {
        const int k0 = 0;
        av[0] = aValid ? *reinterpret_cast<const float4*>(Arow0 + k0 + sKoff)
                       : make_float4(0.f, 0.f, 0.f, 0.f);
        av[1] = aValid ? *reinterpret_cast<const float4*>(Arow0 + k0 + sKoff + 4)
                       : make_float4(0.f, 0.f, 0.f, 0.f);
        bv[0] = *reinterpret_cast<const float4*>(Brow0 + k0 + sKoff);
        bv[1] = *reinterpret_cast<const float4*>(Brow0 + k0 + sKoff + 4);
    }
    {
        uint4 sa = make_uint4(pack_h2(av[0].x, av[0].y), pack_h2(av[0].z, av[0].w),
                              pack_h2(av[1].x, av[1].y), pack_h2(av[1].z, av[1].w));
        uint4 sb = make_uint4(pack_h2(bv[0].x, bv[0].y), pack_h2(bv[0].z, bv[0].w),
                              pack_h2(bv[1].x, bv[1].y), pack_h2(bv[1].z, bv[1].w));
        *reinterpret_cast<uint4*>(&As[0][sRow * SW + (tid & 1) * 4]) = sa;
        *reinterpret_cast<uint4*>(&Bs[0][sRow * SW + (tid & 1) * 4]) = sb;
    }
    __syncthreads();

#pragma unroll 1
    for (int t = 0; t < T; ++t) {
        const int cur = t & 1;

        // prefetch next tile (global -> regs), hidden under mma
        if (t + 1 < T) {
            const int tn = t + 1;
            const bool p2 = (tn >= Kt);
            const float* __restrict__ Ar = p2 ? Arow1 : Arow0;
            const float* __restrict__ Br = p2 ? Brow1 : Brow0;
            const int k0 = (tn - (p2 ? Kt : 0)) * BK;
            av[0] = aValid ? *reinterpret_cast<const float4*>(Ar + k0 + sKoff)
                           : make_float4(0.f, 0.f, 0.f, 0.f);
            av[1] = aValid ? *reinterpret_cast<const float4*>(Ar + k0 + sKoff + 4)
                           : make_float4(0.f, 0.f, 0.f, 0.f);
            bv[0] = *reinterpret_cast<const float4*>(Br + k0 + sKoff);
            bv[1] = *reinterpret_cast<const float4*>(Br + k0 + sKoff + 4);
        }

        // compute on current buffer: one k16 step
        {
            const uint32_t* as = As[cur];
            const uint32_t* bs = Bs[cur];
            uint32_t a[2][4], b[8][2];
#pragma unroll
            for (int mt = 0; mt < 2; ++mt) {
                const int m0 = (wm + mt * 16 + gid) * SW;
                a[mt][0] = as[m0 + tig];
                a[mt][1] = as[m0 + 8 * SW + tig];
                a[mt][2] = as[m0 + tig + 4];
                a[mt][3] = as[m0 + 8 * SW + tig + 4];
            }
#pragma unroll
            for (int nt = 0; nt < 8; ++nt) {
                const int n0 = (wn + nt * 8 + gid) * SW;
                b[nt][0] = bs[n0 + tig];
                b[nt][1] = bs[n0 + tig + 4];
            }
#pragma unroll
            for (int mt = 0; mt < 2; ++mt)
#pragma unroll
                for (int nt = 0; nt < 8; ++nt)
                    mma_f16(acc[mt][nt], a[mt], b[nt]);
        }

        // store staged tile -> other buffer
        if (t + 1 < T) {
            const int nxt = cur ^ 1;
            uint4 sa = make_uint4(pack_h2(av[0].x, av[0].y), pack_h2(av[0].z, av[0].w),
                                  pack_h2(av[1].x, av[1].y), pack_h2(av[1].z, av[1].w));
            uint4 sb = make_uint4(pack_h2(bv[0].x, bv[0].y), pack_h2(bv[0].z, bv[0].w),
                                  pack_h2(bv[1].x, bv[1].y), pack_h2(bv[1].z, bv[1].w));
            *reinterpret_cast<uint4*>(&As[nxt][sRow * SW + (tid & 1) * 4]) = sa;
            *reinterpret_cast<uint4*>(&Bs[nxt][sRow * SW + (tid & 1) * 4]) = sb;
            __syncthreads();
        }
    }

    // ---- epilogue: bias + optional relu + guarded float2 stores ----
    float2 bb[8];
#pragma unroll
    for (int nt = 0; nt < 8; ++nt)
        bb[nt] = *reinterpret_cast<const float2*>(&bias[colBase + wn + nt * 8 + 2 * tig]);

#pragma unroll
    for (int mt = 0; mt < 2; ++mt) {
        const int r0 = rowBase + wm + mt * 16 + gid;
        const int r1 = r0 + 8;
#pragma unroll
        for (int nt = 0; nt < 8; ++nt) {
            const int c = colBase + wn + nt * 8 + 2 * tig;
            float v0 = acc[mt][nt][0] + bb[nt].x;
            float v1 = acc[mt][nt][1] + bb[nt].y;
            float v2 = acc[mt][nt][2] + bb[nt].x;
            float v3 = acc[mt][nt][3] + bb[nt].y;
            if (do_relu) {
                v0 = fmaxf(v0, 0.f); v1 = fmaxf(v1, 0.f);
                v2 = fmaxf(v2, 0.f); v3 = fmaxf(v3, 0.f);
            }
            if (r0 < M_store)
                *reinterpret_cast<float2*>(&C[(size_t)r0 * NOUT + c]) = make_float2(v0, v1);
            if (r1 < M_store)
                *reinterpret_cast<float2*>(&C[(size_t)r1 * NOUT + c]) = make_float2(v2, v3);
        }
    }
}

// ---------------- launcher ----------------
extern "C" void kernel_launch(void* const* d_in, const int* in_sizes, int n_in,
                              void* d_out, int out_size)
{
    const float* x    = (const float*)d_in[0];
    const int*   ei   = (const int*)d_in[1];     // int32 (JAX x64 disabled)
    const float* W1_0 = (const float*)d_in[2];
    const float* W1_1 = (const float*)d_in[3];
    const float* b1   = (const float*)d_in[4];
    const float* W2_0 = (const float*)d_in[5];
    const float* W2_1 = (const float*)d_in[6];
    const float* b2   = (const float*)d_in[7];
    const float* W3_0 = (const float*)d_in[8];
    const float* W3_1 = (const float*)d_in[9];
    const float* b3   = (const float*)d_in[10];
    float*       out  = (float*)d_out;

    const int TB = 256;
    k_init <<<(NNODES + TB - 1) / TB, TB>>>();
    k_deg  <<<(NEDGES + TB - 1) / TB, TB>>>(ei);
    k_dinv <<<(NNODES + TB - 1) / TB, TB>>>();
    k_scan1<<<SCAN_BLOCKS, 1024>>>();
    k_scan2<<<SCAN_BLOCKS, 1024>>>();
    k_fill <<<(NEDGES + TB - 1) / TB, TB>>>(ei);
    k_transpose<<<dim3(8, 8, 6), dim3(32, 8)>>>(W1_0, W1_1, W2_0, W2_1, W3_0, W3_1);

    dim3 ggrid(MP / BM, NOUT / BN);   // 391 x 2

    // layer 1 (K = 128)
    k_spmm<128, SEL_EXT><<<NNODES, 64>>>(x);
    k_gemm<SEL_EXT, SEL_H1><<<ggrid, 256>>>(x, WT_OFF_10, WT_OFF_11, b1, nullptr, 128, MP, 1);

    // layer 2 (K = 256)
    k_spmm<256, SEL_H1><<<NNODES, 128>>>(nullptr);
    k_gemm<SEL_H1, SEL_H2><<<ggrid, 256>>>(nullptr, WT_OFF_20, WT_OFF_21, b2, nullptr, 256, MP, 1);

    // layer 3 (K = 256), no relu, store only real rows into d_out
    k_spmm<256, SEL_H2><<<NNODES, 128>>>(nullptr);
    k_gemm<SEL_H2, SEL_EXT><<<ggrid, 256>>>(nullptr, WT_OFF_30, WT_OFF_31, b3, out, 256, NNODES, 0);
}

// round 10
// speedup vs baseline: 3.0320x; 1.1519x over previous
#include <cuda_runtime.h>
#include <cuda_fp16.h>
#include <cstdint>

#define NNODES 50000
#define NEDGES 400000
#define MP     50048
#define NOUT   256
#define SCAN_BLOCKS 49    // 49*1024 >= NNODES

// ---------------- static device scratch (no allocations allowed) ----------------
__device__ int   g_deg[NNODES];
__device__ int   g_cnt[NNODES];
__device__ int   g_fill[NNODES];
__device__ float g_dinv[NNODES];
__device__ int   g_rowptr[NNODES + 1];
__device__ int   g_bsum[SCAN_BLOCKS];
__device__ int   g_col[NEDGES];
__device__ float g_wval[NEDGES];
__device__ float g_agg[(size_t)MP * 256];
__device__ float g_h1 [(size_t)MP * 256];
__device__ float g_h2 [(size_t)MP * 256];
// transposed weights: Wt[n][k]; layout: [m0:256x128][m1:256x128][m2..m5:256x256]
__device__ float g_wt[256 * 128 * 2 + 256 * 256 * 4];

#define WT_OFF_10 0
#define WT_OFF_11 (256 * 128)
#define WT_OFF_20 (256 * 128 * 2)
#define WT_OFF_21 (WT_OFF_20 + 256 * 256)
#define WT_OFF_30 (WT_OFF_21 + 256 * 256)
#define WT_OFF_31 (WT_OFF_30 + 256 * 256)

#define SEL_EXT 0
#define SEL_H1  1
#define SEL_H2  2

__device__ __forceinline__ const float* sel_cbuf(int SEL, const float* ext) {
    switch (SEL) {
        case SEL_H1: return g_h1;
        case SEL_H2: return g_h2;
        default:     return ext;
    }
}
__device__ __forceinline__ float* sel_buf(int SEL, float* ext) {
    switch (SEL) {
        case SEL_H1: return g_h1;
        case SEL_H2: return g_h2;
        default:     return ext;
    }
}

// ---------------- fp16 / mma / ldmatrix helpers ----------------
__device__ __forceinline__ uint32_t pack_h2(float lo, float hi) {
    __half2 h = __floats2half2_rn(lo, hi);   // lo -> bits 15:0
    return *reinterpret_cast<uint32_t*>(&h);
}
__device__ __forceinline__ void mma_f16(float* c, const uint32_t* a, const uint32_t* b) {
    asm volatile(
        "mma.sync.aligned.m16n8k16.row.col.f32.f16.f16.f32 "
        "{%0,%1,%2,%3}, {%4,%5,%6,%7}, {%8,%9}, {%0,%1,%2,%3};"
        : "+f"(c[0]), "+f"(c[1]), "+f"(c[2]), "+f"(c[3])
        : "r"(a[0]), "r"(a[1]), "r"(a[2]), "r"(a[3]), "r"(b[0]), "r"(b[1]));
}
__device__ __forceinline__ void ldsm_x4(uint32_t& r0, uint32_t& r1, uint32_t& r2,
                                        uint32_t& r3, uint32_t addr) {
    asm volatile("ldmatrix.sync.aligned.m8n8.x4.shared.b16 {%0,%1,%2,%3}, [%4];"
                 : "=r"(r0), "=r"(r1), "=r"(r2), "=r"(r3) : "r"(addr));
}
__device__ __forceinline__ uint32_t smem_u32(const void* p) {
    uint32_t a;
    asm("{ .reg .u64 t; cvta.to.shared.u64 t, %1; cvt.u32.u64 %0, t; }" : "=r"(a) : "l"(p));
    return a;
}

// ---------------- graph setup kernels ----------------
__global__ void k_init() {
    int i = blockIdx.x * blockDim.x + threadIdx.x;
    if (i < NNODES) { g_deg[i] = 0; g_cnt[i] = 0; g_fill[i] = 0; }
}

// edge_index is int32 (JAX default config disables x64)
__global__ void k_deg(const int* __restrict__ ei) {
    int e = blockIdx.x * blockDim.x + threadIdx.x;
    if (e < NEDGES) {
        int s = ei[e];
        int d = ei[NEDGES + e];
        if (s != d && (unsigned)s < NNODES && (unsigned)d < NNODES) {
            atomicAdd(&g_deg[s], 1);
            atomicAdd(&g_cnt[d], 1);
        }
    }
}

__global__ void k_dinv() {
    int i = blockIdx.x * blockDim.x + threadIdx.x;
    if (i < NNODES) {
        int dg = g_deg[i];
        g_dinv[i] = (dg > 0) ? rsqrtf((float)dg) : 0.0f;
    }
}

__global__ void k_scan1() {
    __shared__ int sh[1024];
    const int t = threadIdx.x;
    const int i = blockIdx.x * 1024 + t;
    int v = (i < NNODES) ? g_cnt[i] : 0;
    sh[t] = v;
    __syncthreads();
    for (int off = 1; off < 1024; off <<= 1) {
        int u = (t >= off) ? sh[t - off] : 0;
        __syncthreads();
        sh[t] += u;
        __syncthreads();
    }
    if (i < NNODES) g_rowptr[i] = sh[t] - v;
    if (t == 1023) g_bsum[blockIdx.x] = sh[1023];
}

__global__ void k_scan2() {
    __shared__ int sh[SCAN_BLOCKS];
    const int t = threadIdx.x;
    if (t < SCAN_BLOCKS) sh[t] = g_bsum[t];
    __syncthreads();
    int offset = 0, total = 0;
    for (int b = 0; b < SCAN_BLOCKS; ++b) {
        if (b < (int)blockIdx.x) offset += sh[b];
        total += sh[b];
    }
    const int i = blockIdx.x * 1024 + t;
    if (i < NNODES) g_rowptr[i] += offset;
    if (blockIdx.x == SCAN_BLOCKS - 1 && t == 0) g_rowptr[NNODES] = total;
}

__global__ void k_fill(const int* __restrict__ ei) {
    int e = blockIdx.x * blockDim.x + threadIdx.x;
    if (e < NEDGES) {
        int s = ei[e];
        int d = ei[NEDGES + e];
        if (s != d && (unsigned)s < NNODES && (unsigned)d < NNODES) {
            int pos = atomicAdd(&g_fill[d], 1);
            int idx = g_rowptr[d] + pos;
            g_col[idx]  = s;
            g_wval[idx] = -g_dinv[s] * g_dinv[d];
        }
    }
}

// ---------------- weight transpose: g_wt[n][k] = W[k][n] ----------------
__global__ void k_transpose(const float* __restrict__ w10, const float* __restrict__ w11,
                            const float* __restrict__ w20, const float* __restrict__ w21,
                            const float* __restrict__ w30, const float* __restrict__ w31)
{
    __shared__ float sh[32][33];
    const int m = blockIdx.z;
    const float* W; int K, off;
    switch (m) {
        case 0: W = w10; K = 128; off = WT_OFF_10; break;
        case 1: W = w11; K = 128; off = WT_OFF_11; break;
        case 2: W = w20; K = 256; off = WT_OFF_20; break;
        case 3: W = w21; K = 256; off = WT_OFF_21; break;
        case 4: W = w30; K = 256; off = WT_OFF_30; break;
        default: W = w31; K = 256; off = WT_OFF_31; break;
    }
    const int kb = blockIdx.y * 32;
    if (kb >= K) return;
    const int nb = blockIdx.x * 32;
    const int tx = threadIdx.x, ty0 = threadIdx.y;   // block (32, 8)
    for (int ty = ty0; ty < 32; ty += 8)
        sh[ty][tx] = W[(size_t)(kb + ty) * NOUT + nb + tx];
    __syncthreads();
    for (int ty = ty0; ty < 32; ty += 8)
        g_wt[(size_t)off + (size_t)(nb + ty) * K + kb + tx] = sh[tx][ty];
}

// ---------------- SpMM: g_agg[row,:] = sum_j w_j * in[col_j,:] (float4 lanes) ----
template <int F, int SEL_IN>
__global__ void k_spmm(const float* __restrict__ in_ext) {
    const float4* __restrict__ in =
        reinterpret_cast<const float4*>(sel_cbuf(SEL_IN, in_ext));
    const int row = blockIdx.x;
    const int f4  = threadIdx.x;              // F/4 threads
    const int W4  = F / 4;
    const int beg = g_rowptr[row];
    const int end = g_rowptr[row + 1];
    float4 a0 = make_float4(0.f, 0.f, 0.f, 0.f);
    float4 a1 = make_float4(0.f, 0.f, 0.f, 0.f);
    float4 a2 = make_float4(0.f, 0.f, 0.f, 0.f);
    float4 a3 = make_float4(0.f, 0.f, 0.f, 0.f);
    int j = beg;
    for (; j + 3 < end; j += 4) {
        float w0 = g_wval[j];     int c0 = g_col[j];
        float w1 = g_wval[j + 1]; int c1 = g_col[j + 1];
        float w2 = g_wval[j + 2]; int c2 = g_col[j + 2];
        float w3 = g_wval[j + 3]; int c3 = g_col[j + 3];
        float4 v0 = __ldg(&in[(size_t)c0 * W4 + f4]);
        float4 v1 = __ldg(&in[(size_t)c1 * W4 + f4]);
        float4 v2 = __ldg(&in[(size_t)c2 * W4 + f4]);
        float4 v3 = __ldg(&in[(size_t)c3 * W4 + f4]);
        a0.x += w0 * v0.x; a0.y += w0 * v0.y; a0.z += w0 * v0.z; a0.w += w0 * v0.w;
        a1.x += w1 * v1.x; a1.y += w1 * v1.y; a1.z += w1 * v1.z; a1.w += w1 * v1.w;
        a2.x += w2 * v2.x; a2.y += w2 * v2.y; a2.z += w2 * v2.z; a2.w += w2 * v2.w;
        a3.x += w3 * v3.x; a3.y += w3 * v3.y; a3.z += w3 * v3.z; a3.w += w3 * v3.w;
    }
    for (; j < end; ++j) {
        float w = g_wval[j]; int c = g_col[j];
        float4 v = __ldg(&in[(size_t)c * W4 + f4]);
        a0.x += w * v.x; a0.y += w * v.y; a0.z += w * v.z; a0.w += w * v.w;
    }
    float4 r;
    r.x = (a0.x + a1.x) + (a2.x + a3.x);
    r.y = (a0.y + a1.y) + (a2.y + a3.y);
    r.z = (a0.z + a1.z) + (a2.z + a3.z);
    r.w = (a0.w + a1.w) + (a2.w + a3.w);
    reinterpret_cast<float4*>(g_agg)[(size_t)row * W4 + f4] = r;
}

// ---------------- fp16 HMMA fused dual-GEMM (ldmatrix, BK=32) ----------------
// C = A0@W0t^T + g_agg@W1t^T + bias (opt relu), via mma.sync m16n8k16 fp16.
// Block 128x128, 256 threads (8 warps, 4 m x 2 n), warp tile 32x64, BK=32.
// Operands staged as [row][k-pair] fp16x2 words, stride 20 (16 data + 4 pad).
#define BM 128
#define BN 128
#define BK 32
#define SW 20   // smem word-stride per row

template <int SEL_A0, int SEL_C>
__global__ void __launch_bounds__(256, 2) k_gemm(
    const float* __restrict__ A0_ext,
    int wtOff0, int wtOff1,
    const float* __restrict__ bias, float* __restrict__ C_ext,
    int K, int M_store, int do_relu)
{
    const float* __restrict__ A0 = sel_cbuf(SEL_A0, A0_ext);
    const float* __restrict__ A1 = g_agg;
    const float* __restrict__ W0 = g_wt + wtOff0;
    const float* __restrict__ W1 = g_wt + wtOff1;
    float* __restrict__ C = sel_buf(SEL_C, C_ext);

    __shared__ uint32_t As[2][BM * SW];   // [m][k-pair]
    __shared__ uint32_t Bs[2][BN * SW];   // [n][k-pair]

    const int tid  = threadIdx.x;        // 0..255
    const int warp = tid >> 5;           // 0..7
    const int lane = tid & 31;
    const int gid  = lane >> 2;          // 0..7
    const int tig  = lane & 3;           // 0..3
    const int wm   = (warp & 3)  * 32;   // warp row offset (4 m-warps)
    const int wn   = (warp >> 2) * 64;   // warp col offset (2 n-warps)

    const int rowBase = blockIdx.x * BM;
    const int colBase = blockIdx.y * BN;

    // stager: row = tid>>1 (0..127), k-half = (tid&1)*16 floats
    const int sRow  = tid >> 1;
    const int sKoff = (tid & 1) * 16;
    const bool aValid = (rowBase + sRow < NNODES);
    const float* __restrict__ Arow0 = A0 + (size_t)(rowBase + sRow) * K;
    const float* __restrict__ Arow1 = A1 + (size_t)(rowBase + sRow) * K;
    const float* __restrict__ Brow0 = W0 + (size_t)(colBase + sRow) * K;
    const float* __restrict__ Brow1 = W1 + (size_t)(colBase + sRow) * K;
    const int sDst = sRow * SW + (tid & 1) * 8;   // word offset of this thread's 8 words

    // ldmatrix lane addressing (per warp, per buffer)
    // A (mt): matrices (r0-7,k0-7)(r8-15,k0-7)(r0-7,k8-15)(r8-15,k8-15)
    const int aLRow = wm + (lane & 7) + ((lane >> 3) & 1) * 8;   // + mt*16
    const int aLKw  = (lane >> 4) * 4;                            // + ko words
    // B (ntp): matrices (n0-7,k0-7)(n0-7,k8-15)(n8-15,k0-7)(n8-15,k8-15)
    const int bLRow = wn + (lane & 7) + (lane >> 4) * 8;          // + ntp*16
    const int bLKw  = ((lane >> 3) & 1) * 4;                      // + ko words

    const uint32_t asB0 = smem_u32(&As[0][0]);
    const uint32_t asB1 = smem_u32(&As[1][0]);
    const uint32_t bsB0 = smem_u32(&Bs[0][0]);
    const uint32_t bsB1 = smem_u32(&Bs[1][0]);

    const int Kt = K / BK;     // tiles per pass
    const int T  = 2 * Kt;     // A0 pass then A1(g_agg) pass

    float acc[2][8][4];
#pragma unroll
    for (int mt = 0; mt < 2; ++mt)
#pragma unroll
        for (int nt = 0; nt < 8; ++nt)
#pragma unroll
            for (int q = 0; q < 4; ++q) acc[mt][nt][q] = 0.0f;

    float4 av[4], bv[4];   // staged 16 floats of A, 16 floats of B

    // ---- stage tile 0 ----
#pragma unroll
    for (int q = 0; q < 4; ++q) {
        av[q] = aValid ? *reinterpret_cast<const float4*>(Arow0 + sKoff + 4 * q)
                       : make_float4(0.f, 0.f, 0.f, 0.f);
        bv[q] = *reinterpret_cast<const float4*>(Brow0 + sKoff + 4 * q);
    }
#pragma unroll
    for (int h = 0; h < 2; ++h) {
        uint4 sa = make_uint4(pack_h2(av[2*h].x, av[2*h].y),   pack_h2(av[2*h].z, av[2*h].w),
                              pack_h2(av[2*h+1].x, av[2*h+1].y), pack_h2(av[2*h+1].z, av[2*h+1].w));
        uint4 sb = make_uint4(pack_h2(bv[2*h].x, bv[2*h].y),   pack_h2(bv[2*h].z, bv[2*h].w),
                              pack_h2(bv[2*h+1].x, bv[2*h+1].y), pack_h2(bv[2*h+1].z, bv[2*h+1].w));
        *reinterpret_cast<uint4*>(&As[0][sDst + 4 * h]) = sa;
        *reinterpret_cast<uint4*>(&Bs[0][sDst + 4 * h]) = sb;
    }
    __syncthreads();

#pragma unroll 1
    for (int t = 0; t < T; ++t) {
        const int cur = t & 1;
        const uint32_t asC = cur ? asB1 : asB0;
        const uint32_t bsC = cur ? bsB1 : bsB0;

        // prefetch next tile (global -> regs), hidden under mma
        if (t + 1 < T) {
            const int tn = t + 1;
            const bool p2 = (tn >= Kt);
            const float* __restrict__ Ar = p2 ? Arow1 : Arow0;
            const float* __restrict__ Br = p2 ? Brow1 : Brow0;
            const int k0 = (tn - (p2 ? Kt : 0)) * BK;
#pragma unroll
            for (int q = 0; q < 4; ++q) {
                av[q] = aValid ? *reinterpret_cast<const float4*>(Ar + k0 + sKoff + 4 * q)
                               : make_float4(0.f, 0.f, 0.f, 0.f);
                bv[q] = *reinterpret_cast<const float4*>(Br + k0 + sKoff + 4 * q);
            }
        }

        // compute on current buffer: two k16 steps via ldmatrix
#pragma unroll
        for (int kh = 0; kh < 2; ++kh) {
            const int kw = kh * 8;
            uint32_t a[2][4], b[8][2];
#pragma unroll
            for (int mt = 0; mt < 2; ++mt) {
                uint32_t addr = asC + (uint32_t)(((aLRow + mt * 16) * SW + aLKw + kw) * 4);
                ldsm_x4(a[mt][0], a[mt][1], a[mt][2], a[mt][3], addr);
            }
#pragma unroll
            for (int ntp = 0; ntp < 4; ++ntp) {
                uint32_t addr = bsC + (uint32_t)(((bLRow + ntp * 16) * SW + bLKw + kw) * 4);
                ldsm_x4(b[2*ntp][0], b[2*ntp][1], b[2*ntp+1][0], b[2*ntp+1][1], addr);
            }
#pragma unroll
            for (int mt = 0; mt < 2; ++mt)
#pragma unroll
                for (int nt = 0; nt < 8; ++nt)
                    mma_f16(acc[mt][nt], a[mt], b[nt]);
        }

        // store staged tile -> other buffer
        if (t + 1 < T) {
            const int nxt = cur ^ 1;
#pragma unroll
            for (int h = 0; h < 2; ++h) {
                uint4 sa = make_uint4(pack_h2(av[2*h].x, av[2*h].y),   pack_h2(av[2*h].z, av[2*h].w),
                                      pack_h2(av[2*h+1].x, av[2*h+1].y), pack_h2(av[2*h+1].z, av[2*h+1].w));
                uint4 sb = make_uint4(pack_h2(bv[2*h].x, bv[2*h].y),   pack_h2(bv[2*h].z, bv[2*h].w),
                                      pack_h2(bv[2*h+1].x, bv[2*h+1].y), pack_h2(bv[2*h+1].z, bv[2*h+1].w));
                *reinterpret_cast<uint4*>(&As[nxt][sDst + 4 * h]) = sa;
                *reinterpret_cast<uint4*>(&Bs[nxt][sDst + 4 * h]) = sb;
            }
            __syncthreads();
        }
    }

    // ---- epilogue: bias + optional relu + guarded float2 stores ----
    float2 bb[8];
#pragma unroll
    for (int nt = 0; nt < 8; ++nt)
        bb[nt] = *reinterpret_cast<const float2*>(&bias[colBase + wn + nt * 8 + 2 * tig]);

#pragma unroll
    for (int mt = 0; mt < 2; ++mt) {
        const int r0 = rowBase + wm + mt * 16 + gid;
        const int r1 = r0 + 8;
#pragma unroll
        for (int nt = 0; nt < 8; ++nt) {
            const int c = colBase + wn + nt * 8 + 2 * tig;
            float v0 = acc[mt][nt][0] + bb[nt].x;
            float v1 = acc[mt][nt][1] + bb[nt].y;
            float v2 = acc[mt][nt][2] + bb[nt].x;
            float v3 = acc[mt][nt][3] + bb[nt].y;
            if (do_relu) {
                v0 = fmaxf(v0, 0.f); v1 = fmaxf(v1, 0.f);
                v2 = fmaxf(v2, 0.f); v3 = fmaxf(v3, 0.f);
            }
            if (r0 < M_store)
                *reinterpret_cast<float2*>(&C[(size_t)r0 * NOUT + c]) = make_float2(v0, v1);
            if (r1 < M_store)
                *reinterpret_cast<float2*>(&C[(size_t)r1 * NOUT + c]) = make_float2(v2, v3);
        }
    }
}

// ---------------- launcher ----------------
extern "C" void kernel_launch(void* const* d_in, const int* in_sizes, int n_in,
                              void* d_out, int out_size)
{
    const float* x    = (const float*)d_in[0];
    const int*   ei   = (const int*)d_in[1];     // int32 (JAX x64 disabled)
    const float* W1_0 = (const float*)d_in[2];
    const float* W1_1 = (const float*)d_in[3];
    const float* b1   = (const float*)d_in[4];
    const float* W2_0 = (const float*)d_in[5];
    const float* W2_1 = (const float*)d_in[6];
    const float* b2   = (const float*)d_in[7];
    const float* W3_0 = (const float*)d_in[8];
    const float* W3_1 = (const float*)d_in[9];
    const float* b3   = (const float*)d_in[10];
    float*       out  = (float*)d_out;

    const int TB = 256;
    k_init <<<(NNODES + TB - 1) / TB, TB>>>();
    k_deg  <<<(NEDGES + TB - 1) / TB, TB>>>(ei);
    k_dinv <<<(NNODES + TB - 1) / TB, TB>>>();
    k_scan1<<<SCAN_BLOCKS, 1024>>>();
    k_scan2<<<SCAN_BLOCKS, 1024>>>();
    k_fill <<<(NEDGES + TB - 1) / TB, TB>>>(ei);
    k_transpose<<<dim3(8, 8, 6), dim3(32, 8)>>>(W1_0, W1_1, W2_0, W2_1, W3_0, W3_1);

    dim3 ggrid(MP / BM, NOUT / BN);   // 391 x 2

    // layer 1 (K = 128)
    k_spmm<128, SEL_EXT><<<NNODES, 32>>>(x);
    k_gemm<SEL_EXT, SEL_H1><<<ggrid, 256>>>(x, WT_OFF_10, WT_OFF_11, b1, nullptr, 128, MP, 1);

    // layer 2 (K = 256)
    k_spmm<256, SEL_H1><<<NNODES, 64>>>(nullptr);
    k_gemm<SEL_H1, SEL_H2><<<ggrid, 256>>>(nullptr, WT_OFF_20, WT_OFF_21, b2, nullptr, 256, MP, 1);

    // layer 3 (K = 256), no relu, store only real rows into d_out
    k_spmm<256, SEL_H2><<<NNODES, 64>>>(nullptr);
    k_gemm<SEL_H2, SEL_EXT><<<ggrid, 256>>>(nullptr, WT_OFF_30, WT_OFF_31, b3, out, 256, NNODES, 0);
}

// round 11
// speedup vs baseline: 4.0163x; 1.3247x over previous
#include <cuda_runtime.h>
#include <cuda_fp16.h>
#include <cstdint>

#define NNODES 50000
#define NEDGES 400000
#define MP     50048
#define NOUT   256
#define SCAN_BLOCKS 49    // 49*1024 >= NNODES

// ---------------- static device scratch (no allocations allowed) ----------------
__device__ int    g_deg[NNODES];
__device__ int    g_cnt[NNODES];
__device__ int    g_fill[NNODES];
__device__ float  g_dinv[NNODES];
__device__ int    g_rowptr[NNODES + 1];
__device__ int    g_bsum[SCAN_BLOCKS];
__device__ int    g_col[NEDGES];
__device__ float  g_wval[NEDGES];
// fp16 activation / weight storage
__device__ __half g_xh  [(size_t)MP * 128];
__device__ __half g_h1h [(size_t)MP * 256];
__device__ __half g_h2h [(size_t)MP * 256];
__device__ __half g_aggh[(size_t)MP * 256];
__device__ __half g_wth [256 * 128 * 2 + 256 * 256 * 4];   // Wt[n][k] fp16

#define WT_OFF_10 0
#define WT_OFF_11 (256 * 128)
#define WT_OFF_20 (256 * 128 * 2)
#define WT_OFF_21 (WT_OFF_20 + 256 * 256)
#define WT_OFF_30 (WT_OFF_21 + 256 * 256)
#define WT_OFF_31 (WT_OFF_30 + 256 * 256)

#define SEL_X   0
#define SEL_H1  1
#define SEL_H2  2

__device__ __forceinline__ const __half* sel_ch(int SEL) {
    switch (SEL) {
        case SEL_H1: return g_h1h;
        case SEL_H2: return g_h2h;
        default:     return g_xh;
    }
}

// ---------------- mma / ldmatrix helpers ----------------
__device__ __forceinline__ void mma_f16(float* c, const uint32_t* a, const uint32_t* b) {
    asm volatile(
        "mma.sync.aligned.m16n8k16.row.col.f32.f16.f16.f32 "
        "{%0,%1,%2,%3}, {%4,%5,%6,%7}, {%8,%9}, {%0,%1,%2,%3};"
        : "+f"(c[0]), "+f"(c[1]), "+f"(c[2]), "+f"(c[3])
        : "r"(a[0]), "r"(a[1]), "r"(a[2]), "r"(a[3]), "r"(b[0]), "r"(b[1]));
}
__device__ __forceinline__ void ldsm_x4(uint32_t& r0, uint32_t& r1, uint32_t& r2,
                                        uint32_t& r3, uint32_t addr) {
    asm volatile("ldmatrix.sync.aligned.m8n8.x4.shared.b16 {%0,%1,%2,%3}, [%4];"
                 : "=r"(r0), "=r"(r1), "=r"(r2), "=r"(r3) : "r"(addr));
}
__device__ __forceinline__ uint32_t smem_u32(const void* p) {
    uint32_t a;
    asm("{ .reg .u64 t; cvta.to.shared.u64 t, %1; cvt.u32.u64 %0, t; }" : "=r"(a) : "l"(p));
    return a;
}

// ---------------- graph setup kernels ----------------
__global__ void k_init() {
    int i = blockIdx.x * blockDim.x + threadIdx.x;
    if (i < NNODES) { g_deg[i] = 0; g_cnt[i] = 0; g_fill[i] = 0; }
}

// edge_index is int32 (JAX default config disables x64)
__global__ void k_deg(const int* __restrict__ ei) {
    int e = blockIdx.x * blockDim.x + threadIdx.x;
    if (e < NEDGES) {
        int s = ei[e];
        int d = ei[NEDGES + e];
        if (s != d && (unsigned)s < NNODES && (unsigned)d < NNODES) {
            atomicAdd(&g_deg[s], 1);
            atomicAdd(&g_cnt[d], 1);
        }
    }
}

__global__ void k_dinv() {
    int i = blockIdx.x * blockDim.x + threadIdx.x;
    if (i < NNODES) {
        int dg = g_deg[i];
        g_dinv[i] = (dg > 0) ? rsqrtf((float)dg) : 0.0f;
    }
}

__global__ void k_scan1() {
    __shared__ int sh[1024];
    const int t = threadIdx.x;
    const int i = blockIdx.x * 1024 + t;
    int v = (i < NNODES) ? g_cnt[i] : 0;
    sh[t] = v;
    __syncthreads();
    for (int off = 1; off < 1024; off <<= 1) {
        int u = (t >= off) ? sh[t - off] : 0;
        __syncthreads();
        sh[t] += u;
        __syncthreads();
    }
    if (i < NNODES) g_rowptr[i] = sh[t] - v;
    if (t == 1023) g_bsum[blockIdx.x] = sh[1023];
}

__global__ void k_scan2() {
    __shared__ int sh[SCAN_BLOCKS];
    const int t = threadIdx.x;
    if (t < SCAN_BLOCKS) sh[t] = g_bsum[t];
    __syncthreads();
    int offset = 0, total = 0;
    for (int b = 0; b < SCAN_BLOCKS; ++b) {
        if (b < (int)blockIdx.x) offset += sh[b];
        total += sh[b];
    }
    const int i = blockIdx.x * 1024 + t;
    if (i < NNODES) g_rowptr[i] += offset;
    if (blockIdx.x == SCAN_BLOCKS - 1 && t == 0) g_rowptr[NNODES] = total;
}

__global__ void k_fill(const int* __restrict__ ei) {
    int e = blockIdx.x * blockDim.x + threadIdx.x;
    if (e < NEDGES) {
        int s = ei[e];
        int d = ei[NEDGES + e];
        if (s != d && (unsigned)s < NNODES && (unsigned)d < NNODES) {
            int pos = atomicAdd(&g_fill[d], 1);
            int idx = g_rowptr[d] + pos;
            g_col[idx]  = s;
            g_wval[idx] = -g_dinv[s] * g_dinv[d];
        }
    }
}

// ---------------- x -> fp16 (pad rows >= NNODES with zeros) ----------------
__global__ void k_x2h(const float* __restrict__ x) {
    const size_t i = (size_t)blockIdx.x * blockDim.x + threadIdx.x;   // half2 index
    const size_t n = (size_t)MP * 64;                                  // 64 half2 per row
    if (i < n) {
        int row = (int)(i >> 6);
        __half2 v = __float2half2_rn(0.f);
        if (row < NNODES) {
            float2 f = reinterpret_cast<const float2*>(x)[i];
            v = __floats2half2_rn(f.x, f.y);
        }
        reinterpret_cast<__half2*>(g_xh)[i] = v;
    }
}

// ---------------- weight transpose + fp16: g_wth[n][k] = W[k][n] ----------------
__global__ void k_transpose(const float* __restrict__ w10, const float* __restrict__ w11,
                            const float* __restrict__ w20, const float* __restrict__ w21,
                            const float* __restrict__ w30, const float* __restrict__ w31)
{
    __shared__ float sh[32][33];
    const int m = blockIdx.z;
    const float* W; int K, off;
    switch (m) {
        case 0: W = w10; K = 128; off = WT_OFF_10; break;
        case 1: W = w11; K = 128; off = WT_OFF_11; break;
        case 2: W = w20; K = 256; off = WT_OFF_20; break;
        case 3: W = w21; K = 256; off = WT_OFF_21; break;
        case 4: W = w30; K = 256; off = WT_OFF_30; break;
        default: W = w31; K = 256; off = WT_OFF_31; break;
    }
    const int kb = blockIdx.y * 32;
    if (kb >= K) return;
    const int nb = blockIdx.x * 32;
    const int tx = threadIdx.x, ty0 = threadIdx.y;   // block (32, 8)
    for (int ty = ty0; ty < 32; ty += 8)
        sh[ty][tx] = W[(size_t)(kb + ty) * NOUT + nb + tx];
    __syncthreads();
    for (int ty = ty0; ty < 32; ty += 8)
        g_wth[(size_t)off + (size_t)(nb + ty) * K + kb + tx] = __float2half(sh[tx][ty]);
}

// ---------------- SpMM (fp16 in/out, fp32 accum): agg[row,:] = sum w_j in[col_j,:]
// threads = F/8; each thread handles 8 feature halves (one uint4 per edge).
template <int F, int SEL_IN>
__global__ void k_spmm(int dummy) {
    const uint4* __restrict__ in = reinterpret_cast<const uint4*>(sel_ch(SEL_IN));
    const int row = blockIdx.x;
    const int t   = threadIdx.x;
    const int W8  = F / 8;
    const int beg = g_rowptr[row];
    const int end = g_rowptr[row + 1];

    float ac[8];
#pragma unroll
    for (int q = 0; q < 8; ++q) ac[q] = 0.f;

    int j = beg;
    for (; j + 1 < end; j += 2) {
        float w0 = g_wval[j];     int c0 = g_col[j];
        float w1 = g_wval[j + 1]; int c1 = g_col[j + 1];
        uint4 v0 = __ldg(&in[(size_t)c0 * W8 + t]);
        uint4 v1 = __ldg(&in[(size_t)c1 * W8 + t]);
        const __half2* h0 = reinterpret_cast<const __half2*>(&v0);
        const __half2* h1 = reinterpret_cast<const __half2*>(&v1);
#pragma unroll
        for (int q = 0; q < 4; ++q) {
            float2 f0 = __half22float2(h0[q]);
            float2 f1 = __half22float2(h1[q]);
            ac[2*q]   += w0 * f0.x + w1 * f1.x;
            ac[2*q+1] += w0 * f0.y + w1 * f1.y;
        }
    }
    if (j < end) {
        float w = g_wval[j]; int c = g_col[j];
        uint4 v = __ldg(&in[(size_t)c * W8 + t]);
        const __half2* h = reinterpret_cast<const __half2*>(&v);
#pragma unroll
        for (int q = 0; q < 4; ++q) {
            float2 f = __half22float2(h[q]);
            ac[2*q]   += w * f.x;
            ac[2*q+1] += w * f.y;
        }
    }

    uint4 o;
    __half2* oh = reinterpret_cast<__half2*>(&o);
#pragma unroll
    for (int q = 0; q < 4; ++q) oh[q] = __floats2half2_rn(ac[2*q], ac[2*q+1]);
    reinterpret_cast<uint4*>(g_aggh)[(size_t)row * W8 + t] = o;
}

// ---------------- fp16 HMMA fused dual-GEMM (ldmatrix, BK=32, fp16 operands) ----
// C = A0@W0t^T + agg@W1t^T + bias (opt relu).
// Block 128x128, 256 threads (8 warps, 4 m x 2 n), warp tile 32x64, BK=32.
// smem: [row][k-pair] fp16x2 words, stride 20 (16 data + 4 pad).
#define BM 128
#define BN 128
#define BK 32
#define SW 20   // smem word-stride per row

template <int SEL_A0, int SEL_C>
__global__ void __launch_bounds__(256, 2) k_gemm(
    int wtOff0, int wtOff1,
    const float* __restrict__ bias, float* __restrict__ C_ext,
    int K, int do_relu)
{
    const __half* __restrict__ A0 = sel_ch(SEL_A0);
    const __half* __restrict__ A1 = g_aggh;
    const __half* __restrict__ W0 = g_wth + wtOff0;
    const __half* __restrict__ W1 = g_wth + wtOff1;

    __shared__ uint32_t As[2][BM * SW];   // [m][k-pair]
    __shared__ uint32_t Bs[2][BN * SW];   // [n][k-pair]

    const int tid  = threadIdx.x;        // 0..255
    const int warp = tid >> 5;           // 0..7
    const int lane = tid & 31;
    const int gid  = lane >> 2;          // 0..7
    const int tig  = lane & 3;           // 0..3
    const int wm   = (warp & 3)  * 32;   // warp row offset (4 m-warps)
    const int wn   = (warp >> 2) * 64;   // warp col offset (2 n-warps)

    const int rowBase = blockIdx.x * BM;
    const int colBase = blockIdx.y * BN;

    // stager: row = tid>>1 (0..127), k-half = (tid&1)*16 halves
    const int sRow  = tid >> 1;
    const int sKoff = (tid & 1) * 16;
    const bool aValid = (rowBase + sRow < NNODES);
    const __half* __restrict__ Arow0 = A0 + (size_t)(rowBase + sRow) * K;
    const __half* __restrict__ Arow1 = A1 + (size_t)(rowBase + sRow) * K;
    const __half* __restrict__ Brow0 = W0 + (size_t)(colBase + sRow) * K;
    const __half* __restrict__ Brow1 = W1 + (size_t)(colBase + sRow) * K;
    const int sDst = sRow * SW + (tid & 1) * 8;   // word offset of thread's 8 words

    // ldmatrix lane addressing
    const int aLRow = wm + (lane & 7) + ((lane >> 3) & 1) * 8;   // + mt*16
    const int aLKw  = (lane >> 4) * 4;                            // + ko words
    const int bLRow = wn + (lane & 7) + (lane >> 4) * 8;          // + ntp*16
    const int bLKw  = ((lane >> 3) & 1) * 4;                      // + ko words

    const uint32_t asB0 = smem_u32(&As[0][0]);
    const uint32_t asB1 = smem_u32(&As[1][0]);
    const uint32_t bsB0 = smem_u32(&Bs[0][0]);
    const uint32_t bsB1 = smem_u32(&Bs[1][0]);

    const int Kt = K / BK;     // tiles per pass
    const int T  = 2 * Kt;     // A0 pass then agg pass

    float acc[2][8][4];
#pragma unroll
    for (int mt = 0; mt < 2; ++mt)
#pragma unroll
        for (int nt = 0; nt < 8; ++nt)
#pragma unroll
            for (int q = 0; q < 4; ++q) acc[mt][nt][q] = 0.0f;

    uint4 av[2], bv[2];   // staged 16 halves of A, 16 halves of B
    const uint4 z4 = make_uint4(0u, 0u, 0u, 0u);

    // ---- stage tile 0 ----
    av[0] = aValid ? *reinterpret_cast<const uint4*>(Arow0 + sKoff)     : z4;
    av[1] = aValid ? *reinterpret_cast<const uint4*>(Arow0 + sKoff + 8) : z4;
    bv[0] = *reinterpret_cast<const uint4*>(Brow0 + sKoff);
    bv[1] = *reinterpret_cast<const uint4*>(Brow0 + sKoff + 8);
    *reinterpret_cast<uint4*>(&As[0][sDst])     = av[0];
    *reinterpret_cast<uint4*>(&As[0][sDst + 4]) = av[1];
    *reinterpret_cast<uint4*>(&Bs[0][sDst])     = bv[0];
    *reinterpret_cast<uint4*>(&Bs[0][sDst + 4]) = bv[1];
    __syncthreads();

#pragma unroll 1
    for (int t = 0; t < T; ++t) {
        const int cur = t & 1;
        const uint32_t asC = cur ? asB1 : asB0;
        const uint32_t bsC = cur ? bsB1 : bsB0;

        // prefetch next tile (global -> regs), hidden under mma
        if (t + 1 < T) {
            const int tn = t + 1;
            const bool p2 = (tn >= Kt);
            const __half* __restrict__ Ar = p2 ? Arow1 : Arow0;
            const __half* __restrict__ Br = p2 ? Brow1 : Brow0;
            const int k0 = (tn - (p2 ? Kt : 0)) * BK;
            av[0] = aValid ? *reinterpret_cast<const uint4*>(Ar + k0 + sKoff)     : z4;
            av[1] = aValid ? *reinterpret_cast<const uint4*>(Ar + k0 + sKoff + 8) : z4;
            bv[0] = *reinterpret_cast<const uint4*>(Br + k0 + sKoff);
            bv[1] = *reinterpret_cast<const uint4*>(Br + k0 + sKoff + 8);
        }

        // compute on current buffer: two k16 steps via ldmatrix
#pragma unroll
        for (int kh = 0; kh < 2; ++kh) {
            const int kw = kh * 8;
            uint32_t a[2][4], b[8][2];
#pragma unroll
            for (int mt = 0; mt < 2; ++mt) {
                uint32_t addr = asC + (uint32_t)(((aLRow + mt * 16) * SW + aLKw + kw) * 4);
                ldsm_x4(a[mt][0], a[mt][1], a[mt][2], a[mt][3], addr);
            }
#pragma unroll
            for (int ntp = 0; ntp < 4; ++ntp) {
                uint32_t addr = bsC + (uint32_t)(((bLRow + ntp * 16) * SW + bLKw + kw) * 4);
                ldsm_x4(b[2*ntp][0], b[2*ntp][1], b[2*ntp+1][0], b[2*ntp+1][1], addr);
            }
#pragma unroll
            for (int mt = 0; mt < 2; ++mt)
#pragma unroll
                for (int nt = 0; nt < 8; ++nt)
                    mma_f16(acc[mt][nt], a[mt], b[nt]);
        }

        // store staged tile -> other buffer
        if (t + 1 < T) {
            const int nxt = cur ^ 1;
            *reinterpret_cast<uint4*>(&As[nxt][sDst])     = av[0];
            *reinterpret_cast<uint4*>(&As[nxt][sDst + 4]) = av[1];
            *reinterpret_cast<uint4*>(&Bs[nxt][sDst])     = bv[0];
            *reinterpret_cast<uint4*>(&Bs[nxt][sDst + 4]) = bv[1];
            __syncthreads();
        }
    }

    // ---- epilogue: bias + optional relu ----
    float2 bb[8];
#pragma unroll
    for (int nt = 0; nt < 8; ++nt)
        bb[nt] = *reinterpret_cast<const float2*>(&bias[colBase + wn + nt * 8 + 2 * tig]);

    if (SEL_C == SEL_X) {
        // fp32 store to external buffer, only real rows
        float* __restrict__ C = C_ext;
#pragma unroll
        for (int mt = 0; mt < 2; ++mt) {
            const int r0 = rowBase + wm + mt * 16 + gid;
            const int r1 = r0 + 8;
#pragma unroll
            for (int nt = 0; nt < 8; ++nt) {
                const int c = colBase + wn + nt * 8 + 2 * tig;
                float v0 = acc[mt][nt][0] + bb[nt].x;
                float v1 = acc[mt][nt][1] + bb[nt].y;
                float v2 = acc[mt][nt][2] + bb[nt].x;
                float v3 = acc[mt][nt][3] + bb[nt].y;
                if (do_relu) {
                    v0 = fmaxf(v0, 0.f); v1 = fmaxf(v1, 0.f);
                    v2 = fmaxf(v2, 0.f); v3 = fmaxf(v3, 0.f);
                }
                if (r0 < NNODES)
                    *reinterpret_cast<float2*>(&C[(size_t)r0 * NOUT + c]) = make_float2(v0, v1);
                if (r1 < NNODES)
                    *reinterpret_cast<float2*>(&C[(size_t)r1 * NOUT + c]) = make_float2(v2, v3);
            }
        }
    } else {
        // fp16 store to internal activation buffer (all MP rows; pad rows never read)
        __half* __restrict__ Ch = (SEL_C == SEL_H1) ? g_h1h : g_h2h;
#pragma unroll
        for (int mt = 0; mt < 2; ++mt) {
            const int r0 = rowBase + wm + mt * 16 + gid;
            const int r1 = r0 + 8;
#pragma unroll
            for (int nt = 0; nt < 8; ++nt) {
                const int c = colBase + wn + nt * 8 + 2 * tig;
                float v0 = acc[mt][nt][0] + bb[nt].x;
                float v1 = acc[mt][nt][1] + bb[nt].y;
                float v2 = acc[mt][nt][2] + bb[nt].x;
                float v3 = acc[mt][nt][3] + bb[nt].y;
                if (do_relu) {
                    v0 = fmaxf(v0, 0.f); v1 = fmaxf(v1, 0.f);
                    v2 = fmaxf(v2, 0.f); v3 = fmaxf(v3, 0.f);
                }
                *reinterpret_cast<__half2*>(&Ch[(size_t)r0 * NOUT + c]) = __floats2half2_rn(v0, v1);
                *reinterpret_cast<__half2*>(&Ch[(size_t)r1 * NOUT + c]) = __floats2half2_rn(v2, v3);
            }
        }
    }
}

// ---------------- launcher ----------------
extern "C" void kernel_launch(void* const* d_in, const int* in_sizes, int n_in,
                              void* d_out, int out_size)
{
    const float* x    = (const float*)d_in[0];
    const int*   ei   = (const int*)d_in[1];     // int32 (JAX x64 disabled)
    const float* W1_0 = (const float*)d_in[2];
    const float* W1_1 = (const float*)d_in[3];
    const float* b1   = (const float*)d_in[4];
    const float* W2_0 = (const float*)d_in[5];
    const float* W2_1 = (const float*)d_in[6];
    const float* b2   = (const float*)d_in[7];
    const float* W3_0 = (const float*)d_in[8];
    const float* W3_1 = (const float*)d_in[9];
    const float* b3   = (const float*)d_in[10];
    float*       out  = (float*)d_out;

    const int TB = 256;
    k_init <<<(NNODES + TB - 1) / TB, TB>>>();
    k_deg  <<<(NEDGES + TB - 1) / TB, TB>>>(ei);
    k_dinv <<<(NNODES + TB - 1) / TB, TB>>>();
    k_scan1<<<SCAN_BLOCKS, 1024>>>();
    k_scan2<<<SCAN_BLOCKS, 1024>>>();
    k_fill <<<(NEDGES + TB - 1) / TB, TB>>>(ei);
    k_x2h  <<<(int)(((size_t)MP * 64 + TB - 1) / TB), TB>>>(x);
    k_transpose<<<dim3(8, 8, 6), dim3(32, 8)>>>(W1_0, W1_1, W2_0, W2_1, W3_0, W3_1);

    dim3 ggrid(MP / BM, NOUT / BN);   // 391 x 2

    // layer 1 (K = 128)
    k_spmm<128, SEL_X><<<NNODES, 16>>>(0);
    k_gemm<SEL_X, SEL_H1><<<ggrid, 256>>>(WT_OFF_10, WT_OFF_11, b1, nullptr, 128, 1);

    // layer 2 (K = 256)
    k_spmm<256, SEL_H1><<<NNODES, 32>>>(0);
    k_gemm<SEL_H1, SEL_H2><<<ggrid, 256>>>(WT_OFF_20, WT_OFF_21, b2, nullptr, 256, 1);

    // layer 3 (K = 256), no relu, fp32 store into d_out
    k_spmm<256, SEL_H2><<<NNODES, 32>>>(0);
    k_gemm<SEL_H2, SEL_X><<<ggrid, 256>>>(WT_OFF_30, WT_OFF_31, b3, out, 256, 0);
}

// round 12
// speedup vs baseline: 4.4680x; 1.1125x over previous
#include <cuda_runtime.h>
#include <cuda_fp16.h>
#include <cstdint>

#define NNODES 50000
#define NEDGES 400000
#define MP     50048
#define NOUT   256
#define SCAN_BLOCKS 49    // 49*1024 >= NNODES

// ---------------- static device scratch (no allocations allowed) ----------------
__device__ int    g_deg[NNODES];
__device__ int    g_cnt[NNODES];
__device__ int    g_fill[NNODES];
__device__ float  g_dinv[NNODES];
__device__ int    g_rowptr[NNODES + 1];
__device__ int    g_bsum[SCAN_BLOCKS];
__device__ int    g_col[NEDGES];
__device__ float  g_wval[NEDGES];
// fp16 activation / weight storage
__device__ __half g_xh  [(size_t)MP * 128];
__device__ __half g_h1h [(size_t)MP * 256];
__device__ __half g_h2h [(size_t)MP * 256];
__device__ __half g_aggh[(size_t)MP * 256];
__device__ __half g_wth [256 * 128 * 2 + 256 * 256 * 4];   // Wt[n][k] fp16

#define WT_OFF_10 0
#define WT_OFF_11 (256 * 128)
#define WT_OFF_20 (256 * 128 * 2)
#define WT_OFF_21 (WT_OFF_20 + 256 * 256)
#define WT_OFF_30 (WT_OFF_21 + 256 * 256)
#define WT_OFF_31 (WT_OFF_30 + 256 * 256)

#define SEL_X   0
#define SEL_H1  1
#define SEL_H2  2

__device__ __forceinline__ const __half* sel_ch(int SEL) {
    switch (SEL) {
        case SEL_H1: return g_h1h;
        case SEL_H2: return g_h2h;
        default:     return g_xh;
    }
}

// ---------------- mma / ldmatrix / cp.async helpers ----------------
__device__ __forceinline__ void mma_f16(float* c, const uint32_t* a, const uint32_t* b) {
    asm volatile(
        "mma.sync.aligned.m16n8k16.row.col.f32.f16.f16.f32 "
        "{%0,%1,%2,%3}, {%4,%5,%6,%7}, {%8,%9}, {%0,%1,%2,%3};"
        : "+f"(c[0]), "+f"(c[1]), "+f"(c[2]), "+f"(c[3])
        : "r"(a[0]), "r"(a[1]), "r"(a[2]), "r"(a[3]), "r"(b[0]), "r"(b[1]));
}
__device__ __forceinline__ void ldsm_x4(uint32_t& r0, uint32_t& r1, uint32_t& r2,
                                        uint32_t& r3, uint32_t addr) {
    asm volatile("ldmatrix.sync.aligned.m8n8.x4.shared.b16 {%0,%1,%2,%3}, [%4];"
                 : "=r"(r0), "=r"(r1), "=r"(r2), "=r"(r3) : "r"(addr));
}
__device__ __forceinline__ uint32_t smem_u32(const void* p) {
    uint32_t a;
    asm("{ .reg .u64 t; cvta.to.shared.u64 t, %1; cvt.u32.u64 %0, t; }" : "=r"(a) : "l"(p));
    return a;
}
__device__ __forceinline__ void cp_async16(uint32_t dst, const void* src, bool valid) {
    int sz = valid ? 16 : 0;   // src-size 0 -> zero-fill
    asm volatile("cp.async.cg.shared.global [%0], [%1], 16, %2;"
                 :: "r"(dst), "l"(src), "r"(sz) : "memory");
}
#define CP_COMMIT()  asm volatile("cp.async.commit_group;" ::: "memory")
#define CP_WAIT1()   asm volatile("cp.async.wait_group 1;" ::: "memory")
#define CP_WAIT0()   asm volatile("cp.async.wait_group 0;" ::: "memory")

// ---------------- graph setup kernels ----------------
__global__ void k_init() {
    int i = blockIdx.x * blockDim.x + threadIdx.x;
    if (i < NNODES) { g_deg[i] = 0; g_cnt[i] = 0; g_fill[i] = 0; }
}

// edge_index is int32 (JAX default config disables x64)
__global__ void k_deg(const int* __restrict__ ei) {
    int e = blockIdx.x * blockDim.x + threadIdx.x;
    if (e < NEDGES) {
        int s = ei[e];
        int d = ei[NEDGES + e];
        if (s != d && (unsigned)s < NNODES && (unsigned)d < NNODES) {
            atomicAdd(&g_deg[s], 1);
            atomicAdd(&g_cnt[d], 1);
        }
    }
}

__global__ void k_dinv() {
    int i = blockIdx.x * blockDim.x + threadIdx.x;
    if (i < NNODES) {
        int dg = g_deg[i];
        g_dinv[i] = (dg > 0) ? rsqrtf((float)dg) : 0.0f;
    }
}

__global__ void k_scan1() {
    __shared__ int sh[1024];
    const int t = threadIdx.x;
    const int i = blockIdx.x * 1024 + t;
    int v = (i < NNODES) ? g_cnt[i] : 0;
    sh[t] = v;
    __syncthreads();
    for (int off = 1; off < 1024; off <<= 1) {
        int u = (t >= off) ? sh[t - off] : 0;
        __syncthreads();
        sh[t] += u;
        __syncthreads();
    }
    if (i < NNODES) g_rowptr[i] = sh[t] - v;
    if (t == 1023) g_bsum[blockIdx.x] = sh[1023];
}

__global__ void k_scan2() {
    __shared__ int sh[SCAN_BLOCKS];
    const int t = threadIdx.x;
    if (t < SCAN_BLOCKS) sh[t] = g_bsum[t];
    __syncthreads();
    int offset = 0, total = 0;
    for (int b = 0; b < SCAN_BLOCKS; ++b) {
        if (b < (int)blockIdx.x) offset += sh[b];
        total += sh[b];
    }
    const int i = blockIdx.x * 1024 + t;
    if (i < NNODES) g_rowptr[i] += offset;
    if (blockIdx.x == SCAN_BLOCKS - 1 && t == 0) g_rowptr[NNODES] = total;
}

__global__ void k_fill(const int* __restrict__ ei) {
    int e = blockIdx.x * blockDim.x + threadIdx.x;
    if (e < NEDGES) {
        int s = ei[e];
        int d = ei[NEDGES + e];
        if (s != d && (unsigned)s < NNODES && (unsigned)d < NNODES) {
            int pos = atomicAdd(&g_fill[d], 1);
            int idx = g_rowptr[d] + pos;
            g_col[idx]  = s;
            g_wval[idx] = -g_dinv[s] * g_dinv[d];
        }
    }
}

// ---------------- x -> fp16 (pad rows >= NNODES with zeros) ----------------
__global__ void k_x2h(const float* __restrict__ x) {
    const size_t i = (size_t)blockIdx.x * blockDim.x + threadIdx.x;   // half2 index
    const size_t n = (size_t)MP * 64;                                  // 64 half2 per row
    if (i < n) {
        int row = (int)(i >> 6);
        __half2 v = __float2half2_rn(0.f);
        if (row < NNODES) {
            float2 f = reinterpret_cast<const float2*>(x)[i];
            v = __floats2half2_rn(f.x, f.y);
        }
        reinterpret_cast<__half2*>(g_xh)[i] = v;
    }
}

// ---------------- weight transpose + fp16: g_wth[n][k] = W[k][n] ----------------
__global__ void k_transpose(const float* __restrict__ w10, const float* __restrict__ w11,
                            const float* __restrict__ w20, const float* __restrict__ w21,
                            const float* __restrict__ w30, const float* __restrict__ w31)
{
    __shared__ float sh[32][33];
    const int m = blockIdx.z;
    const float* W; int K, off;
    switch (m) {
        case 0: W = w10; K = 128; off = WT_OFF_10; break;
        case 1: W = w11; K = 128; off = WT_OFF_11; break;
        case 2: W = w20; K = 256; off = WT_OFF_20; break;
        case 3: W = w21; K = 256; off = WT_OFF_21; break;
        case 4: W = w30; K = 256; off = WT_OFF_30; break;
        default: W = w31; K = 256; off = WT_OFF_31; break;
    }
    const int kb = blockIdx.y * 32;
    if (kb >= K) return;
    const int nb = blockIdx.x * 32;
    const int tx = threadIdx.x, ty0 = threadIdx.y;   // block (32, 8)
    for (int ty = ty0; ty < 32; ty += 8)
        sh[ty][tx] = W[(size_t)(kb + ty) * NOUT + nb + tx];
    __syncthreads();
    for (int ty = ty0; ty < 32; ty += 8)
        g_wth[(size_t)off + (size_t)(nb + ty) * K + kb + tx] = __float2half(sh[tx][ty]);
}

// ---------------- SpMM (fp16 in/out, fp32 accum) ----------------
template <int F, int SEL_IN>
__global__ void k_spmm(int dummy) {
    const uint4* __restrict__ in = reinterpret_cast<const uint4*>(sel_ch(SEL_IN));
    const int row = blockIdx.x;
    const int t   = threadIdx.x;
    const int W8  = F / 8;
    const int beg = g_rowptr[row];
    const int end = g_rowptr[row + 1];

    float ac[8];
#pragma unroll
    for (int q = 0; q < 8; ++q) ac[q] = 0.f;

    int j = beg;
    for (; j + 1 < end; j += 2) {
        float w0 = g_wval[j];     int c0 = g_col[j];
        float w1 = g_wval[j + 1]; int c1 = g_col[j + 1];
        uint4 v0 = __ldg(&in[(size_t)c0 * W8 + t]);
        uint4 v1 = __ldg(&in[(size_t)c1 * W8 + t]);
        const __half2* h0 = reinterpret_cast<const __half2*>(&v0);
        const __half2* h1 = reinterpret_cast<const __half2*>(&v1);
#pragma unroll
        for (int q = 0; q < 4; ++q) {
            float2 f0 = __half22float2(h0[q]);
            float2 f1 = __half22float2(h1[q]);
            ac[2*q]   += w0 * f0.x + w1 * f1.x;
            ac[2*q+1] += w0 * f0.y + w1 * f1.y;
        }
    }
    if (j < end) {
        float w = g_wval[j]; int c = g_col[j];
        uint4 v = __ldg(&in[(size_t)c * W8 + t]);
        const __half2* h = reinterpret_cast<const __half2*>(&v);
#pragma unroll
        for (int q = 0; q < 4; ++q) {
            float2 f = __half22float2(h[q]);
            ac[2*q]   += w * f.x;
            ac[2*q+1] += w * f.y;
        }
    }

    uint4 o;
    __half2* oh = reinterpret_cast<__half2*>(&o);
#pragma unroll
    for (int q = 0; q < 4; ++q) oh[q] = __floats2half2_rn(ac[2*q], ac[2*q+1]);
    reinterpret_cast<uint4*>(g_aggh)[(size_t)row * W8 + t] = o;
}

// ---------------- fp16 HMMA fused dual-GEMM: cp.async 3-stage, swizzled ----------
// C = A0@W0t^T + agg@W1t^T + bias (opt relu).
// Block 128x128, 256 threads (8 warps, 4 m x 2 n), warp tile 32x64, BK=32.
// smem: [row][16 words], XOR swizzle g' = g ^ ((row>>1)&3); 3 stages, 48KB total.
#define BM 128
#define BN 128
#define BK 32
#define STG_WORDS (128 * 16)        // words per stage per operand
#define STG_BYTES (STG_WORDS * 4)   // 8192

template <int SEL_A0, int SEL_C>
__global__ void __launch_bounds__(256, 2) k_gemm(
    int wtOff0, int wtOff1,
    const float* __restrict__ bias, float* __restrict__ C_ext,
    int K, int do_relu)
{
    const __half* __restrict__ A0 = sel_ch(SEL_A0);
    const __half* __restrict__ A1 = g_aggh;
    const __half* __restrict__ W0 = g_wth + wtOff0;
    const __half* __restrict__ W1 = g_wth + wtOff1;

    __shared__ uint32_t As[3][STG_WORDS];
    __shared__ uint32_t Bs[3][STG_WORDS];

    const int tid  = threadIdx.x;        // 0..255
    const int warp = tid >> 5;           // 0..7
    const int lane = tid & 31;
    const int gid  = lane >> 2;          // 0..7
    const int tig  = lane & 3;           // 0..3
    const int wm   = (warp & 3)  * 32;   // warp row offset (4 m-warps)
    const int wn   = (warp >> 2) * 64;   // warp col offset (2 n-warps)

    const int rowBase = blockIdx.x * BM;
    const int colBase = blockIdx.y * BN;

    // stager: row = tid>>1 (0..127); groups (tid&1)*2 + {0,1} (each 8 halves = 16B)
    const int sRow = tid >> 1;
    const int g0   = (tid & 1) * 2;
    const int swz  = (sRow >> 1) & 3;
    const bool aValid = (rowBase + sRow < NNODES);
    const __half* __restrict__ Arow0 = A0 + (size_t)(rowBase + sRow) * K;
    const __half* __restrict__ Arow1 = A1 + (size_t)(rowBase + sRow) * K;
    const __half* __restrict__ Brow0 = W0 + (size_t)(colBase + sRow) * K;
    const __half* __restrict__ Brow1 = W1 + (size_t)(colBase + sRow) * K;

    // ldmatrix lane addressing
    const int aLRow = wm + (lane & 7) + ((lane >> 3) & 1) * 8;   // + mt*16
    const int aG    = lane >> 4;                                  // k-group within k16
    const int bLRow = wn + (lane & 7) + (lane >> 4) * 8;          // + ntp*16
    const int bG    = (lane >> 3) & 1;

    const uint32_t asBase = smem_u32(&As[0][0]);
    const uint32_t bsBase = smem_u32(&Bs[0][0]);

    const int Kt = K / BK;     // tiles per pass
    const int T  = 2 * Kt;     // A0 pass then agg pass

    float acc[2][8][4];
#pragma unroll
    for (int mt = 0; mt < 2; ++mt)
#pragma unroll
        for (int nt = 0; nt < 8; ++nt)
#pragma unroll
            for (int q = 0; q < 4; ++q) acc[mt][nt][q] = 0.0f;

    // issue stage tn into ring buffer `buf`
    auto issue = [&](int tn, int buf) {
        const bool p2 = (tn >= Kt);
        const __half* __restrict__ Ar = p2 ? Arow1 : Arow0;
        const __half* __restrict__ Br = p2 ? Brow1 : Brow0;
        const int k0 = (tn - (p2 ? Kt : 0)) * BK;
        const uint32_t aB = asBase + (uint32_t)buf * STG_BYTES;
        const uint32_t bB = bsBase + (uint32_t)buf * STG_BYTES;
#pragma unroll
        for (int q = 0; q < 2; ++q) {
            const int g  = g0 + q;
            const int gp = g ^ swz;
            const uint32_t dOff = (uint32_t)((sRow * 16 + gp * 4) * 4);
            cp_async16(aB + dOff, Ar + k0 + g * 8, aValid);
            cp_async16(bB + dOff, Br + k0 + g * 8, true);
        }
        CP_COMMIT();
    };

    issue(0, 0);
    if (T > 1) issue(1, 1);

#pragma unroll 1
    for (int t = 0; t < T; ++t) {
        if (t + 1 < T) { CP_WAIT1(); } else { CP_WAIT0(); }
        __syncthreads();

        if (t + 2 < T) issue(t + 2, (t + 2) % 3);

        const uint32_t asC = asBase + (uint32_t)(t % 3) * STG_BYTES;
        const uint32_t bsC = bsBase + (uint32_t)(t % 3) * STG_BYTES;

#pragma unroll
        for (int kh = 0; kh < 2; ++kh) {
            uint32_t a[2][4], b[8][2];
#pragma unroll
            for (int mt = 0; mt < 2; ++mt) {
                const int row = aLRow + mt * 16;
                const int gp  = (kh * 2 + aG) ^ ((row >> 1) & 3);
                ldsm_x4(a[mt][0], a[mt][1], a[mt][2], a[mt][3],
                        asC + (uint32_t)((row * 16 + gp * 4) * 4));
            }
#pragma unroll
            for (int ntp = 0; ntp < 4; ++ntp) {
                const int row = bLRow + ntp * 16;
                const int gp  = (kh * 2 + bG) ^ ((row >> 1) & 3);
                ldsm_x4(b[2*ntp][0], b[2*ntp][1], b[2*ntp+1][0], b[2*ntp+1][1],
                        bsC + (uint32_t)((row * 16 + gp * 4) * 4));
            }
#pragma unroll
            for (int mt = 0; mt < 2; ++mt)
#pragma unroll
                for (int nt = 0; nt < 8; ++nt)
                    mma_f16(acc[mt][nt], a[mt], b[nt]);
        }
        __syncthreads();   // all warps done with buf (t%3) before it is refilled
    }

    // ---- epilogue: bias + optional relu ----
    float2 bb[8];
#pragma unroll
    for (int nt = 0; nt < 8; ++nt)
        bb[nt] = *reinterpret_cast<const float2*>(&bias[colBase + wn + nt * 8 + 2 * tig]);

    if (SEL_C == SEL_X) {
        float* __restrict__ C = C_ext;
#pragma unroll
        for (int mt = 0; mt < 2; ++mt) {
            const int r0 = rowBase + wm + mt * 16 + gid;
            const int r1 = r0 + 8;
#pragma unroll
            for (int nt = 0; nt < 8; ++nt) {
                const int c = colBase + wn + nt * 8 + 2 * tig;
                float v0 = acc[mt][nt][0] + bb[nt].x;
                float v1 = acc[mt][nt][1] + bb[nt].y;
                float v2 = acc[mt][nt][2] + bb[nt].x;
                float v3 = acc[mt][nt][3] + bb[nt].y;
                if (do_relu) {
                    v0 = fmaxf(v0, 0.f); v1 = fmaxf(v1, 0.f);
                    v2 = fmaxf(v2, 0.f); v3 = fmaxf(v3, 0.f);
                }
                if (r0 < NNODES)
                    *reinterpret_cast<float2*>(&C[(size_t)r0 * NOUT + c]) = make_float2(v0, v1);
                if (r1 < NNODES)
                    *reinterpret_cast<float2*>(&C[(size_t)r1 * NOUT + c]) = make_float2(v2, v3);
            }
        }
    } else {
        __half* __restrict__ Ch = (SEL_C == SEL_H1) ? g_h1h : g_h2h;
#pragma unroll
        for (int mt = 0; mt < 2; ++mt) {
            const int r0 = rowBase + wm + mt * 16 + gid;
            const int r1 = r0 + 8;
#pragma unroll
            for (int nt = 0; nt < 8; ++nt) {
                const int c = colBase + wn + nt * 8 + 2 * tig;
                float v0 = acc[mt][nt][0] + bb[nt].x;
                float v1 = acc[mt][nt][1] + bb[nt].y;
                float v2 = acc[mt][nt][2] + bb[nt].x;
                float v3 = acc[mt][nt][3] + bb[nt].y;
                if (do_relu) {
                    v0 = fmaxf(v0, 0.f); v1 = fmaxf(v1, 0.f);
                    v2 = fmaxf(v2, 0.f); v3 = fmaxf(v3, 0.f);
                }
                *reinterpret_cast<__half2*>(&Ch[(size_t)r0 * NOUT + c]) = __floats2half2_rn(v0, v1);
                *reinterpret_cast<__half2*>(&Ch[(size_t)r1 * NOUT + c]) = __floats2half2_rn(v2, v3);
            }
        }
    }
}

// ---------------- launcher ----------------
extern "C" void kernel_launch(void* const* d_in, const int* in_sizes, int n_in,
                              void* d_out, int out_size)
{
    const float* x    = (const float*)d_in[0];
    const int*   ei   = (const int*)d_in[1];     // int32 (JAX x64 disabled)
    const float* W1_0 = (const float*)d_in[2];
    const float* W1_1 = (const float*)d_in[3];
    const float* b1   = (const float*)d_in[4];
    const float* W2_0 = (const float*)d_in[5];
    const float* W2_1 = (const float*)d_in[6];
    const float* b2   = (const float*)d_in[7];
    const float* W3_0 = (const float*)d_in[8];
    const float* W3_1 = (const float*)d_in[9];
    const float* b3   = (const float*)d_in[10];
    float*       out  = (float*)d_out;

    const int TB = 256;
    k_init <<<(NNODES + TB - 1) / TB, TB>>>();
    k_deg  <<<(NEDGES + TB - 1) / TB, TB>>>(ei);
    k_dinv <<<(NNODES + TB - 1) / TB, TB>>>();
    k_scan1<<<SCAN_BLOCKS, 1024>>>();
    k_scan2<<<SCAN_BLOCKS, 1024>>>();
    k_fill <<<(NEDGES + TB - 1) / TB, TB>>>(ei);
    k_x2h  <<<(int)(((size_t)MP * 64 + TB - 1) / TB), TB>>>(x);
    k_transpose<<<dim3(8, 8, 6), dim3(32, 8)>>>(W1_0, W1_1, W2_0, W2_1, W3_0, W3_1);

    dim3 ggrid(MP / BM, NOUT / BN);   // 391 x 2

    // layer 1 (K = 128)
    k_spmm<128, SEL_X><<<NNODES, 16>>>(0);
    k_gemm<SEL_X, SEL_H1><<<ggrid, 256>>>(WT_OFF_10, WT_OFF_11, b1, nullptr, 128, 1);

    // layer 2 (K = 256)
    k_spmm<256, SEL_H1><<<NNODES, 32>>>(0);
    k_gemm<SEL_H1, SEL_H2><<<ggrid, 256>>>(WT_OFF_20, WT_OFF_21, b2, nullptr, 256, 1);

    // layer 3 (K = 256), no relu, fp32 store into d_out
    k_spmm<256, SEL_H2><<<NNODES, 32>>>(0);
    k_gemm<SEL_H2, SEL_X><<<ggrid, 256>>>(WT_OFF_30, WT_OFF_31, b3, out, 256, 0);
}

// round 13
// speedup vs baseline: 4.9932x; 1.1175x over previous
#include <cuda_runtime.h>
#include <cuda_fp16.h>
#include <cstdint>

#define NNODES 50000
#define NEDGES 400000
#define MP     50048
#define NOUT   256
#define SCAN_BLOCKS 49    // 49*1024 >= NNODES

// ---------------- static device scratch (no allocations allowed) ----------------
__device__ int    g_deg[NNODES];
__device__ int    g_cnt[NNODES];
__device__ int    g_fill[NNODES];
__device__ float  g_dinv[NNODES];
__device__ int    g_rowptr[NNODES + 1];
__device__ int    g_bsum[SCAN_BLOCKS];
__device__ int    g_col[NEDGES];
__device__ float  g_wval[NEDGES];
// fp16 activation / weight storage
__device__ __half g_xh  [(size_t)MP * 128];
__device__ __half g_h1h [(size_t)MP * 256];
__device__ __half g_h2h [(size_t)MP * 256];
__device__ __half g_aggh[(size_t)MP * 256];
__device__ __half g_wth [256 * 128 * 2 + 256 * 256 * 4];   // Wt[n][k] fp16

#define WT_OFF_10 0
#define WT_OFF_11 (256 * 128)
#define WT_OFF_20 (256 * 128 * 2)
#define WT_OFF_21 (WT_OFF_20 + 256 * 256)
#define WT_OFF_30 (WT_OFF_21 + 256 * 256)
#define WT_OFF_31 (WT_OFF_30 + 256 * 256)

#define SEL_X   0
#define SEL_H1  1
#define SEL_H2  2

__device__ __forceinline__ const __half* sel_ch(int SEL) {
    switch (SEL) {
        case SEL_H1: return g_h1h;
        case SEL_H2: return g_h2h;
        default:     return g_xh;
    }
}

// ---------------- mma / ldmatrix / cp.async helpers ----------------
__device__ __forceinline__ void mma_f16(float* c, const uint32_t* a, const uint32_t* b) {
    asm volatile(
        "mma.sync.aligned.m16n8k16.row.col.f32.f16.f16.f32 "
        "{%0,%1,%2,%3}, {%4,%5,%6,%7}, {%8,%9}, {%0,%1,%2,%3};"
        : "+f"(c[0]), "+f"(c[1]), "+f"(c[2]), "+f"(c[3])
        : "r"(a[0]), "r"(a[1]), "r"(a[2]), "r"(a[3]), "r"(b[0]), "r"(b[1]));
}
__device__ __forceinline__ void ldsm_x4(uint32_t& r0, uint32_t& r1, uint32_t& r2,
                                        uint32_t& r3, uint32_t addr) {
    asm volatile("ldmatrix.sync.aligned.m8n8.x4.shared.b16 {%0,%1,%2,%3}, [%4];"
                 : "=r"(r0), "=r"(r1), "=r"(r2), "=r"(r3) : "r"(addr));
}
__device__ __forceinline__ uint32_t smem_u32(const void* p) {
    uint32_t a;
    asm("{ .reg .u64 t; cvta.to.shared.u64 t, %1; cvt.u32.u64 %0, t; }" : "=r"(a) : "l"(p));
    return a;
}
__device__ __forceinline__ void cp_async16(uint32_t dst, const void* src, bool valid) {
    int sz = valid ? 16 : 0;   // src-size 0 -> zero-fill
    asm volatile("cp.async.cg.shared.global [%0], [%1], 16, %2;"
                 :: "r"(dst), "l"(src), "r"(sz) : "memory");
}
#define CP_COMMIT()  asm volatile("cp.async.commit_group;" ::: "memory")
#define CP_WAIT1()   asm volatile("cp.async.wait_group 1;" ::: "memory")
#define CP_WAIT0()   asm volatile("cp.async.wait_group 0;" ::: "memory")

// ---------------- graph setup kernels ----------------
__global__ void k_init() {
    int i = blockIdx.x * blockDim.x + threadIdx.x;
    if (i < NNODES) { g_deg[i] = 0; g_cnt[i] = 0; g_fill[i] = 0; }
}

// edge_index is int32 (JAX default config disables x64)
__global__ void k_deg(const int* __restrict__ ei) {
    int e = blockIdx.x * blockDim.x + threadIdx.x;
    if (e < NEDGES) {
        int s = ei[e];
        int d = ei[NEDGES + e];
        if (s != d && (unsigned)s < NNODES && (unsigned)d < NNODES) {
            atomicAdd(&g_deg[s], 1);
            atomicAdd(&g_cnt[d], 1);
        }
    }
}

__global__ void k_dinv() {
    int i = blockIdx.x * blockDim.x + threadIdx.x;
    if (i < NNODES) {
        int dg = g_deg[i];
        g_dinv[i] = (dg > 0) ? rsqrtf((float)dg) : 0.0f;
    }
}

__global__ void k_scan1() {
    __shared__ int sh[1024];
    const int t = threadIdx.x;
    const int i = blockIdx.x * 1024 + t;
    int v = (i < NNODES) ? g_cnt[i] : 0;
    sh[t] = v;
    __syncthreads();
    for (int off = 1; off < 1024; off <<= 1) {
        int u = (t >= off) ? sh[t - off] : 0;
        __syncthreads();
        sh[t] += u;
        __syncthreads();
    }
    if (i < NNODES) g_rowptr[i] = sh[t] - v;
    if (t == 1023) g_bsum[blockIdx.x] = sh[1023];
}

__global__ void k_scan2() {
    __shared__ int sh[SCAN_BLOCKS];
    const int t = threadIdx.x;
    if (t < SCAN_BLOCKS) sh[t] = g_bsum[t];
    __syncthreads();
    int offset = 0, total = 0;
    for (int b = 0; b < SCAN_BLOCKS; ++b) {
        if (b < (int)blockIdx.x) offset += sh[b];
        total += sh[b];
    }
    const int i = blockIdx.x * 1024 + t;
    if (i < NNODES) g_rowptr[i] += offset;
    if (blockIdx.x == SCAN_BLOCKS - 1 && t == 0) g_rowptr[NNODES] = total;
}

__global__ void k_fill(const int* __restrict__ ei) {
    int e = blockIdx.x * blockDim.x + threadIdx.x;
    if (e < NEDGES) {
        int s = ei[e];
        int d = ei[NEDGES + e];
        if (s != d && (unsigned)s < NNODES && (unsigned)d < NNODES) {
            int pos = atomicAdd(&g_fill[d], 1);
            int idx = g_rowptr[d] + pos;
            g_col[idx]  = s;
            g_wval[idx] = -g_dinv[s] * g_dinv[d];
        }
    }
}

// ---------------- x -> fp16 (pad rows >= NNODES with zeros) ----------------
__global__ void k_x2h(const float* __restrict__ x) {
    const size_t i = (size_t)blockIdx.x * blockDim.x + threadIdx.x;   // half2 index
    const size_t n = (size_t)MP * 64;                                  // 64 half2 per row
    if (i < n) {
        int row = (int)(i >> 6);
        __half2 v = __float2half2_rn(0.f);
        if (row < NNODES) {
            float2 f = reinterpret_cast<const float2*>(x)[i];
            v = __floats2half2_rn(f.x, f.y);
        }
        reinterpret_cast<__half2*>(g_xh)[i] = v;
    }
}

// ---------------- weight transpose + fp16: g_wth[n][k] = W[k][n] ----------------
__global__ void k_transpose(const float* __restrict__ w10, const float* __restrict__ w11,
                            const float* __restrict__ w20, const float* __restrict__ w21,
                            const float* __restrict__ w30, const float* __restrict__ w31)
{
    __shared__ float sh[32][33];
    const int m = blockIdx.z;
    const float* W; int K, off;
    switch (m) {
        case 0: W = w10; K = 128; off = WT_OFF_10; break;
        case 1: W = w11; K = 128; off = WT_OFF_11; break;
        case 2: W = w20; K = 256; off = WT_OFF_20; break;
        case 3: W = w21; K = 256; off = WT_OFF_21; break;
        case 4: W = w30; K = 256; off = WT_OFF_30; break;
        default: W = w31; K = 256; off = WT_OFF_31; break;
    }
    const int kb = blockIdx.y * 32;
    if (kb >= K) return;
    const int nb = blockIdx.x * 32;
    const int tx = threadIdx.x, ty0 = threadIdx.y;   // block (32, 8)
    for (int ty = ty0; ty < 32; ty += 8)
        sh[ty][tx] = W[(size_t)(kb + ty) * NOUT + nb + tx];
    __syncthreads();
    for (int ty = ty0; ty < 32; ty += 8)
        g_wth[(size_t)off + (size_t)(nb + ty) * K + kb + tx] = __float2half(sh[tx][ty]);
}

// ---------------- SpMM (fp16 in/out, fp32 accum) ----------------
// 8 rows per block; each row handled by W8 = F/8 lanes (one uint4 per lane).
// Edge loop unrolled x4 for MLP.
#define SPMM_ROWS 8
template <int F, int SEL_IN>
__global__ void k_spmm(int dummy) {
    const uint4* __restrict__ in = reinterpret_cast<const uint4*>(sel_ch(SEL_IN));
    const int W8  = F / 8;
    const int row = blockIdx.x * SPMM_ROWS + threadIdx.x / W8;
    const int t   = threadIdx.x % W8;
    if (row >= NNODES) return;
    const int beg = g_rowptr[row];
    const int end = g_rowptr[row + 1];

    float ac[8];
#pragma unroll
    for (int q = 0; q < 8; ++q) ac[q] = 0.f;

    int j = beg;
    for (; j + 3 < end; j += 4) {
        float w0 = g_wval[j];     int c0 = g_col[j];
        float w1 = g_wval[j + 1]; int c1 = g_col[j + 1];
        float w2 = g_wval[j + 2]; int c2 = g_col[j + 2];
        float w3 = g_wval[j + 3]; int c3 = g_col[j + 3];
        uint4 v0 = __ldg(&in[(size_t)c0 * W8 + t]);
        uint4 v1 = __ldg(&in[(size_t)c1 * W8 + t]);
        uint4 v2 = __ldg(&in[(size_t)c2 * W8 + t]);
        uint4 v3 = __ldg(&in[(size_t)c3 * W8 + t]);
        const __half2* h0 = reinterpret_cast<const __half2*>(&v0);
        const __half2* h1 = reinterpret_cast<const __half2*>(&v1);
        const __half2* h2 = reinterpret_cast<const __half2*>(&v2);
        const __half2* h3 = reinterpret_cast<const __half2*>(&v3);
#pragma unroll
        for (int q = 0; q < 4; ++q) {
            float2 f0 = __half22float2(h0[q]);
            float2 f1 = __half22float2(h1[q]);
            float2 f2 = __half22float2(h2[q]);
            float2 f3 = __half22float2(h3[q]);
            ac[2*q]   += (w0 * f0.x + w1 * f1.x) + (w2 * f2.x + w3 * f3.x);
            ac[2*q+1] += (w0 * f0.y + w1 * f1.y) + (w2 * f2.y + w3 * f3.y);
        }
    }
    for (; j < end; ++j) {
        float w = g_wval[j]; int c = g_col[j];
        uint4 v = __ldg(&in[(size_t)c * W8 + t]);
        const __half2* h = reinterpret_cast<const __half2*>(&v);
#pragma unroll
        for (int q = 0; q < 4; ++q) {
            float2 f = __half22float2(h[q]);
            ac[2*q]   += w * f.x;
            ac[2*q+1] += w * f.y;
        }
    }

    uint4 o;
    __half2* oh = reinterpret_cast<__half2*>(&o);
#pragma unroll
    for (int q = 0; q < 4; ++q) oh[q] = __floats2half2_rn(ac[2*q], ac[2*q+1]);
    reinterpret_cast<uint4*>(g_aggh)[(size_t)row * W8 + t] = o;
}

// ---------------- fp16 HMMA fused dual-GEMM: cp.async 3-stage, swizzled ----------
// C = A0@W0t^T + agg@W1t^T + bias (opt relu).
// Block 128x128, 256 threads (8 warps, 4 m x 2 n), warp tile 32x64, BK=32.
// smem: [row][16 words], XOR swizzle g' = g ^ ((row>>1)&3); 3 stages, 48KB total.
#define BM 128
#define BN 128
#define BK 32
#define STG_WORDS (128 * 16)        // words per stage per operand
#define STG_BYTES (STG_WORDS * 4)   // 8192

template <int SEL_A0, int SEL_C>
__global__ void __launch_bounds__(256, 2) k_gemm(
    int wtOff0, int wtOff1,
    const float* __restrict__ bias, float* __restrict__ C_ext,
    int K, int do_relu)
{
    const __half* __restrict__ A0 = sel_ch(SEL_A0);
    const __half* __restrict__ A1 = g_aggh;
    const __half* __restrict__ W0 = g_wth + wtOff0;
    const __half* __restrict__ W1 = g_wth + wtOff1;

    __shared__ uint32_t As[3][STG_WORDS];
    __shared__ uint32_t Bs[3][STG_WORDS];

    const int tid  = threadIdx.x;        // 0..255
    const int warp = tid >> 5;           // 0..7
    const int lane = tid & 31;
    const int gid  = lane >> 2;          // 0..7
    const int tig  = lane & 3;           // 0..3
    const int wm   = (warp & 3)  * 32;   // warp row offset (4 m-warps)
    const int wn   = (warp >> 2) * 64;   // warp col offset (2 n-warps)

    const int rowBase = blockIdx.x * BM;
    const int colBase = blockIdx.y * BN;

    // stager: row = tid>>1 (0..127); groups (tid&1)*2 + {0,1} (each 8 halves = 16B)
    const int sRow = tid >> 1;
    const int g0   = (tid & 1) * 2;
    const int swz  = (sRow >> 1) & 3;
    const bool aValid = (rowBase + sRow < NNODES);
    const __half* __restrict__ Arow0 = A0 + (size_t)(rowBase + sRow) * K;
    const __half* __restrict__ Arow1 = A1 + (size_t)(rowBase + sRow) * K;
    const __half* __restrict__ Brow0 = W0 + (size_t)(colBase + sRow) * K;
    const __half* __restrict__ Brow1 = W1 + (size_t)(colBase + sRow) * K;

    // ldmatrix lane addressing
    const int aLRow = wm + (lane & 7) + ((lane >> 3) & 1) * 8;   // + mt*16
    const int aG    = lane >> 4;                                  // k-group within k16
    const int bLRow = wn + (lane & 7) + (lane >> 4) * 8;          // + ntp*16
    const int bG    = (lane >> 3) & 1;

    const uint32_t asBase = smem_u32(&As[0][0]);
    const uint32_t bsBase = smem_u32(&Bs[0][0]);

    const int Kt = K / BK;     // tiles per pass
    const int T  = 2 * Kt;     // A0 pass then agg pass

    float acc[2][8][4];
#pragma unroll
    for (int mt = 0; mt < 2; ++mt)
#pragma unroll
        for (int nt = 0; nt < 8; ++nt)
#pragma unroll
            for (int q = 0; q < 4; ++q) acc[mt][nt][q] = 0.0f;

    // issue stage tn into ring buffer `buf`
    auto issue = [&](int tn, int buf) {
        const bool p2 = (tn >= Kt);
        const __half* __restrict__ Ar = p2 ? Arow1 : Arow0;
        const __half* __restrict__ Br = p2 ? Brow1 : Brow0;
        const int k0 = (tn - (p2 ? Kt : 0)) * BK;
        const uint32_t aB = asBase + (uint32_t)buf * STG_BYTES;
        const uint32_t bB = bsBase + (uint32_t)buf * STG_BYTES;
#pragma unroll
        for (int q = 0; q < 2; ++q) {
            const int g  = g0 + q;
            const int gp = g ^ swz;
            const uint32_t dOff = (uint32_t)((sRow * 16 + gp * 4) * 4);
            cp_async16(aB + dOff, Ar + k0 + g * 8, aValid);
            cp_async16(bB + dOff, Br + k0 + g * 8, true);
        }
        CP_COMMIT();
    };

    issue(0, 0);
    if (T > 1) issue(1, 1);

#pragma unroll 1
    for (int t = 0; t < T; ++t) {
        if (t + 1 < T) { CP_WAIT1(); } else { CP_WAIT0(); }
        __syncthreads();
        // NOTE: this top barrier also proves every warp finished reading buffer
        // (t-1)%3 (its compute in iteration t-1 precedes this barrier), so the
        // issue below may safely overwrite it; no bottom barrier needed.

        if (t + 2 < T) issue(t + 2, (t + 2) % 3);

        const uint32_t asC = asBase + (uint32_t)(t % 3) * STG_BYTES;
        const uint32_t bsC = bsBase + (uint32_t)(t % 3) * STG_BYTES;

#pragma unroll
        for (int kh = 0; kh < 2; ++kh) {
            uint32_t a[2][4], b[8][2];
#pragma unroll
            for (int mt = 0; mt < 2; ++mt) {
                const int row = aLRow + mt * 16;
                const int gp  = (kh * 2 + aG) ^ ((row >> 1) & 3);
                ldsm_x4(a[mt][0], a[mt][1], a[mt][2], a[mt][3],
                        asC + (uint32_t)((row * 16 + gp * 4) * 4));
            }
#pragma unroll
            for (int ntp = 0; ntp < 4; ++ntp) {
                const int row = bLRow + ntp * 16;
                const int gp  = (kh * 2 + bG) ^ ((row >> 1) & 3);
                ldsm_x4(b[2*ntp][0], b[2*ntp][1], b[2*ntp+1][0], b[2*ntp+1][1],
                        bsC + (uint32_t)((row * 16 + gp * 4) * 4));
            }
#pragma unroll
            for (int mt = 0; mt < 2; ++mt)
#pragma unroll
                for (int nt = 0; nt < 8; ++nt)
                    mma_f16(acc[mt][nt], a[mt], b[nt]);
        }
    }

    // ---- epilogue: bias + optional relu ----
    float2 bb[8];
#pragma unroll
    for (int nt = 0; nt < 8; ++nt)
        bb[nt] = *reinterpret_cast<const float2*>(&bias[colBase + wn + nt * 8 + 2 * tig]);

    if (SEL_C == SEL_X) {
        float* __restrict__ C = C_ext;
#pragma unroll
        for (int mt = 0; mt < 2; ++mt) {
            const int r0 = rowBase + wm + mt * 16 + gid;
            const int r1 = r0 + 8;
#pragma unroll
            for (int nt = 0; nt < 8; ++nt) {
                const int c = colBase + wn + nt * 8 + 2 * tig;
                float v0 = acc[mt][nt][0] + bb[nt].x;
                float v1 = acc[mt][nt][1] + bb[nt].y;
                float v2 = acc[mt][nt][2] + bb[nt].x;
                float v3 = acc[mt][nt][3] + bb[nt].y;
                if (do_relu) {
                    v0 = fmaxf(v0, 0.f); v1 = fmaxf(v1, 0.f);
                    v2 = fmaxf(v2, 0.f); v3 = fmaxf(v3, 0.f);
                }
                if (r0 < NNODES)
                    *reinterpret_cast<float2*>(&C[(size_t)r0 * NOUT + c]) = make_float2(v0, v1);
                if (r1 < NNODES)
                    *reinterpret_cast<float2*>(&C[(size_t)r1 * NOUT + c]) = make_float2(v2, v3);
            }
        }
    } else {
        __half* __restrict__ Ch = (SEL_C == SEL_H1) ? g_h1h : g_h2h;
#pragma unroll
        for (int mt = 0; mt < 2; ++mt) {
            const int r0 = rowBase + wm + mt * 16 + gid;
            const int r1 = r0 + 8;
#pragma unroll
            for (int nt = 0; nt < 8; ++nt) {
                const int c = colBase + wn + nt * 8 + 2 * tig;
                float v0 = acc[mt][nt][0] + bb[nt].x;
                float v1 = acc[mt][nt][1] + bb[nt].y;
                float v2 = acc[mt][nt][2] + bb[nt].x;
                float v3 = acc[mt][nt][3] + bb[nt].y;
                if (do_relu) {
                    v0 = fmaxf(v0, 0.f); v1 = fmaxf(v1, 0.f);
                    v2 = fmaxf(v2, 0.f); v3 = fmaxf(v3, 0.f);
                }
                *reinterpret_cast<__half2*>(&Ch[(size_t)r0 * NOUT + c]) = __floats2half2_rn(v0, v1);
                *reinterpret_cast<__half2*>(&Ch[(size_t)r1 * NOUT + c]) = __floats2half2_rn(v2, v3);
            }
        }
    }
}

// ---------------- launcher ----------------
extern "C" void kernel_launch(void* const* d_in, const int* in_sizes, int n_in,
                              void* d_out, int out_size)
{
    const float* x    = (const float*)d_in[0];
    const int*   ei   = (const int*)d_in[1];     // int32 (JAX x64 disabled)
    const float* W1_0 = (const float*)d_in[2];
    const float* W1_1 = (const float*)d_in[3];
    const float* b1   = (const float*)d_in[4];
    const float* W2_0 = (const float*)d_in[5];
    const float* W2_1 = (const float*)d_in[6];
    const float* b2   = (const float*)d_in[7];
    const float* W3_0 = (const float*)d_in[8];
    const float* W3_1 = (const float*)d_in[9];
    const float* b3   = (const float*)d_in[10];
    float*       out  = (float*)d_out;

    const int TB = 256;
    k_init <<<(NNODES + TB - 1) / TB, TB>>>();
    k_deg  <<<(NEDGES + TB - 1) / TB, TB>>>(ei);
    k_dinv <<<(NNODES + TB - 1) / TB, TB>>>();
    k_scan1<<<SCAN_BLOCKS, 1024>>>();
    k_scan2<<<SCAN_BLOCKS, 1024>>>();
    k_fill <<<(NEDGES + TB - 1) / TB, TB>>>(ei);
    k_x2h  <<<(int)(((size_t)MP * 64 + TB - 1) / TB), TB>>>(x);
    k_transpose<<<dim3(8, 8, 6), dim3(32, 8)>>>(W1_0, W1_1, W2_0, W2_1, W3_0, W3_1);

    dim3 ggrid(MP / BM, NOUT / BN);   // 391 x 2
    const int spmmGrid = (NNODES + SPMM_ROWS - 1) / SPMM_ROWS;   // 6250

    // layer 1 (K = 128): F=128 -> W8=16 lanes/row, 8 rows -> 128 threads
    k_spmm<128, SEL_X><<<spmmGrid, 128>>>(0);
    k_gemm<SEL_X, SEL_H1><<<ggrid, 256>>>(WT_OFF_10, WT_OFF_11, b1, nullptr, 128, 1);

    // layer 2 (K = 256): F=256 -> W8=32 lanes/row, 8 rows -> 256 threads
    k_spmm<256, SEL_H1><<<spmmGrid, 256>>>(0);
    k_gemm<SEL_H1, SEL_H2><<<ggrid, 256>>>(WT_OFF_20, WT_OFF_21, b2, nullptr, 256, 1);

    // layer 3 (K = 256), no relu, fp32 store into d_out
    k_spmm<256, SEL_H2><<<spmmGrid, 256>>>(0);
    k_gemm<SEL_H2, SEL_X><<<ggrid, 256>>>(WT_OFF_30, WT_OFF_31, b3, out, 256, 0);
}

// round 14
// speedup vs baseline: 5.0434x; 1.0101x over previous
#include <cuda_runtime.h>
#include <cuda_fp16.h>
#include <cstdint>

#define NNODES 50000
#define NEDGES 400000
#define MP     50048
#define NOUT   256
#define SCAN_BLOCKS 49    // 49*1024 >= NNODES

// ---------------- static device scratch (no allocations allowed) ----------------
__device__ int    g_deg[NNODES];
__device__ int    g_cnt[NNODES];
__device__ int    g_fill[NNODES];
__device__ float  g_dinv[NNODES];
__device__ int    g_rowptr[NNODES + 1];
__device__ int    g_bsum[SCAN_BLOCKS];
__device__ int    g_col[NEDGES];
__device__ float  g_wval[NEDGES];
// fp16 activation / weight storage
__device__ __half g_xh  [(size_t)MP * 128];
__device__ __half g_h1h [(size_t)MP * 256];
__device__ __half g_h2h [(size_t)MP * 256];
__device__ __half g_aggh[(size_t)MP * 256];
__device__ __half g_wth [256 * 128 * 2 + 256 * 256 * 4];   // Wt[n][k] fp16

#define WT_OFF_10 0
#define WT_OFF_11 (256 * 128)
#define WT_OFF_20 (256 * 128 * 2)
#define WT_OFF_21 (WT_OFF_20 + 256 * 256)
#define WT_OFF_30 (WT_OFF_21 + 256 * 256)
#define WT_OFF_31 (WT_OFF_30 + 256 * 256)

#define SEL_X   0
#define SEL_H1  1
#define SEL_H2  2

__device__ __forceinline__ const __half* sel_ch(int SEL) {
    switch (SEL) {
        case SEL_H1: return g_h1h;
        case SEL_H2: return g_h2h;
        default:     return g_xh;
    }
}

// ---------------- mma / ldmatrix / cp.async helpers ----------------
__device__ __forceinline__ void mma_f16(float* c, const uint32_t* a, const uint32_t* b) {
    asm volatile(
        "mma.sync.aligned.m16n8k16.row.col.f32.f16.f16.f32 "
        "{%0,%1,%2,%3}, {%4,%5,%6,%7}, {%8,%9}, {%0,%1,%2,%3};"
        : "+f"(c[0]), "+f"(c[1]), "+f"(c[2]), "+f"(c[3])
        : "r"(a[0]), "r"(a[1]), "r"(a[2]), "r"(a[3]), "r"(b[0]), "r"(b[1]));
}
__device__ __forceinline__ void ldsm_x4(uint32_t& r0, uint32_t& r1, uint32_t& r2,
                                        uint32_t& r3, uint32_t addr) {
    asm volatile("ldmatrix.sync.aligned.m8n8.x4.shared.b16 {%0,%1,%2,%3}, [%4];"
                 : "=r"(r0), "=r"(r1), "=r"(r2), "=r"(r3) : "r"(addr));
}
__device__ __forceinline__ uint32_t smem_u32(const void* p) {
    uint32_t a;
    asm("{ .reg .u64 t; cvta.to.shared.u64 t, %1; cvt.u32.u64 %0, t; }" : "=r"(a) : "l"(p));
    return a;
}
__device__ __forceinline__ void cp_async16(uint32_t dst, const void* src, bool valid) {
    int sz = valid ? 16 : 0;   // src-size 0 -> zero-fill
    asm volatile("cp.async.cg.shared.global [%0], [%1], 16, %2;"
                 :: "r"(dst), "l"(src), "r"(sz) : "memory");
}
#define CP_COMMIT()  asm volatile("cp.async.commit_group;" ::: "memory")
#define CP_WAIT2()   asm volatile("cp.async.wait_group 2;" ::: "memory")
#define CP_WAIT1()   asm volatile("cp.async.wait_group 1;" ::: "memory")
#define CP_WAIT0()   asm volatile("cp.async.wait_group 0;" ::: "memory")

// ---------------- graph setup kernels ----------------
__global__ void k_init() {
    int i = blockIdx.x * blockDim.x + threadIdx.x;
    if (i < NNODES) { g_deg[i] = 0; g_cnt[i] = 0; g_fill[i] = 0; }
}

// edge_index is int32 (JAX default config disables x64)
__global__ void k_deg(const int* __restrict__ ei) {
    int e = blockIdx.x * blockDim.x + threadIdx.x;
    if (e < NEDGES) {
        int s = ei[e];
        int d = ei[NEDGES + e];
        if (s != d && (unsigned)s < NNODES && (unsigned)d < NNODES) {
            atomicAdd(&g_deg[s], 1);
            atomicAdd(&g_cnt[d], 1);
        }
    }
}

// scan phase 1 (also computes dinv — independent of the scan data flow)
__global__ void k_scan1() {
    __shared__ int sh[1024];
    const int t = threadIdx.x;
    const int i = blockIdx.x * 1024 + t;
    if (i < NNODES) {
        int dg = g_deg[i];
        g_dinv[i] = (dg > 0) ? rsqrtf((float)dg) : 0.0f;
    }
    int v = (i < NNODES) ? g_cnt[i] : 0;
    sh[t] = v;
    __syncthreads();
    for (int off = 1; off < 1024; off <<= 1) {
        int u = (t >= off) ? sh[t - off] : 0;
        __syncthreads();
        sh[t] += u;
        __syncthreads();
    }
    if (i < NNODES) g_rowptr[i] = sh[t] - v;
    if (t == 1023) g_bsum[blockIdx.x] = sh[1023];
}

__global__ void k_scan2() {
    __shared__ int sh[SCAN_BLOCKS];
    const int t = threadIdx.x;
    if (t < SCAN_BLOCKS) sh[t] = g_bsum[t];
    __syncthreads();
    int offset = 0, total = 0;
    for (int b = 0; b < SCAN_BLOCKS; ++b) {
        if (b < (int)blockIdx.x) offset += sh[b];
        total += sh[b];
    }
    const int i = blockIdx.x * 1024 + t;
    if (i < NNODES) g_rowptr[i] += offset;
    if (blockIdx.x == SCAN_BLOCKS - 1 && t == 0) g_rowptr[NNODES] = total;
}

__global__ void k_fill(const int* __restrict__ ei) {
    int e = blockIdx.x * blockDim.x + threadIdx.x;
    if (e < NEDGES) {
        int s = ei[e];
        int d = ei[NEDGES + e];
        if (s != d && (unsigned)s < NNODES && (unsigned)d < NNODES) {
            int pos = atomicAdd(&g_fill[d], 1);
            int idx = g_rowptr[d] + pos;
            g_col[idx]  = s;
            g_wval[idx] = -g_dinv[s] * g_dinv[d];
        }
    }
}

// ---------------- x -> fp16 (pad rows >= NNODES with zeros) ----------------
__global__ void k_x2h(const float* __restrict__ x) {
    const size_t i = (size_t)blockIdx.x * blockDim.x + threadIdx.x;   // half2 index
    const size_t n = (size_t)MP * 64;                                  // 64 half2 per row
    if (i < n) {
        int row = (int)(i >> 6);
        __half2 v = __float2half2_rn(0.f);
        if (row < NNODES) {
            float2 f = reinterpret_cast<const float2*>(x)[i];
            v = __floats2half2_rn(f.x, f.y);
        }
        reinterpret_cast<__half2*>(g_xh)[i] = v;
    }
}

// ---------------- weight transpose + fp16: g_wth[n][k] = W[k][n] ----------------
__global__ void k_transpose(const float* __restrict__ w10, const float* __restrict__ w11,
                            const float* __restrict__ w20, const float* __restrict__ w21,
                            const float* __restrict__ w30, const float* __restrict__ w31)
{
    __shared__ float sh[32][33];
    const int m = blockIdx.z;
    const float* W; int K, off;
    switch (m) {
        case 0: W = w10; K = 128; off = WT_OFF_10; break;
        case 1: W = w11; K = 128; off = WT_OFF_11; break;
        case 2: W = w20; K = 256; off = WT_OFF_20; break;
        case 3: W = w21; K = 256; off = WT_OFF_21; break;
        case 4: W = w30; K = 256; off = WT_OFF_30; break;
        default: W = w31; K = 256; off = WT_OFF_31; break;
    }
    const int kb = blockIdx.y * 32;
    if (kb >= K) return;
    const int nb = blockIdx.x * 32;
    const int tx = threadIdx.x, ty0 = threadIdx.y;   // block (32, 8)
    for (int ty = ty0; ty < 32; ty += 8)
        sh[ty][tx] = W[(size_t)(kb + ty) * NOUT + nb + tx];
    __syncthreads();
    for (int ty = ty0; ty < 32; ty += 8)
        g_wth[(size_t)off + (size_t)(nb + ty) * K + kb + tx] = __float2half(sh[tx][ty]);
}

// ---------------- SpMM (fp16 in/out, fp32 accum) ----------------
// 8 rows per block; each row handled by W8 = F/8 lanes (one uint4 per lane).
// Edge loop unrolled x4 for MLP.
#define SPMM_ROWS 8
template <int F, int SEL_IN>
__global__ void k_spmm(int dummy) {
    const uint4* __restrict__ in = reinterpret_cast<const uint4*>(sel_ch(SEL_IN));
    const int W8  = F / 8;
    const int row = blockIdx.x * SPMM_ROWS + threadIdx.x / W8;
    const int t   = threadIdx.x % W8;
    if (row >= NNODES) return;
    const int beg = g_rowptr[row];
    const int end = g_rowptr[row + 1];

    float ac[8];
#pragma unroll
    for (int q = 0; q < 8; ++q) ac[q] = 0.f;

    int j = beg;
    for (; j + 3 < end; j += 4) {
        float w0 = g_wval[j];     int c0 = g_col[j];
        float w1 = g_wval[j + 1]; int c1 = g_col[j + 1];
        float w2 = g_wval[j + 2]; int c2 = g_col[j + 2];
        float w3 = g_wval[j + 3]; int c3 = g_col[j + 3];
        uint4 v0 = __ldg(&in[(size_t)c0 * W8 + t]);
        uint4 v1 = __ldg(&in[(size_t)c1 * W8 + t]);
        uint4 v2 = __ldg(&in[(size_t)c2 * W8 + t]);
        uint4 v3 = __ldg(&in[(size_t)c3 * W8 + t]);
        const __half2* h0 = reinterpret_cast<const __half2*>(&v0);
        const __half2* h1 = reinterpret_cast<const __half2*>(&v1);
        const __half2* h2 = reinterpret_cast<const __half2*>(&v2);
        const __half2* h3 = reinterpret_cast<const __half2*>(&v3);
#pragma unroll
        for (int q = 0; q < 4; ++q) {
            float2 f0 = __half22float2(h0[q]);
            float2 f1 = __half22float2(h1[q]);
            float2 f2 = __half22float2(h2[q]);
            float2 f3 = __half22float2(h3[q]);
            ac[2*q]   += (w0 * f0.x + w1 * f1.x) + (w2 * f2.x + w3 * f3.x);
            ac[2*q+1] += (w0 * f0.y + w1 * f1.y) + (w2 * f2.y + w3 * f3.y);
        }
    }
    for (; j < end; ++j) {
        float w = g_wval[j]; int c = g_col[j];
        uint4 v = __ldg(&in[(size_t)c * W8 + t]);
        const __half2* h = reinterpret_cast<const __half2*>(&v);
#pragma unroll
        for (int q = 0; q < 4; ++q) {
            float2 f = __half22float2(h[q]);
            ac[2*q]   += w * f.x;
            ac[2*q+1] += w * f.y;
        }
    }

    uint4 o;
    __half2* oh = reinterpret_cast<__half2*>(&o);
#pragma unroll
    for (int q = 0; q < 4; ++q) oh[q] = __floats2half2_rn(ac[2*q], ac[2*q+1]);
    reinterpret_cast<uint4*>(g_aggh)[(size_t)row * W8 + t] = o;
}

// ---------------- fp16 HMMA fused dual-GEMM: cp.async 4-stage, swizzled ----------
// C = A0@W0t^T + agg@W1t^T + bias (opt relu).
// Block 128x128, 256 threads (8 warps, 4 m x 2 n), warp tile 32x64, BK=32.
// smem (dynamic 64KB): 4 stages x (A 8KB + B 8KB); XOR swizzle g'=g^((row>>1)&3).
#define BM 128
#define BN 128
#define BK 32
#define STG_WORDS (128 * 16)        // words per stage per operand
#define STG_BYTES (STG_WORDS * 4)   // 8192
#define NSTG 4
#define SMEM_DYN (NSTG * 2 * STG_BYTES)   // 65536

template <int SEL_A0, int SEL_C>
__global__ void __launch_bounds__(256, 2) k_gemm(
    int wtOff0, int wtOff1,
    const float* __restrict__ bias, float* __restrict__ C_ext,
    int K, int do_relu)
{
    extern __shared__ uint32_t smem_dyn[];
    // layout: As stages [0 .. NSTG*STG_WORDS), Bs stages after
    const __half* __restrict__ A0 = sel_ch(SEL_A0);
    const __half* __restrict__ A1 = g_aggh;
    const __half* __restrict__ W0 = g_wth + wtOff0;
    const __half* __restrict__ W1 = g_wth + wtOff1;

    const int tid  = threadIdx.x;        // 0..255
    const int warp = tid >> 5;           // 0..7
    const int lane = tid & 31;
    const int gid  = lane >> 2;          // 0..7
    const int tig  = lane & 3;           // 0..3
    const int wm   = (warp & 3)  * 32;   // warp row offset (4 m-warps)
    const int wn   = (warp >> 2) * 64;   // warp col offset (2 n-warps)

    const int rowBase = blockIdx.x * BM;
    const int colBase = blockIdx.y * BN;

    // stager: row = tid>>1 (0..127); groups (tid&1)*2 + {0,1} (each 8 halves = 16B)
    const int sRow = tid >> 1;
    const int g0   = (tid & 1) * 2;
    const int swz  = (sRow >> 1) & 3;
    const bool aValid = (rowBase + sRow < NNODES);
    const __half* __restrict__ Arow0 = A0 + (size_t)(rowBase + sRow) * K;
    const __half* __restrict__ Arow1 = A1 + (size_t)(rowBase + sRow) * K;
    const __half* __restrict__ Brow0 = W0 + (size_t)(colBase + sRow) * K;
    const __half* __restrict__ Brow1 = W1 + (size_t)(colBase + sRow) * K;

    // ldmatrix lane addressing
    const int aLRow = wm + (lane & 7) + ((lane >> 3) & 1) * 8;   // + mt*16
    const int aG    = lane >> 4;                                  // k-group within k16
    const int bLRow = wn + (lane & 7) + (lane >> 4) * 8;          // + ntp*16
    const int bG    = (lane >> 3) & 1;

    const uint32_t asBase = smem_u32(&smem_dyn[0]);
    const uint32_t bsBase = asBase + NSTG * STG_BYTES;

    const int Kt = K / BK;     // tiles per pass
    const int T  = 2 * Kt;     // A0 pass then agg pass (T = 8 or 16)

    float acc[2][8][4];
#pragma unroll
    for (int mt = 0; mt < 2; ++mt)
#pragma unroll
        for (int nt = 0; nt < 8; ++nt)
#pragma unroll
            for (int q = 0; q < 4; ++q) acc[mt][nt][q] = 0.0f;

    // issue stage tn into ring buffer `buf`
    auto issue = [&](int tn, int buf) {
        const bool p2 = (tn >= Kt);
        const __half* __restrict__ Ar = p2 ? Arow1 : Arow0;
        const __half* __restrict__ Br = p2 ? Brow1 : Brow0;
        const int k0 = (tn - (p2 ? Kt : 0)) * BK;
        const uint32_t aB = asBase + (uint32_t)buf * STG_BYTES;
        const uint32_t bB = bsBase + (uint32_t)buf * STG_BYTES;
#pragma unroll
        for (int q = 0; q < 2; ++q) {
            const int g  = g0 + q;
            const int gp = g ^ swz;
            const uint32_t dOff = (uint32_t)((sRow * 16 + gp * 4) * 4);
            cp_async16(aB + dOff, Ar + k0 + g * 8, aValid);
            cp_async16(bB + dOff, Br + k0 + g * 8, true);
        }
        CP_COMMIT();
    };

    issue(0, 0);
    if (T > 1) issue(1, 1);
    if (T > 2) issue(2, 2);

#pragma unroll 1
    for (int t = 0; t < T; ++t) {
        // need groups pending <= min(2, T-1-t) so stage t is complete
        if (t + 3 <= T - 1)      { CP_WAIT2(); }
        else if (t + 2 <= T - 1) { CP_WAIT1(); }
        else                     { CP_WAIT0(); }
        __syncthreads();
        // top barrier also seals all reads of buffer (t-1)%4 (done in iter t-1),
        // so the issue below may overwrite it; no bottom barrier needed.

        if (t + 3 < T) issue(t + 3, (t + 3) & (NSTG - 1));

        const uint32_t asC = asBase + (uint32_t)(t & (NSTG - 1)) * STG_BYTES;
        const uint32_t bsC = bsBase + (uint32_t)(t & (NSTG - 1)) * STG_BYTES;

#pragma unroll
        for (int kh = 0; kh < 2; ++kh) {
            uint32_t a[2][4], b[8][2];
#pragma unroll
            for (int mt = 0; mt < 2; ++mt) {
                const int row = aLRow + mt * 16;
                const int gp  = (kh * 2 + aG) ^ ((row >> 1) & 3);
                ldsm_x4(a[mt][0], a[mt][1], a[mt][2], a[mt][3],
                        asC + (uint32_t)((row * 16 + gp * 4) * 4));
            }
#pragma unroll
            for (int ntp = 0; ntp < 4; ++ntp) {
                const int row = bLRow + ntp * 16;
                const int gp  = (kh * 2 + bG) ^ ((row >> 1) & 3);
                ldsm_x4(b[2*ntp][0], b[2*ntp][1], b[2*ntp+1][0], b[2*ntp+1][1],
                        bsC + (uint32_t)((row * 16 + gp * 4) * 4));
            }
#pragma unroll
            for (int mt = 0; mt < 2; ++mt)
#pragma unroll
                for (int nt = 0; nt < 8; ++nt)
                    mma_f16(acc[mt][nt], a[mt], b[nt]);
        }
    }

    // ---- epilogue: bias + optional relu ----
    float2 bb[8];
#pragma unroll
    for (int nt = 0; nt < 8; ++nt)
        bb[nt] = *reinterpret_cast<const float2*>(&bias[colBase + wn + nt * 8 + 2 * tig]);

    if (SEL_C == SEL_X) {
        float* __restrict__ C = C_ext;
#pragma unroll
        for (int mt = 0; mt < 2; ++mt) {
            const int r0 = rowBase + wm + mt * 16 + gid;
            const int r1 = r0 + 8;
#pragma unroll
            for (int nt = 0; nt < 8; ++nt) {
                const int c = colBase + wn + nt * 8 + 2 * tig;
                float v0 = acc[mt][nt][0] + bb[nt].x;
                float v1 = acc[mt][nt][1] + bb[nt].y;
                float v2 = acc[mt][nt][2] + bb[nt].x;
                float v3 = acc[mt][nt][3] + bb[nt].y;
                if (do_relu) {
                    v0 = fmaxf(v0, 0.f); v1 = fmaxf(v1, 0.f);
                    v2 = fmaxf(v2, 0.f); v3 = fmaxf(v3, 0.f);
                }
                if (r0 < NNODES)
                    *reinterpret_cast<float2*>(&C[(size_t)r0 * NOUT + c]) = make_float2(v0, v1);
                if (r1 < NNODES)
                    *reinterpret_cast<float2*>(&C[(size_t)r1 * NOUT + c]) = make_float2(v2, v3);
            }
        }
    } else {
        __half* __restrict__ Ch = (SEL_C == SEL_H1) ? g_h1h : g_h2h;
#pragma unroll
        for (int mt = 0; mt < 2; ++mt) {
            const int r0 = rowBase + wm + mt * 16 + gid;
            const int r1 = r0 + 8;
#pragma unroll
            for (int nt = 0; nt < 8; ++nt) {
                const int c = colBase + wn + nt * 8 + 2 * tig;
                float v0 = acc[mt][nt][0] + bb[nt].x;
                float v1 = acc[mt][nt][1] + bb[nt].y;
                float v2 = acc[mt][nt][2] + bb[nt].x;
                float v3 = acc[mt][nt][3] + bb[nt].y;
                if (do_relu) {
                    v0 = fmaxf(v0, 0.f); v1 = fmaxf(v1, 0.f);
                    v2 = fmaxf(v2, 0.f); v3 = fmaxf(v3, 0.f);
                }
                *reinterpret_cast<__half2*>(&Ch[(size_t)r0 * NOUT + c]) = __floats2half2_rn(v0, v1);
                *reinterpret_cast<__half2*>(&Ch[(size_t)r1 * NOUT + c]) = __floats2half2_rn(v2, v3);
            }
        }
    }
}

// ---------------- launcher ----------------
extern "C" void kernel_launch(void* const* d_in, const int* in_sizes, int n_in,
                              void* d_out, int out_size)
{
    const float* x    = (const float*)d_in[0];
    const int*   ei   = (const int*)d_in[1];     // int32 (JAX x64 disabled)
    const float* W1_0 = (const float*)d_in[2];
    const float* W1_1 = (const float*)d_in[3];
    const float* b1   = (const float*)d_in[4];
    const float* W2_0 = (const float*)d_in[5];
    const float* W2_1 = (const float*)d_in[6];
    const float* b2   = (const float*)d_in[7];
    const float* W3_0 = (const float*)d_in[8];
    const float* W3_1 = (const float*)d_in[9];
    const float* b3   = (const float*)d_in[10];
    float*       out  = (float*)d_out;

    // raise dynamic-smem limit for the three GEMM instantiations (idempotent,
    // non-stream API: legal during graph capture)
    cudaFuncSetAttribute(k_gemm<SEL_X,  SEL_H1>, cudaFuncAttributeMaxDynamicSharedMemorySize, SMEM_DYN);
    cudaFuncSetAttribute(k_gemm<SEL_H1, SEL_H2>, cudaFuncAttributeMaxDynamicSharedMemorySize, SMEM_DYN);
    cudaFuncSetAttribute(k_gemm<SEL_H2, SEL_X >, cudaFuncAttributeMaxDynamicSharedMemorySize, SMEM_DYN);

    const int TB = 256;
    k_init <<<(NNODES + TB - 1) / TB, TB>>>();
    k_deg  <<<(NEDGES + TB - 1) / TB, TB>>>(ei);
    k_scan1<<<SCAN_BLOCKS, 1024>>>();
    k_scan2<<<SCAN_BLOCKS, 1024>>>();
    k_fill <<<(NEDGES + TB - 1) / TB, TB>>>(ei);
    k_x2h  <<<(int)(((size_t)MP * 64 + TB - 1) / TB), TB>>>(x);
    k_transpose<<<dim3(8, 8, 6), dim3(32, 8)>>>(W1_0, W1_1, W2_0, W2_1, W3_0, W3_1);

    dim3 ggrid(MP / BM, NOUT / BN);   // 391 x 2
    const int spmmGrid = (NNODES + SPMM_ROWS - 1) / SPMM_ROWS;   // 6250

    // layer 1 (K = 128)
    k_spmm<128, SEL_X><<<spmmGrid, 128>>>(0);
    k_gemm<SEL_X, SEL_H1><<<ggrid, 256, SMEM_DYN>>>(WT_OFF_10, WT_OFF_11, b1, nullptr, 128, 1);

    // layer 2 (K = 256)
    k_spmm<256, SEL_H1><<<spmmGrid, 256>>>(0);
    k_gemm<SEL_H1, SEL_H2><<<ggrid, 256, SMEM_DYN>>>(WT_OFF_20, WT_OFF_21, b2, nullptr, 256, 1);

    // layer 3 (K = 256), no relu, fp32 store into d_out
    k_spmm<256, SEL_H2><<<spmmGrid, 256>>>(0);
    k_gemm<SEL_H2, SEL_X><<<ggrid, 256, SMEM_DYN>>>(WT_OFF_30, WT_OFF_31, b3, out, 256, 0);
}

// round 15
// speedup vs baseline: 5.0777x; 1.0068x over previous
#include <cuda_runtime.h>
#include <cuda_fp16.h>
#include <cstdint>

#define NNODES 50000
#define NEDGES 400000
#define MP     50048
#define NOUT   256
#define SCAN_BLOCKS 49    // 49*1024 >= NNODES+1

// ---------------- static device scratch (no allocations allowed) ----------------
__device__ int    g_deg[NNODES];
__device__ int    g_cnt[NNODES];
__device__ int    g_fill[NNODES];
__device__ float  g_dinv[NNODES];
__device__ int    g_rowptr[NNODES + 1];   // block-LOCAL exclusive scan
__device__ int    g_bsum[SCAN_BLOCKS];
__device__ int    g_boff[SCAN_BLOCKS];    // global offset of each scan block
__device__ int    g_col[NEDGES];
__device__ float  g_wval[NEDGES];
// fp16 activation / weight storage
__device__ __half g_xh  [(size_t)MP * 128];
__device__ __half g_h1h [(size_t)MP * 256];
__device__ __half g_h2h [(size_t)MP * 256];
__device__ __half g_aggh[(size_t)MP * 256];
__device__ __half g_wth [256 * 128 * 2 + 256 * 256 * 4];   // Wt[n][k] fp16

#define WT_OFF_10 0
#define WT_OFF_11 (256 * 128)
#define WT_OFF_20 (256 * 128 * 2)
#define WT_OFF_21 (WT_OFF_20 + 256 * 256)
#define WT_OFF_30 (WT_OFF_21 + 256 * 256)
#define WT_OFF_31 (WT_OFF_30 + 256 * 256)

#define SEL_X   0
#define SEL_H1  1
#define SEL_H2  2

__device__ __forceinline__ const __half* sel_ch(int SEL) {
    switch (SEL) {
        case SEL_H1: return g_h1h;
        case SEL_H2: return g_h2h;
        default:     return g_xh;
    }
}

// ---------------- mma / ldmatrix / cp.async helpers ----------------
__device__ __forceinline__ void mma_f16(float* c, const uint32_t* a, const uint32_t* b) {
    asm volatile(
        "mma.sync.aligned.m16n8k16.row.col.f32.f16.f16.f32 "
        "{%0,%1,%2,%3}, {%4,%5,%6,%7}, {%8,%9}, {%0,%1,%2,%3};"
        : "+f"(c[0]), "+f"(c[1]), "+f"(c[2]), "+f"(c[3])
        : "r"(a[0]), "r"(a[1]), "r"(a[2]), "r"(a[3]), "r"(b[0]), "r"(b[1]));
}
__device__ __forceinline__ void ldsm_x4(uint32_t& r0, uint32_t& r1, uint32_t& r2,
                                        uint32_t& r3, uint32_t addr) {
    asm volatile("ldmatrix.sync.aligned.m8n8.x4.shared.b16 {%0,%1,%2,%3}, [%4];"
                 : "=r"(r0), "=r"(r1), "=r"(r2), "=r"(r3) : "r"(addr));
}
__device__ __forceinline__ uint32_t smem_u32(const void* p) {
    uint32_t a;
    asm("{ .reg .u64 t; cvta.to.shared.u64 t, %1; cvt.u32.u64 %0, t; }" : "=r"(a) : "l"(p));
    return a;
}
__device__ __forceinline__ void cp_async16(uint32_t dst, const void* src, bool valid) {
    int sz = valid ? 16 : 0;   // src-size 0 -> zero-fill
    asm volatile("cp.async.cg.shared.global [%0], [%1], 16, %2;"
                 :: "r"(dst), "l"(src), "r"(sz) : "memory");
}
#define CP_COMMIT()  asm volatile("cp.async.commit_group;" ::: "memory")
#define CP_WAIT2()   asm volatile("cp.async.wait_group 2;" ::: "memory")
#define CP_WAIT1()   asm volatile("cp.async.wait_group 1;" ::: "memory")
#define CP_WAIT0()   asm volatile("cp.async.wait_group 0;" ::: "memory")

// ---------------- fused prep: init counters + x->fp16 + weight transpose ---------
#define NB_X2H 12512                      // MP*64 half2 / 256
#define NB_INIT 196                       // ceil(NNODES/256)
#define NB_TR   384                       // 6 matrices * 8 kb * 8 nb
__global__ void k_prep(const float* __restrict__ x,
                       const float* __restrict__ w10, const float* __restrict__ w11,
                       const float* __restrict__ w20, const float* __restrict__ w21,
                       const float* __restrict__ w30, const float* __restrict__ w31)
{
    const int b = blockIdx.x;
    if (b < NB_X2H) {
        // x -> fp16 with zero padding
        const size_t i = (size_t)b * 256 + threadIdx.x;   // half2 index
        int row = (int)(i >> 6);
        __half2 v = __float2half2_rn(0.f);
        if (row < NNODES) {
            float2 f = reinterpret_cast<const float2*>(x)[i];
            v = __floats2half2_rn(f.x, f.y);
        }
        reinterpret_cast<__half2*>(g_xh)[i] = v;
    } else if (b < NB_X2H + NB_INIT) {
        const int i = (b - NB_X2H) * 256 + threadIdx.x;
        if (i < NNODES) { g_deg[i] = 0; g_cnt[i] = 0; g_fill[i] = 0; }
    } else {
        // weight transpose + fp16: g_wth[n][k] = W[k][n]
        __shared__ float sh[32][33];
        const int idx = b - (NB_X2H + NB_INIT);
        const int m   = idx / 64;
        const int rem = idx % 64;
        const int kb  = (rem / 8) * 32;
        const int nb  = (rem % 8) * 32;
        const float* W; int K, off;
        switch (m) {
            case 0: W = w10; K = 128; off = WT_OFF_10; break;
            case 1: W = w11; K = 128; off = WT_OFF_11; break;
            case 2: W = w20; K = 256; off = WT_OFF_20; break;
            case 3: W = w21; K = 256; off = WT_OFF_21; break;
            case 4: W = w30; K = 256; off = WT_OFF_30; break;
            default: W = w31; K = 256; off = WT_OFF_31; break;
        }
        if (kb >= K) return;
        const int tx = threadIdx.x & 31, ty0 = threadIdx.x >> 5;   // 32 x 8
        for (int ty = ty0; ty < 32; ty += 8)
            sh[ty][tx] = W[(size_t)(kb + ty) * NOUT + nb + tx];
        __syncthreads();
        for (int ty = ty0; ty < 32; ty += 8)
            g_wth[(size_t)off + (size_t)(nb + ty) * K + kb + tx] = __float2half(sh[tx][ty]);
    }
}

// edge_index is int32 (JAX default config disables x64)
__global__ void k_deg(const int* __restrict__ ei) {
    int e = blockIdx.x * blockDim.x + threadIdx.x;
    if (e < NEDGES) {
        int s = ei[e];
        int d = ei[NEDGES + e];
        if (s != d && (unsigned)s < NNODES && (unsigned)d < NNODES) {
            atomicAdd(&g_deg[s], 1);
            atomicAdd(&g_cnt[d], 1);
        }
    }
}

// scan phase 1: block-local exclusive scan via warp shuffles (2 barriers);
// also computes dinv (independent of scan data flow).
__global__ void k_scan1() {
    __shared__ int wsum[32];
    const int t    = threadIdx.x;
    const int lane = t & 31;
    const int wid  = t >> 5;
    const int i    = blockIdx.x * 1024 + t;

    if (i < NNODES) {
        int dg = g_deg[i];
        g_dinv[i] = (dg > 0) ? rsqrtf((float)dg) : 0.0f;
    }

    int v = (i < NNODES) ? g_cnt[i] : 0;
    // inclusive warp scan
    int x = v;
#pragma unroll
    for (int off = 1; off < 32; off <<= 1) {
        int y = __shfl_up_sync(0xFFFFFFFFu, x, off);
        if (lane >= off) x += y;
    }
    if (lane == 31) wsum[wid] = x;
    __syncthreads();
    if (wid == 0) {
        int s = wsum[lane];
#pragma unroll
        for (int off = 1; off < 32; off <<= 1) {
            int y = __shfl_up_sync(0xFFFFFFFFu, s, off);
            if (lane >= off) s += y;
        }
        wsum[lane] = s;   // inclusive over warp sums
    }
    __syncthreads();
    int prefix = ((wid > 0) ? wsum[wid - 1] : 0) + (x - v);   // block-local exclusive
    if (i <= NNODES) g_rowptr[i] = prefix;
    if (t == 1023) g_bsum[blockIdx.x] = wsum[31];
}

// tiny kernel: exclusive scan of the 49 block sums into g_boff
__global__ void k_scanb() {
    __shared__ int sh[SCAN_BLOCKS];
    const int t = threadIdx.x;
    if (t < SCAN_BLOCKS) sh[t] = g_bsum[t];
    __syncthreads();
    if (t == 0) {
        int s = 0;
        for (int b = 0; b < SCAN_BLOCKS; ++b) { g_boff[b] = s; s += sh[b]; }
    }
}

__global__ void k_fill(const int* __restrict__ ei) {
    int e = blockIdx.x * blockDim.x + threadIdx.x;
    if (e < NEDGES) {
        int s = ei[e];
        int d = ei[NEDGES + e];
        if (s != d && (unsigned)s < NNODES && (unsigned)d < NNODES) {
            int pos = atomicAdd(&g_fill[d], 1);
            int idx = g_rowptr[d] + g_boff[d >> 10] + pos;
            g_col[idx]  = s;
            g_wval[idx] = -g_dinv[s] * g_dinv[d];
        }
    }
}

// ---------------- SpMM (fp16 in/out, fp32 accum) ----------------
// 8 rows per block; each row handled by W8 = F/8 lanes (one uint4 per lane).
#define SPMM_ROWS 8
template <int F, int SEL_IN>
__global__ void k_spmm(int dummy) {
    const uint4* __restrict__ in = reinterpret_cast<const uint4*>(sel_ch(SEL_IN));
    const int W8  = F / 8;
    const int row = blockIdx.x * SPMM_ROWS + threadIdx.x / W8;
    const int t   = threadIdx.x % W8;
    if (row >= NNODES) return;
    const int beg = g_rowptr[row]     + g_boff[row >> 10];
    const int end = g_rowptr[row + 1] + g_boff[(row + 1) >> 10];

    float ac[8];
#pragma unroll
    for (int q = 0; q < 8; ++q) ac[q] = 0.f;

    int j = beg;
    for (; j + 3 < end; j += 4) {
        float w0 = g_wval[j];     int c0 = g_col[j];
        float w1 = g_wval[j + 1]; int c1 = g_col[j + 1];
        float w2 = g_wval[j + 2]; int c2 = g_col[j + 2];
        float w3 = g_wval[j + 3]; int c3 = g_col[j + 3];
        uint4 v0 = __ldg(&in[(size_t)c0 * W8 + t]);
        uint4 v1 = __ldg(&in[(size_t)c1 * W8 + t]);
        uint4 v2 = __ldg(&in[(size_t)c2 * W8 + t]);
        uint4 v3 = __ldg(&in[(size_t)c3 * W8 + t]);
        const __half2* h0 = reinterpret_cast<const __half2*>(&v0);
        const __half2* h1 = reinterpret_cast<const __half2*>(&v1);
        const __half2* h2 = reinterpret_cast<const __half2*>(&v2);
        const __half2* h3 = reinterpret_cast<const __half2*>(&v3);
#pragma unroll
        for (int q = 0; q < 4; ++q) {
            float2 f0 = __half22float2(h0[q]);
            float2 f1 = __half22float2(h1[q]);
            float2 f2 = __half22float2(h2[q]);
            float2 f3 = __half22float2(h3[q]);
            ac[2*q]   += (w0 * f0.x + w1 * f1.x) + (w2 * f2.x + w3 * f3.x);
            ac[2*q+1] += (w0 * f0.y + w1 * f1.y) + (w2 * f2.y + w3 * f3.y);
        }
    }
    for (; j < end; ++j) {
        float w = g_wval[j]; int c = g_col[j];
        uint4 v = __ldg(&in[(size_t)c * W8 + t]);
        const __half2* h = reinterpret_cast<const __half2*>(&v);
#pragma unroll
        for (int q = 0; q < 4; ++q) {
            float2 f = __half22float2(h[q]);
            ac[2*q]   += w * f.x;
            ac[2*q+1] += w * f.y;
        }
    }

    uint4 o;
    __half2* oh = reinterpret_cast<__half2*>(&o);
#pragma unroll
    for (int q = 0; q < 4; ++q) oh[q] = __floats2half2_rn(ac[2*q], ac[2*q+1]);
    reinterpret_cast<uint4*>(g_aggh)[(size_t)row * W8 + t] = o;
}

// ---------------- fp16 HMMA fused dual-GEMM: cp.async 4-stage, swizzled ----------
#define BM 128
#define BN 128
#define BK 32
#define STG_WORDS (128 * 16)        // words per stage per operand
#define STG_BYTES (STG_WORDS * 4)   // 8192
#define NSTG 4
#define SMEM_DYN (NSTG * 2 * STG_BYTES)   // 65536

template <int SEL_A0, int SEL_C>
__global__ void __launch_bounds__(256, 2) k_gemm(
    int wtOff0, int wtOff1,
    const float* __restrict__ bias, float* __restrict__ C_ext,
    int K, int do_relu)
{
    extern __shared__ uint32_t smem_dyn[];
    const __half* __restrict__ A0 = sel_ch(SEL_A0);
    const __half* __restrict__ A1 = g_aggh;
    const __half* __restrict__ W0 = g_wth + wtOff0;
    const __half* __restrict__ W1 = g_wth + wtOff1;

    const int tid  = threadIdx.x;        // 0..255
    const int warp = tid >> 5;           // 0..7
    const int lane = tid & 31;
    const int gid  = lane >> 2;          // 0..7
    const int tig  = lane & 3;           // 0..3
    const int wm   = (warp & 3)  * 32;   // warp row offset (4 m-warps)
    const int wn   = (warp >> 2) * 64;   // warp col offset (2 n-warps)

    const int rowBase = blockIdx.x * BM;
    const int colBase = blockIdx.y * BN;

    // stager: row = tid>>1 (0..127); groups (tid&1)*2 + {0,1} (each 8 halves = 16B)
    const int sRow = tid >> 1;
    const int g0   = (tid & 1) * 2;
    const int swz  = (sRow >> 1) & 3;
    const bool aValid = (rowBase + sRow < NNODES);
    const __half* __restrict__ Arow0 = A0 + (size_t)(rowBase + sRow) * K;
    const __half* __restrict__ Arow1 = A1 + (size_t)(rowBase + sRow) * K;
    const __half* __restrict__ Brow0 = W0 + (size_t)(colBase + sRow) * K;
    const __half* __restrict__ Brow1 = W1 + (size_t)(colBase + sRow) * K;

    // ldmatrix lane addressing
    const int aLRow = wm + (lane & 7) + ((lane >> 3) & 1) * 8;   // + mt*16
    const int aG    = lane >> 4;                                  // k-group within k16
    const int bLRow = wn + (lane & 7) + (lane >> 4) * 8;          // + ntp*16
    const int bG    = (lane >> 3) & 1;

    const uint32_t asBase = smem_u32(&smem_dyn[0]);
    const uint32_t bsBase = asBase + NSTG * STG_BYTES;

    const int Kt = K / BK;     // tiles per pass
    const int T  = 2 * Kt;     // A0 pass then agg pass (T = 8 or 16)

    float acc[2][8][4];
#pragma unroll
    for (int mt = 0; mt < 2; ++mt)
#pragma unroll
        for (int nt = 0; nt < 8; ++nt)
#pragma unroll
            for (int q = 0; q < 4; ++q) acc[mt][nt][q] = 0.0f;

    // issue stage tn into ring buffer `buf`
    auto issue = [&](int tn, int buf) {
        const bool p2 = (tn >= Kt);
        const __half* __restrict__ Ar = p2 ? Arow1 : Arow0;
        const __half* __restrict__ Br = p2 ? Brow1 : Brow0;
        const int k0 = (tn - (p2 ? Kt : 0)) * BK;
        const uint32_t aB = asBase + (uint32_t)buf * STG_BYTES;
        const uint32_t bB = bsBase + (uint32_t)buf * STG_BYTES;
#pragma unroll
        for (int q = 0; q < 2; ++q) {
            const int g  = g0 + q;
            const int gp = g ^ swz;
            const uint32_t dOff = (uint32_t)((sRow * 16 + gp * 4) * 4);
            cp_async16(aB + dOff, Ar + k0 + g * 8, aValid);
            cp_async16(bB + dOff, Br + k0 + g * 8, true);
        }
        CP_COMMIT();
    };

    issue(0, 0);
    if (T > 1) issue(1, 1);
    if (T > 2) issue(2, 2);

#pragma unroll 1
    for (int t = 0; t < T; ++t) {
        if (t + 3 <= T - 1)      { CP_WAIT2(); }
        else if (t + 2 <= T - 1) { CP_WAIT1(); }
        else                     { CP_WAIT0(); }
        __syncthreads();
        // top barrier also seals all reads of buffer (t-1)%4 (done in iter t-1),
        // so the issue below may overwrite it; no bottom barrier needed.

        if (t + 3 < T) issue(t + 3, (t + 3) & (NSTG - 1));

        const uint32_t asC = asBase + (uint32_t)(t & (NSTG - 1)) * STG_BYTES;
        const uint32_t bsC = bsBase + (uint32_t)(t & (NSTG - 1)) * STG_BYTES;

#pragma unroll
        for (int kh = 0; kh < 2; ++kh) {
            uint32_t a[2][4], b[8][2];
#pragma unroll
            for (int mt = 0; mt < 2; ++mt) {
                const int row = aLRow + mt * 16;
                const int gp  = (kh * 2 + aG) ^ ((row >> 1) & 3);
                ldsm_x4(a[mt][0], a[mt][1], a[mt][2], a[mt][3],
                        asC + (uint32_t)((row * 16 + gp * 4) * 4));
            }
#pragma unroll
            for (int ntp = 0; ntp < 4; ++ntp) {
                const int row = bLRow + ntp * 16;
                const int gp  = (kh * 2 + bG) ^ ((row >> 1) & 3);
                ldsm_x4(b[2*ntp][0], b[2*ntp][1], b[2*ntp+1][0], b[2*ntp+1][1],
                        bsC + (uint32_t)((row * 16 + gp * 4) * 4));
            }
#pragma unroll
            for (int mt = 0; mt < 2; ++mt)
#pragma unroll
                for (int nt = 0; nt < 8; ++nt)
                    mma_f16(acc[mt][nt], a[mt], b[nt]);
        }
    }

    // ---- epilogue: bias + optional relu ----
    float2 bb[8];
#pragma unroll
    for (int nt = 0; nt < 8; ++nt)
        bb[nt] = *reinterpret_cast<const float2*>(&bias[colBase + wn + nt * 8 + 2 * tig]);

    if (SEL_C == SEL_X) {
        float* __restrict__ C = C_ext;
#pragma unroll
        for (int mt = 0; mt < 2; ++mt) {
            const int r0 = rowBase + wm + mt * 16 + gid;
            const int r1 = r0 + 8;
#pragma unroll
            for (int nt = 0; nt < 8; ++nt) {
                const int c = colBase + wn + nt * 8 + 2 * tig;
                float v0 = acc[mt][nt][0] + bb[nt].x;
                float v1 = acc[mt][nt][1] + bb[nt].y;
                float v2 = acc[mt][nt][2] + bb[nt].x;
                float v3 = acc[mt][nt][3] + bb[nt].y;
                if (do_relu) {
                    v0 = fmaxf(v0, 0.f); v1 = fmaxf(v1, 0.f);
                    v2 = fmaxf(v2, 0.f); v3 = fmaxf(v3, 0.f);
                }
                if (r0 < NNODES)
                    *reinterpret_cast<float2*>(&C[(size_t)r0 * NOUT + c]) = make_float2(v0, v1);
                if (r1 < NNODES)
                    *reinterpret_cast<float2*>(&C[(size_t)r1 * NOUT + c]) = make_float2(v2, v3);
            }
        }
    } else {
        __half* __restrict__ Ch = (SEL_C == SEL_H1) ? g_h1h : g_h2h;
#pragma unroll
        for (int mt = 0; mt < 2; ++mt) {
            const int r0 = rowBase + wm + mt * 16 + gid;
            const int r1 = r0 + 8;
#pragma unroll
            for (int nt = 0; nt < 8; ++nt) {
                const int c = colBase + wn + nt * 8 + 2 * tig;
                float v0 = acc[mt][nt][0] + bb[nt].x;
                float v1 = acc[mt][nt][1] + bb[nt].y;
                float v2 = acc[mt][nt][2] + bb[nt].x;
                float v3 = acc[mt][nt][3] + bb[nt].y;
                if (do_relu) {
                    v0 = fmaxf(v0, 0.f); v1 = fmaxf(v1, 0.f);
                    v2 = fmaxf(v2, 0.f); v3 = fmaxf(v3, 0.f);
                }
                *reinterpret_cast<__half2*>(&Ch[(size_t)r0 * NOUT + c]) = __floats2half2_rn(v0, v1);
                *reinterpret_cast<__half2*>(&Ch[(size_t)r1 * NOUT + c]) = __floats2half2_rn(v2, v3);
            }
        }
    }
}

// ---------------- launcher ----------------
extern "C" void kernel_launch(void* const* d_in, const int* in_sizes, int n_in,
                              void* d_out, int out_size)
{
    const float* x    = (const float*)d_in[0];
    const int*   ei   = (const int*)d_in[1];     // int32 (JAX x64 disabled)
    const float* W1_0 = (const float*)d_in[2];
    const float* W1_1 = (const float*)d_in[3];
    const float* b1   = (const float*)d_in[4];
    const float* W2_0 = (const float*)d_in[5];
    const float* W2_1 = (const float*)d_in[6];
    const float* b2   = (const float*)d_in[7];
    const float* W3_0 = (const float*)d_in[8];
    const float* W3_1 = (const float*)d_in[9];
    const float* b3   = (const float*)d_in[10];
    float*       out  = (float*)d_out;

    cudaFuncSetAttribute(k_gemm<SEL_X,  SEL_H1>, cudaFuncAttributeMaxDynamicSharedMemorySize, SMEM_DYN);
    cudaFuncSetAttribute(k_gemm<SEL_H1, SEL_H2>, cudaFuncAttributeMaxDynamicSharedMemorySize, SMEM_DYN);
    cudaFuncSetAttribute(k_gemm<SEL_H2, SEL_X >, cudaFuncAttributeMaxDynamicSharedMemorySize, SMEM_DYN);

    const int TB = 256;
    k_prep <<<NB_X2H + NB_INIT + NB_TR, TB>>>(x, W1_0, W1_1, W2_0, W2_1, W3_0, W3_1);
    k_deg  <<<(NEDGES + TB - 1) / TB, TB>>>(ei);
    k_scan1<<<SCAN_BLOCKS, 1024>>>();
    k_scanb<<<1, 64>>>();
    k_fill <<<(NEDGES + TB - 1) / TB, TB>>>(ei);

    dim3 ggrid(MP / BM, NOUT / BN);   // 391 x 2
    const int spmmGrid = (NNODES + SPMM_ROWS - 1) / SPMM_ROWS;   // 6250

    // layer 1 (K = 128)
    k_spmm<128, SEL_X><<<spmmGrid, 128>>>(0);
    k_gemm<SEL_X, SEL_H1><<<ggrid, 256, SMEM_DYN>>>(WT_OFF_10, WT_OFF_11, b1, nullptr, 128, 1);

    // layer 2 (K = 256)
    k_spmm<256, SEL_H1><<<spmmGrid, 256>>>(0);
    k_gemm<SEL_H1, SEL_H2><<<ggrid, 256, SMEM_DYN>>>(WT_OFF_20, WT_OFF_21, b2, nullptr, 256, 1);

    // layer 3 (K = 256), no relu, fp32 store into d_out
    k_spmm<256, SEL_H2><<<spmmGrid, 256>>>(0);
    k_gemm<SEL_H2, SEL_X><<<ggrid, 256, SMEM_DYN>>>(WT_OFF_30, WT_OFF_31, b3, out, 256, 0);
}